// round 5
// baseline (speedup 1.0000x reference)
#include <cuda_runtime.h>
#include <cuda_bf16.h>
#include <math.h>
#include <stdint.h>

#define Bq 8
#define Cq 256
#define Hq 128
#define Wq 128
#define Pq (Hq*Wq)
#define NHq 8
#define HDq 32
#define NGq (Bq*NHq)

// Scratch (no allocations allowed)
__device__ float g_ix[Bq*NHq*Pq];
__device__ float g_iy[Bq*NHq*Pq];
__device__ float g_V [Bq*Cq*Pq];                  // V projection, (B,C,P) fp32
__device__ __nv_bfloat16 g_xThi[(size_t)Bq*Pq*Cq]; // x transposed (B,P,C) hi
__device__ __nv_bfloat16 g_xTlo[(size_t)Bq*Pq*Cq]; // x transposed (B,P,C) lo
__device__ __nv_bfloat16 g_SThi[(size_t)Bq*Pq*Cq]; // sampled (B,P,C) hi
__device__ __nv_bfloat16 g_STlo[(size_t)Bq*Pq*Cq]; // sampled (B,P,C) lo
__device__ __nv_bfloat16 g_wvhi[Cq*Cq], g_wvlo[Cq*Cq];
__device__ __nv_bfloat16 g_wohi[Cq*Cq], g_wolo[Cq*Cq];
__device__ float g_sum[NGq];
__device__ float g_sq [NGq];
__device__ float g_mean[NGq];
__device__ float g_rstd[NGq];

// ---------------------------------------------------------------- helpers
__device__ __forceinline__ uint32_t smem_u32(const void* p) {
    uint32_t a;
    asm("{ .reg .u64 t; cvta.to.shared.u64 t, %1; cvt.u32.u64 %0, t; }" : "=r"(a) : "l"(p));
    return a;
}

__device__ __forceinline__ uint32_t swz(uint32_t byte) {
    return byte ^ ((byte >> 3) & 0x70);
}

__device__ __forceinline__ void ldsm4(uint32_t* r, uint32_t a) {
    asm volatile("ldmatrix.sync.aligned.m8n8.x4.shared.b16 {%0,%1,%2,%3}, [%4];"
        : "=r"(r[0]), "=r"(r[1]), "=r"(r[2]), "=r"(r[3]) : "r"(a));
}

__device__ __forceinline__ void mma16816(float* d, const uint32_t* a, const uint32_t* b) {
    asm volatile(
        "mma.sync.aligned.m16n8k16.row.col.f32.bf16.bf16.f32 "
        "{%0,%1,%2,%3}, {%4,%5,%6,%7}, {%8,%9}, {%0,%1,%2,%3};"
        : "+f"(d[0]), "+f"(d[1]), "+f"(d[2]), "+f"(d[3])
        : "r"(a[0]), "r"(a[1]), "r"(a[2]), "r"(a[3]), "r"(b[0]), "r"(b[1]));
}

__device__ __forceinline__ uint32_t a_addr(uint32_t base, int m_base, int kb, int lane) {
    int mat = lane >> 3, r = lane & 7;
    int row = m_base + ((mat & 1) << 3) + r;
    int col = kb + ((mat >> 1) << 3);
    return base + swz((uint32_t)(row * 128 + col * 2));
}

__device__ __forceinline__ uint32_t b_addr(uint32_t base, int n_base, int kb, int lane) {
    int mat = lane >> 3, r = lane & 7;
    int row = n_base + ((mat >> 1) << 3) + r;
    int col = kb + ((mat & 1) << 3);
    return base + swz((uint32_t)(row * 128 + col * 2));
}

__device__ __forceinline__ void cp16(uint32_t s, const void* g) {
    asm volatile("cp.async.cg.shared.global [%0], [%1], 16;" :: "r"(s), "l"(g));
}

__device__ __forceinline__ uint32_t pack_hi2(float a, float b) {
    __nv_bfloat16 ha = __float2bfloat16(a), hb = __float2bfloat16(b);
    return (uint32_t)__bfloat16_as_ushort(ha) | ((uint32_t)__bfloat16_as_ushort(hb) << 16);
}
__device__ __forceinline__ uint32_t pack_lo2(float a, float b) {
    __nv_bfloat16 ha = __float2bfloat16(a), hb = __float2bfloat16(b);
    __nv_bfloat16 la = __float2bfloat16(a - __bfloat162float(ha));
    __nv_bfloat16 lb = __float2bfloat16(b - __bfloat162float(hb));
    return (uint32_t)__bfloat16_as_ushort(la) | ((uint32_t)__bfloat16_as_ushort(lb) << 16);
}

// ---------------------------------------------------------------- small kernels
__global__ void k_zero() {
    int i = threadIdx.x;
    if (i < NGq) { g_sum[i] = 0.f; g_sq[i] = 0.f; }
}

// Weight conversion: vw/ow [o][c] fp32 -> bf16 hi/lo, same layout
__global__ void k_wcvt(const float* __restrict__ vw, const float* __restrict__ ow) {
    int idx = blockIdx.x * 256 + threadIdx.x;   // 32768 threads, 2 elems each
    int e = idx * 2;
    float v0 = __ldg(vw + e), v1 = __ldg(vw + e + 1);
    ((uint32_t*)g_wvhi)[idx] = pack_hi2(v0, v1);
    ((uint32_t*)g_wvlo)[idx] = pack_lo2(v0, v1);
    float o0 = __ldg(ow + e), o1 = __ldg(ow + e + 1);
    ((uint32_t*)g_wohi)[idx] = pack_hi2(o0, o1);
    ((uint32_t*)g_wolo)[idx] = pack_lo2(o0, o1);
}

// x (B,C,P) fp32 -> g_xThi/lo (B,P,C) bf16 hi/lo, smem tile transpose 64c x 32p
__global__ void __launch_bounds__(256) k_cvt(const float* __restrict__ x) {
    __shared__ float xs[32][65];   // [p][c]
    const int tid = threadIdx.x;
    const int p0 = blockIdx.x * 32, c0 = blockIdx.y * 64, b = blockIdx.z;
    const float* xb = x + (size_t)b * Cq * Pq;
#pragma unroll
    for (int i = 0; i < 8; i++) {
        int idx = tid + i * 256;
        int cr = idx >> 5, pc = idx & 31;
        xs[pc][cr] = xb[(size_t)(c0 + cr) * Pq + p0 + pc];
    }
    __syncthreads();
    uint32_t* dhi = (uint32_t*)g_xThi;
    uint32_t* dlo = (uint32_t*)g_xTlo;
#pragma unroll
    for (int i = 0; i < 4; i++) {
        int idx = tid + i * 256;
        int pr = idx >> 5, c2 = (idx & 31) * 2;
        float f0 = xs[pr][c2], f1 = xs[pr][c2 + 1];
        size_t e = (size_t)b * Pq * Cq + (size_t)(p0 + pr) * Cq + c0 + c2;
        dhi[e >> 1] = pack_hi2(f0, f1);
        dlo[e >> 1] = pack_lo2(f0, f1);
    }
}

// Fused dwconv 3x3 -> offset proj -> tanh -> grid coords (smem-staged)
__global__ void __launch_bounds__(256) k_offsets(const float* __restrict__ x,
                                                 const float* __restrict__ dw,
                                                 const float* __restrict__ offw,
                                                 const float* __restrict__ offb) {
    __shared__ float xs[2][4][Wq];
    __shared__ float offw_s[Cq*16];
    __shared__ float dw_s[Cq*9];

    const int tid = threadIdx.x;
    const int px  = tid & 127;
    const int ry  = tid >> 7;
    const int b   = blockIdx.y;
    const int r0  = blockIdx.x * 2;

    for (int i = tid; i < Cq*9; i += 256) dw_s[i] = __ldg(dw + i);
#pragma unroll
    for (int o = 0; o < 16; o++) offw_s[tid*16 + o] = __ldg(offw + o*Cq + tid);

    float acc[16];
#pragma unroll
    for (int o = 0; o < 16; o++) acc[o] = __ldg(offb + o);

    const float* xb = x + (size_t)b * Cq * Pq;
    {
        const float* xc = xb;
#pragma unroll
        for (int j = 0; j < 2; j++) {
            int rr = ry + 2*j;
            int gr = r0 - 1 + rr;
            xs[0][rr][px] = (gr >= 0 && gr < Hq) ? xc[gr*Wq + px] : 0.f;
        }
    }
    __syncthreads();

    for (int c = 0; c < Cq; c++) {
        const int buf = c & 1;
        float hv = 0.f;
        const float* wv = &dw_s[c*9];
#pragma unroll
        for (int ky = 0; ky < 3; ky++) {
            const float* row = xs[buf][ry + ky];
            float wl = wv[ky*3+0], wc = wv[ky*3+1], wr = wv[ky*3+2];
            if (px > 0)      hv = fmaf(row[px-1], wl, hv);
                             hv = fmaf(row[px  ], wc, hv);
            if (px < Wq-1)   hv = fmaf(row[px+1], wr, hv);
        }
#pragma unroll
        for (int o4 = 0; o4 < 4; o4++) {
            float4 w4 = *(const float4*)&offw_s[c*16 + o4*4];
            acc[o4*4+0] = fmaf(hv, w4.x, acc[o4*4+0]);
            acc[o4*4+1] = fmaf(hv, w4.y, acc[o4*4+1]);
            acc[o4*4+2] = fmaf(hv, w4.z, acc[o4*4+2]);
            acc[o4*4+3] = fmaf(hv, w4.w, acc[o4*4+3]);
        }
        if (c + 1 < Cq) {
            const float* xc = xb + (size_t)(c+1) * Pq;
#pragma unroll
            for (int j = 0; j < 2; j++) {
                int rr = ry + 2*j;
                int gr = r0 - 1 + rr;
                xs[buf^1][rr][px] = (gr >= 0 && gr < Hq) ? xc[gr*Wq + px] : 0.f;
            }
            __syncthreads();
        }
    }

    const int y = r0 + ry;
    const int p = y * Wq + px;
    float gy = -1.f + 2.f * (float)y  / (float)(Hq - 1);
    float gx = -1.f + 2.f * (float)px / (float)(Wq - 1);
#pragma unroll
    for (int hh = 0; hh < NHq; hh++) {
        float dy = tanhf(acc[2*hh  ]) * 0.5f;
        float dx = tanhf(acc[2*hh+1]) * 0.5f;
        float sy = fminf(fmaxf(gy + dy, -1.f), 1.f);
        float sx = fminf(fmaxf(gx + dx, -1.f), 1.f);
        g_iy[(b*NHq + hh)*Pq + p] = (sy + 1.f) * 0.5f * (float)(Hq - 1);
        g_ix[(b*NHq + hh)*Pq + p] = (sx + 1.f) * 0.5f * (float)(Wq - 1);
    }
}

// Bilinear sampling: g_V (B,C,P) fp32 -> g_SThi/lo (B,P,C) bf16 hi/lo
__global__ void __launch_bounds__(256) k_sample() {
    __shared__ uint32_t s_hi[256][17];
    __shared__ uint32_t s_lo[256][17];
    const int tid = threadIdx.x;
    const int p0  = blockIdx.x * 256;
    const int hh  = blockIdx.y;
    const int b   = blockIdx.z;
    const int p   = p0 + tid;
    const int bh  = b * NHq + hh;

    float ixv = g_ix[bh*Pq + p];
    float iyv = g_iy[bh*Pq + p];
    float x0f = floorf(ixv), y0f = floorf(iyv);
    float wx = ixv - x0f, wy = iyv - y0f;
    int x0 = min(max((int)x0f,     0), Wq - 1);
    int x1 = min(max((int)x0f + 1, 0), Wq - 1);
    int y0 = min(max((int)y0f,     0), Hq - 1);
    int y1 = min(max((int)y0f + 1, 0), Hq - 1);
    float w00 = (1.f-wx)*(1.f-wy), w01 = wx*(1.f-wy);
    float w10 = (1.f-wx)*wy,       w11 = wx*wy;
    int i00 = y0*Wq + x0, i01 = y0*Wq + x1;
    int i10 = y1*Wq + x0, i11 = y1*Wq + x1;

    const float* Vb = g_V + ((size_t)b * Cq + hh * HDq) * Pq;
#pragma unroll 4
    for (int d = 0; d < 16; d++) {
        const float* V0 = Vb + (size_t)(2*d) * Pq;
        const float* V1 = V0 + Pq;
        float v0 = w00 * __ldg(V0 + i00) + w01 * __ldg(V0 + i01)
                 + w10 * __ldg(V0 + i10) + w11 * __ldg(V0 + i11);
        float v1 = w00 * __ldg(V1 + i00) + w01 * __ldg(V1 + i01)
                 + w10 * __ldg(V1 + i10) + w11 * __ldg(V1 + i11);
        s_hi[tid][d] = pack_hi2(v0, v1);
        s_lo[tid][d] = pack_lo2(v0, v1);
    }
    __syncthreads();

    uint32_t* dhi = (uint32_t*)g_SThi;
    uint32_t* dlo = (uint32_t*)g_STlo;
#pragma unroll
    for (int i = 0; i < 16; i++) {
        int idx = tid + i * 256;
        int row = idx >> 4, col = idx & 15;
        size_t e = (size_t)b * Pq * Cq + (size_t)(p0 + row) * Cq + hh * HDq;
        dhi[(e >> 1) + col] = s_hi[row][col];
        dlo[(e >> 1) + col] = s_lo[row][col];
    }
}

__global__ void k_finalize() {
    int g = threadIdx.x;
    if (g < NGq) {
        float n  = (float)(HDq * Pq);
        float mu = g_sum[g] / n;
        float var = g_sq[g] / n - mu * mu;
        g_mean[g] = mu;
        g_rstd[g] = rsqrtf(var + 1e-5f);
    }
}

__global__ void k_norm(const float* __restrict__ x,
                       const float* __restrict__ gamma,
                       const float* __restrict__ beta,
                       float* __restrict__ out) {
    size_t i = (size_t)blockIdx.x * blockDim.x + threadIdx.x;
    int c = (int)((i / Pq) % Cq);
    int b = (int)(i / ((size_t)Cq * Pq));
    int g = b * NHq + c / HDq;
    float v = out[i];
    out[i] = x[i] + (v - g_mean[g]) * g_rstd[g] * __ldg(gamma + c) + __ldg(beta + c);
}

// ---------------------------------------------------------------- pipelined HMMA GEMM
// Out[b][o][p] = sum_c A[o][c] * Bt[b][p][c] via bf16 hi/lo split (3 passes).
// All operands pre-converted bf16; tiles loaded by cp.async, 2-stage pipeline.
// Stage: A hi/lo [128m][64k] (16KB ea) + B hi/lo [128n][64k] -> 64KB; 2 stages = 128KB.
#define SMEM_GEMM_BYTES (131072 + 64)

template<bool STATS>
__global__ void __launch_bounds__(256, 1) k_gemm_pipe(
    const __nv_bfloat16* __restrict__ Ahi, const __nv_bfloat16* __restrict__ Alo,
    const __nv_bfloat16* __restrict__ Bhi, const __nv_bfloat16* __restrict__ Blo,
    float* __restrict__ Out) {
    extern __shared__ char dsm[];
    const int tid   = threadIdx.x;
    const int lane  = tid & 31;
    const int wid   = tid >> 5;
    const int b     = blockIdx.z;
    const int om    = blockIdx.y * 128;
    const int p0    = blockIdx.x * 128;
    const int mwarp = wid & 1;
    const int nwarp = wid >> 1;

    uint32_t sb = smem_u32(dsm);
    float* ssum = (float*)(dsm + 131072);
    if (STATS && tid < 8) ssum[tid] = 0.f;

    const size_t bofs = (size_t)b * Pq * Cq;
    const __nv_bfloat16* Bh = Bhi + bofs;
    const __nv_bfloat16* Bl = Blo + bofs;

    float acc[4][4][4] = {};

    auto prefetch = [&](int kc, int buf) {
        uint32_t s0 = sb + buf * 65536;
        const int kofs = kc * 64;
#pragma unroll
        for (int i = 0; i < 4; i++) {
            int idx = tid + i * 256;
            int row = idx >> 3, ch = idx & 7;
            uint32_t sw = swz((uint32_t)(row * 128 + ch * 16));
            cp16(s0 + sw,         Ahi + (size_t)(om + row) * Cq + kofs + ch * 8);
            cp16(s0 + 16384 + sw, Alo + (size_t)(om + row) * Cq + kofs + ch * 8);
            cp16(s0 + 32768 + sw, Bh + (size_t)(p0 + row) * Cq + kofs + ch * 8);
            cp16(s0 + 49152 + sw, Bl + (size_t)(p0 + row) * Cq + kofs + ch * 8);
        }
    };

    prefetch(0, 0);
    asm volatile("cp.async.commit_group;");

    for (int kc = 0; kc < 4; kc++) {
        if (kc < 3) {
            prefetch(kc + 1, (kc + 1) & 1);
            asm volatile("cp.async.commit_group;");
            asm volatile("cp.async.wait_group 1;");
        } else {
            asm volatile("cp.async.wait_group 0;");
        }
        __syncthreads();

        const uint32_t sA_hi = sb + (kc & 1) * 65536;
        const uint32_t sB_hi = sA_hi + 32768;

#pragma unroll
        for (int ks = 0; ks < 4; ks++) {
            const int kb = ks * 16;
            uint32_t bh[8], bl[8];
#pragma unroll
            for (int t2 = 0; t2 < 2; t2++) {
                uint32_t ab = b_addr(sB_hi, nwarp * 32 + t2 * 16, kb, lane);
                ldsm4(&bh[t2 * 4], ab);
                ldsm4(&bl[t2 * 4], ab + 16384);
            }
#pragma unroll
            for (int mt = 0; mt < 4; mt++) {
                uint32_t aa = a_addr(sA_hi, mwarp * 64 + mt * 16, kb, lane);
                uint32_t ah[4], al[4];
                ldsm4(ah, aa);
                ldsm4(al, aa + 16384);
#pragma unroll
                for (int nt = 0; nt < 4; nt++) {
                    mma16816(acc[mt][nt], ah, &bh[nt * 2]);
                    mma16816(acc[mt][nt], ah, &bl[nt * 2]);
                    mma16816(acc[mt][nt], al, &bh[nt * 2]);
                }
            }
        }
        __syncthreads();
    }

    // --- Epilogue ---
    const int g  = lane >> 2;
    const int s2 = (lane & 3) * 2;
    float* Ob = Out + (size_t)b * Cq * Pq;
    float slocal[2] = {0.f, 0.f}, qlocal[2] = {0.f, 0.f};

#pragma unroll
    for (int mt = 0; mt < 4; mt++) {
        int o0 = om + mwarp * 64 + mt * 16 + g;
#pragma unroll
        for (int nt = 0; nt < 4; nt++) {
            int p = p0 + nwarp * 32 + nt * 8 + s2;
            float d0 = acc[mt][nt][0], d1 = acc[mt][nt][1];
            float d2 = acc[mt][nt][2], d3 = acc[mt][nt][3];
            *(float2*)(Ob + (size_t)o0 * Pq + p)       = make_float2(d0, d1);
            *(float2*)(Ob + (size_t)(o0 + 8) * Pq + p) = make_float2(d2, d3);
            if (STATS) {
                int j = mt >> 1;
                slocal[j] += d0 + d1 + d2 + d3;
                qlocal[j] += d0*d0 + d1*d1 + d2*d2 + d3*d3;
            }
        }
    }

    if (STATS) {
#pragma unroll
        for (int j = 0; j < 2; j++) {
#pragma unroll
            for (int o = 16; o; o >>= 1) {
                slocal[j] += __shfl_xor_sync(0xFFFFFFFFu, slocal[j], o);
                qlocal[j] += __shfl_xor_sync(0xFFFFFFFFu, qlocal[j], o);
            }
            if (lane == 0) {
                int gidx = mwarp * 2 + j;
                atomicAdd(&ssum[gidx],     slocal[j]);
                atomicAdd(&ssum[4 + gidx], qlocal[j]);
            }
        }
        __syncthreads();
        if (tid < 4) {
            int gg = b * NHq + blockIdx.y * 4 + tid;
            atomicAdd(&g_sum[gg], ssum[tid]);
            atomicAdd(&g_sq[gg],  ssum[4 + tid]);
        }
    }
}

// ---------------------------------------------------------------- launch
extern "C" void kernel_launch(void* const* d_in, const int* in_sizes, int n_in,
                              void* d_out, int out_size) {
    const float* x     = (const float*)d_in[0];
    const float* dw    = (const float*)d_in[1];
    const float* offw  = (const float*)d_in[2];
    const float* offb  = (const float*)d_in[3];
    const float* vw    = (const float*)d_in[4];
    const float* ow    = (const float*)d_in[5];
    const float* gamma = (const float*)d_in[6];
    const float* beta  = (const float*)d_in[7];
    float* out = (float*)d_out;

    cudaFuncSetAttribute(k_gemm_pipe<false>, cudaFuncAttributeMaxDynamicSharedMemorySize, SMEM_GEMM_BYTES);
    cudaFuncSetAttribute(k_gemm_pipe<true>,  cudaFuncAttributeMaxDynamicSharedMemorySize, SMEM_GEMM_BYTES);

    float* gV = nullptr; cudaGetSymbolAddress((void**)&gV, g_V);
    __nv_bfloat16 *xThi, *xTlo, *SThi, *STlo, *wvhi, *wvlo, *wohi, *wolo;
    cudaGetSymbolAddress((void**)&xThi, g_xThi);
    cudaGetSymbolAddress((void**)&xTlo, g_xTlo);
    cudaGetSymbolAddress((void**)&SThi, g_SThi);
    cudaGetSymbolAddress((void**)&STlo, g_STlo);
    cudaGetSymbolAddress((void**)&wvhi, g_wvhi);
    cudaGetSymbolAddress((void**)&wvlo, g_wvlo);
    cudaGetSymbolAddress((void**)&wohi, g_wohi);
    cudaGetSymbolAddress((void**)&wolo, g_wolo);

    k_zero<<<1, 64>>>();
    k_wcvt<<<128, 256>>>(vw, ow);
    k_cvt<<<dim3(Pq/32, Cq/64, Bq), 256>>>(x);
    k_offsets<<<dim3(Hq/2, Bq), 256>>>(x, dw, offw, offb);

    // V projection: g_V = vw @ x
    k_gemm_pipe<false><<<dim3(Pq/128, Cq/128, Bq), 256, SMEM_GEMM_BYTES>>>(wvhi, wvlo, xThi, xTlo, gV);
    // Bilinear sampling -> (P,C) bf16 hi/lo
    k_sample<<<dim3(Pq/256, NHq, Bq), 256>>>();
    // O projection + groupnorm stats, into d_out
    k_gemm_pipe<true><<<dim3(Pq/128, Cq/128, Bq), 256, SMEM_GEMM_BYTES>>>(wohi, wolo, SThi, STlo, out);
    k_finalize<<<1, 64>>>();
    k_norm<<<(Bq*Cq*Pq)/256, 256>>>(x, gamma, beta, out);
}

// round 6
// speedup vs baseline: 1.5078x; 1.5078x over previous
#include <cuda_runtime.h>
#include <cuda_bf16.h>
#include <math.h>
#include <stdint.h>

#define Bq 8
#define Cq 256
#define Hq 128
#define Wq 128
#define Pq (Hq*Wq)
#define NHq 8
#define HDq 32
#define NGq (Bq*NHq)

// Scratch (no allocations allowed)
__device__ float g_ix[Bq*NHq*Pq];
__device__ float g_iy[Bq*NHq*Pq];
__device__ uint32_t g_Vp[(size_t)Bq*Cq*Pq];        // V packed (hi|lo bf16) in (B,NH,P,HD)
__device__ __nv_bfloat16 g_xThi[(size_t)Bq*Pq*Cq]; // x transposed (B,P,C) hi
__device__ __nv_bfloat16 g_xTlo[(size_t)Bq*Pq*Cq]; // x transposed (B,P,C) lo
__device__ __nv_bfloat16 g_SThi[(size_t)Bq*Pq*Cq]; // sampled (B,P,C) hi
__device__ __nv_bfloat16 g_STlo[(size_t)Bq*Pq*Cq]; // sampled (B,P,C) lo
__device__ __nv_bfloat16 g_wvhi[Cq*Cq], g_wvlo[Cq*Cq];
__device__ __nv_bfloat16 g_wohi[Cq*Cq], g_wolo[Cq*Cq];
__device__ float g_sum[NGq];
__device__ float g_sq [NGq];
__device__ float g_mean[NGq];
__device__ float g_rstd[NGq];

// ---------------------------------------------------------------- helpers
__device__ __forceinline__ uint32_t smem_u32(const void* p) {
    uint32_t a;
    asm("{ .reg .u64 t; cvta.to.shared.u64 t, %1; cvt.u32.u64 %0, t; }" : "=r"(a) : "l"(p));
    return a;
}

__device__ __forceinline__ uint32_t swz(uint32_t byte) {
    return byte ^ ((byte >> 3) & 0x70);
}

__device__ __forceinline__ void ldsm4(uint32_t* r, uint32_t a) {
    asm volatile("ldmatrix.sync.aligned.m8n8.x4.shared.b16 {%0,%1,%2,%3}, [%4];"
        : "=r"(r[0]), "=r"(r[1]), "=r"(r[2]), "=r"(r[3]) : "r"(a));
}

__device__ __forceinline__ void mma16816(float* d, const uint32_t* a, const uint32_t* b) {
    asm volatile(
        "mma.sync.aligned.m16n8k16.row.col.f32.bf16.bf16.f32 "
        "{%0,%1,%2,%3}, {%4,%5,%6,%7}, {%8,%9}, {%0,%1,%2,%3};"
        : "+f"(d[0]), "+f"(d[1]), "+f"(d[2]), "+f"(d[3])
        : "r"(a[0]), "r"(a[1]), "r"(a[2]), "r"(a[3]), "r"(b[0]), "r"(b[1]));
}

__device__ __forceinline__ uint32_t a_addr(uint32_t base, int m_base, int kb, int lane) {
    int mat = lane >> 3, r = lane & 7;
    int row = m_base + ((mat & 1) << 3) + r;
    int col = kb + ((mat >> 1) << 3);
    return base + swz((uint32_t)(row * 128 + col * 2));
}

__device__ __forceinline__ uint32_t b_addr(uint32_t base, int n_base, int kb, int lane) {
    int mat = lane >> 3, r = lane & 7;
    int row = n_base + ((mat >> 1) << 3) + r;
    int col = kb + ((mat & 1) << 3);
    return base + swz((uint32_t)(row * 128 + col * 2));
}

__device__ __forceinline__ void cp16(uint32_t s, const void* g) {
    asm volatile("cp.async.cg.shared.global [%0], [%1], 16;" :: "r"(s), "l"(g));
}

__device__ __forceinline__ uint32_t pack_hi2(float a, float b) {
    __nv_bfloat16 ha = __float2bfloat16(a), hb = __float2bfloat16(b);
    return (uint32_t)__bfloat16_as_ushort(ha) | ((uint32_t)__bfloat16_as_ushort(hb) << 16);
}
__device__ __forceinline__ uint32_t pack_lo2(float a, float b) {
    __nv_bfloat16 ha = __float2bfloat16(a), hb = __float2bfloat16(b);
    __nv_bfloat16 la = __float2bfloat16(a - __bfloat162float(ha));
    __nv_bfloat16 lb = __float2bfloat16(b - __bfloat162float(hb));
    return (uint32_t)__bfloat16_as_ushort(la) | ((uint32_t)__bfloat16_as_ushort(lb) << 16);
}
// pack one float as (hi bf16 | lo bf16) in one u32
__device__ __forceinline__ uint32_t pack_hl(float v) {
    __nv_bfloat16 h = __float2bfloat16(v);
    __nv_bfloat16 l = __float2bfloat16(v - __bfloat162float(h));
    return (uint32_t)__bfloat16_as_ushort(h) | ((uint32_t)__bfloat16_as_ushort(l) << 16);
}
// unpack (hi|lo) -> fp32 sum
__device__ __forceinline__ float unpk(uint32_t u) {
    float h = __bfloat162float(__ushort_as_bfloat16((unsigned short)(u & 0xFFFF)));
    float l = __bfloat162float(__ushort_as_bfloat16((unsigned short)(u >> 16)));
    return h + l;
}

// ---------------------------------------------------------------- small kernels
__global__ void k_zero() {
    int i = threadIdx.x;
    if (i < NGq) { g_sum[i] = 0.f; g_sq[i] = 0.f; }
}

__global__ void k_wcvt(const float* __restrict__ vw, const float* __restrict__ ow) {
    int idx = blockIdx.x * 256 + threadIdx.x;
    int e = idx * 2;
    float v0 = __ldg(vw + e), v1 = __ldg(vw + e + 1);
    ((uint32_t*)g_wvhi)[idx] = pack_hi2(v0, v1);
    ((uint32_t*)g_wvlo)[idx] = pack_lo2(v0, v1);
    float o0 = __ldg(ow + e), o1 = __ldg(ow + e + 1);
    ((uint32_t*)g_wohi)[idx] = pack_hi2(o0, o1);
    ((uint32_t*)g_wolo)[idx] = pack_lo2(o0, o1);
}

// x (B,C,P) fp32 -> g_xThi/lo (B,P,C) bf16 hi/lo
__global__ void __launch_bounds__(256) k_cvt(const float* __restrict__ x) {
    __shared__ float xs[32][65];
    const int tid = threadIdx.x;
    const int p0 = blockIdx.x * 32, c0 = blockIdx.y * 64, b = blockIdx.z;
    const float* xb = x + (size_t)b * Cq * Pq;
#pragma unroll
    for (int i = 0; i < 8; i++) {
        int idx = tid + i * 256;
        int cr = idx >> 5, pc = idx & 31;
        xs[pc][cr] = xb[(size_t)(c0 + cr) * Pq + p0 + pc];
    }
    __syncthreads();
    uint32_t* dhi = (uint32_t*)g_xThi;
    uint32_t* dlo = (uint32_t*)g_xTlo;
#pragma unroll
    for (int i = 0; i < 4; i++) {
        int idx = tid + i * 256;
        int pr = idx >> 5, c2 = (idx & 31) * 2;
        float f0 = xs[pr][c2], f1 = xs[pr][c2 + 1];
        size_t e = (size_t)b * Pq * Cq + (size_t)(p0 + pr) * Cq + c0 + c2;
        dhi[e >> 1] = pack_hi2(f0, f1);
        dlo[e >> 1] = pack_lo2(f0, f1);
    }
}

// Fused dwconv 3x3 -> offset proj -> tanh -> grid coords.
// cp.async pipelined over channel groups of 4 (double-buffered).
__global__ void __launch_bounds__(256) k_offsets(const float* __restrict__ x,
                                                 const float* __restrict__ dw,
                                                 const float* __restrict__ offw,
                                                 const float* __restrict__ offb) {
    __shared__ float xs[2][4][4][Wq];   // [buf][ci][row][px] : 16KB
    __shared__ float offw_s[Cq*16];     // [c][o]
    __shared__ float dw_s[Cq*9];

    const int tid = threadIdx.x;
    const int px  = tid & 127;
    const int ry  = tid >> 7;
    const int b   = blockIdx.y;
    const int r0  = blockIdx.x * 2;

    for (int i = tid; i < Cq*9; i += 256) dw_s[i] = __ldg(dw + i);
#pragma unroll
    for (int o = 0; o < 16; o++) offw_s[tid*16 + o] = __ldg(offw + o*Cq + tid);

    float acc[16];
#pragma unroll
    for (int o = 0; o < 16; o++) acc[o] = __ldg(offb + o);

    const float* xb = x + (size_t)b * Cq * Pq;

    auto prefetch = [&](int g, int buf) {
        int c0 = g * 4;
#pragma unroll
        for (int i = 0; i < 2; i++) {
            int idx = tid + i * 256;                 // 0..511
            int ci = idx >> 7;                       // 0..3
            int rr = (idx >> 5) & 3;                 // 0..3
            int p4 = (idx & 31) * 4;
            int gr = r0 - 1 + rr;
            if (gr >= 0 && gr < Hq) {
                cp16(smem_u32(&xs[buf][ci][rr][p4]),
                     xb + (size_t)(c0 + ci) * Pq + gr * Wq + p4);
            } else {
                *(float4*)&xs[buf][ci][rr][p4] = make_float4(0.f, 0.f, 0.f, 0.f);
            }
        }
    };

    prefetch(0, 0);
    asm volatile("cp.async.commit_group;");

    for (int g = 0; g < 64; g++) {
        if (g < 63) {
            prefetch(g + 1, (g + 1) & 1);
            asm volatile("cp.async.commit_group;");
            asm volatile("cp.async.wait_group 1;");
        } else {
            asm volatile("cp.async.wait_group 0;");
        }
        __syncthreads();
        const int buf = g & 1;
        const int c0  = g * 4;
#pragma unroll
        for (int ci = 0; ci < 4; ci++) {
            const int c = c0 + ci;
            const float* wv = &dw_s[c*9];
            float hv = 0.f;
#pragma unroll
            for (int ky = 0; ky < 3; ky++) {
                const float* row = xs[buf][ci][ry + ky];
                if (px > 0)      hv = fmaf(row[px-1], wv[ky*3+0], hv);
                                 hv = fmaf(row[px  ], wv[ky*3+1], hv);
                if (px < Wq-1)   hv = fmaf(row[px+1], wv[ky*3+2], hv);
            }
#pragma unroll
            for (int o4 = 0; o4 < 4; o4++) {
                float4 w4 = *(const float4*)&offw_s[c*16 + o4*4];
                acc[o4*4+0] = fmaf(hv, w4.x, acc[o4*4+0]);
                acc[o4*4+1] = fmaf(hv, w4.y, acc[o4*4+1]);
                acc[o4*4+2] = fmaf(hv, w4.z, acc[o4*4+2]);
                acc[o4*4+3] = fmaf(hv, w4.w, acc[o4*4+3]);
            }
        }
        __syncthreads();
    }

    const int y = r0 + ry;
    const int p = y * Wq + px;
    float gy = -1.f + 2.f * (float)y  / (float)(Hq - 1);
    float gx = -1.f + 2.f * (float)px / (float)(Wq - 1);
#pragma unroll
    for (int hh = 0; hh < NHq; hh++) {
        float dy = tanhf(acc[2*hh  ]) * 0.5f;
        float dx = tanhf(acc[2*hh+1]) * 0.5f;
        float sy = fminf(fmaxf(gy + dy, -1.f), 1.f);
        float sx = fminf(fmaxf(gx + dx, -1.f), 1.f);
        g_iy[(b*NHq + hh)*Pq + p] = (sy + 1.f) * 0.5f * (float)(Hq - 1);
        g_ix[(b*NHq + hh)*Pq + p] = (sx + 1.f) * 0.5f * (float)(Wq - 1);
    }
}

// Bilinear sampling from packed V (B,NH,P,HD) -> g_SThi/lo (B,P,C)
__global__ void __launch_bounds__(256) k_sample() {
    __shared__ uint32_t s_hi[256][17];
    __shared__ uint32_t s_lo[256][17];
    const int tid = threadIdx.x;
    const int p0  = blockIdx.x * 256;
    const int hh  = blockIdx.y;
    const int b   = blockIdx.z;
    const int p   = p0 + tid;
    const int bh  = b * NHq + hh;

    float ixv = g_ix[bh*Pq + p];
    float iyv = g_iy[bh*Pq + p];
    float x0f = floorf(ixv), y0f = floorf(iyv);
    float wx = ixv - x0f, wy = iyv - y0f;
    int x0 = min(max((int)x0f,     0), Wq - 1);
    int x1 = min(max((int)x0f + 1, 0), Wq - 1);
    int y0 = min(max((int)y0f,     0), Hq - 1);
    int y1 = min(max((int)y0f + 1, 0), Hq - 1);
    float w00 = (1.f-wx)*(1.f-wy), w01 = wx*(1.f-wy);
    float w10 = (1.f-wx)*wy,       w11 = wx*wy;

    const uint32_t* V00 = g_Vp + ((size_t)bh * Pq + (y0*Wq + x0)) * HDq;
    const uint32_t* V01 = g_Vp + ((size_t)bh * Pq + (y0*Wq + x1)) * HDq;
    const uint32_t* V10 = g_Vp + ((size_t)bh * Pq + (y1*Wq + x0)) * HDq;
    const uint32_t* V11 = g_Vp + ((size_t)bh * Pq + (y1*Wq + x1)) * HDq;

#pragma unroll
    for (int ch = 0; ch < 4; ch++) {
        const int c0 = ch * 8;
        uint4 a0 = *(const uint4*)(V00 + c0), a1 = *(const uint4*)(V00 + c0 + 4);
        uint4 b0 = *(const uint4*)(V01 + c0), b1 = *(const uint4*)(V01 + c0 + 4);
        uint4 c0v= *(const uint4*)(V10 + c0), c1v= *(const uint4*)(V10 + c0 + 4);
        uint4 d0 = *(const uint4*)(V11 + c0), d1 = *(const uint4*)(V11 + c0 + 4);
        uint32_t ua[8] = {a0.x,a0.y,a0.z,a0.w,a1.x,a1.y,a1.z,a1.w};
        uint32_t ub[8] = {b0.x,b0.y,b0.z,b0.w,b1.x,b1.y,b1.z,b1.w};
        uint32_t uc[8] = {c0v.x,c0v.y,c0v.z,c0v.w,c1v.x,c1v.y,c1v.z,c1v.w};
        uint32_t ud[8] = {d0.x,d0.y,d0.z,d0.w,d1.x,d1.y,d1.z,d1.w};
        float v[8];
#pragma unroll
        for (int j = 0; j < 8; j++) {
            v[j] = w00 * unpk(ua[j]) + w01 * unpk(ub[j])
                 + w10 * unpk(uc[j]) + w11 * unpk(ud[j]);
        }
#pragma unroll
        for (int jj = 0; jj < 4; jj++) {
            s_hi[tid][ch*4 + jj] = pack_hi2(v[2*jj], v[2*jj+1]);
            s_lo[tid][ch*4 + jj] = pack_lo2(v[2*jj], v[2*jj+1]);
        }
    }
    __syncthreads();

    uint32_t* dhi = (uint32_t*)g_SThi;
    uint32_t* dlo = (uint32_t*)g_STlo;
#pragma unroll
    for (int i = 0; i < 16; i++) {
        int idx = tid + i * 256;
        int row = idx >> 4, col = idx & 15;
        size_t e = (size_t)b * Pq * Cq + (size_t)(p0 + row) * Cq + hh * HDq;
        dhi[(e >> 1) + col] = s_hi[row][col];
        dlo[(e >> 1) + col] = s_lo[row][col];
    }
}

__global__ void k_finalize() {
    int g = threadIdx.x;
    if (g < NGq) {
        float n  = (float)(HDq * Pq);
        float mu = g_sum[g] / n;
        float var = g_sq[g] / n - mu * mu;
        g_mean[g] = mu;
        g_rstd[g] = rsqrtf(var + 1e-5f);
    }
}

__global__ void k_norm(const float* __restrict__ x,
                       const float* __restrict__ gamma,
                       const float* __restrict__ beta,
                       float* __restrict__ out) {
    size_t i = (size_t)blockIdx.x * blockDim.x + threadIdx.x;
    int c = (int)((i / Pq) % Cq);
    int b = (int)(i / ((size_t)Cq * Pq));
    int g = b * NHq + c / HDq;
    float v = out[i];
    out[i] = x[i] + (v - g_mean[g]) * g_rstd[g] * __ldg(gamma + c) + __ldg(beta + c);
}

// ---------------------------------------------------------------- pipelined HMMA GEMM
// Out[b][o][p] = sum_c A[o][c] * Bt[b][p][c] via bf16 hi/lo split (3 passes).
// PACKV: epilogue writes packed (hi|lo) u32 V in (B,NH,P,HD) via smem restage.
#define SMEM_GEMM_BYTES (131072 + 64)

template<bool STATS, bool PACKV>
__global__ void __launch_bounds__(256, 1) k_gemm_pipe(
    const __nv_bfloat16* __restrict__ Ahi, const __nv_bfloat16* __restrict__ Alo,
    const __nv_bfloat16* __restrict__ Bhi, const __nv_bfloat16* __restrict__ Blo,
    float* __restrict__ Out) {
    extern __shared__ char dsm[];
    const int tid   = threadIdx.x;
    const int lane  = tid & 31;
    const int wid   = tid >> 5;
    const int b     = blockIdx.z;
    const int om    = blockIdx.y * 128;
    const int p0    = blockIdx.x * 128;
    const int mwarp = wid & 1;
    const int nwarp = wid >> 1;

    uint32_t sb = smem_u32(dsm);
    float* ssum = (float*)(dsm + 131072);
    if (STATS && tid < 8) ssum[tid] = 0.f;

    const size_t bofs = (size_t)b * Pq * Cq;
    const __nv_bfloat16* Bh = Bhi + bofs;
    const __nv_bfloat16* Bl = Blo + bofs;

    float acc[4][4][4] = {};

    auto prefetch = [&](int kc, int buf) {
        uint32_t s0 = sb + buf * 65536;
        const int kofs = kc * 64;
#pragma unroll
        for (int i = 0; i < 4; i++) {
            int idx = tid + i * 256;
            int row = idx >> 3, ch = idx & 7;
            uint32_t sw = swz((uint32_t)(row * 128 + ch * 16));
            cp16(s0 + sw,         Ahi + (size_t)(om + row) * Cq + kofs + ch * 8);
            cp16(s0 + 16384 + sw, Alo + (size_t)(om + row) * Cq + kofs + ch * 8);
            cp16(s0 + 32768 + sw, Bh + (size_t)(p0 + row) * Cq + kofs + ch * 8);
            cp16(s0 + 49152 + sw, Bl + (size_t)(p0 + row) * Cq + kofs + ch * 8);
        }
    };

    prefetch(0, 0);
    asm volatile("cp.async.commit_group;");

    for (int kc = 0; kc < 4; kc++) {
        if (kc < 3) {
            prefetch(kc + 1, (kc + 1) & 1);
            asm volatile("cp.async.commit_group;");
            asm volatile("cp.async.wait_group 1;");
        } else {
            asm volatile("cp.async.wait_group 0;");
        }
        __syncthreads();

        const uint32_t sA_hi = sb + (kc & 1) * 65536;
        const uint32_t sB_hi = sA_hi + 32768;

#pragma unroll
        for (int ks = 0; ks < 4; ks++) {
            const int kb = ks * 16;
            uint32_t bh[8], bl[8];
#pragma unroll
            for (int t2 = 0; t2 < 2; t2++) {
                uint32_t ab = b_addr(sB_hi, nwarp * 32 + t2 * 16, kb, lane);
                ldsm4(&bh[t2 * 4], ab);
                ldsm4(&bl[t2 * 4], ab + 16384);
            }
#pragma unroll
            for (int mt = 0; mt < 4; mt++) {
                uint32_t aa = a_addr(sA_hi, mwarp * 64 + mt * 16, kb, lane);
                uint32_t ah[4], al[4];
                ldsm4(ah, aa);
                ldsm4(al, aa + 16384);
#pragma unroll
                for (int nt = 0; nt < 4; nt++) {
                    mma16816(acc[mt][nt], ah, &bh[nt * 2]);
                    mma16816(acc[mt][nt], ah, &bl[nt * 2]);
                    mma16816(acc[mt][nt], al, &bh[nt * 2]);
                }
            }
        }
        __syncthreads();
    }

    const int g  = lane >> 2;
    const int s2 = (lane & 3) * 2;

    if (PACKV) {
        // Stage packed u32 tile [128 c][128 p] then write (B,NH,P,HD) coalesced
        uint32_t (*stage)[129] = (uint32_t (*)[129])dsm;
#pragma unroll
        for (int mt = 0; mt < 4; mt++) {
            int row = mwarp * 64 + mt * 16 + g;
#pragma unroll
            for (int nt = 0; nt < 4; nt++) {
                int col = nwarp * 32 + nt * 8 + s2;
                stage[row    ][col  ] = pack_hl(acc[mt][nt][0]);
                stage[row    ][col+1] = pack_hl(acc[mt][nt][1]);
                stage[row + 8][col  ] = pack_hl(acc[mt][nt][2]);
                stage[row + 8][col+1] = pack_hl(acc[mt][nt][3]);
            }
        }
        __syncthreads();
        const int head_l = wid & 3;
        const int p_half = (wid >> 2) * 64;
        uint32_t* Vp = g_Vp + ((size_t)(b*NHq + (om >> 5) + head_l) * Pq + p0 + p_half) * HDq;
#pragma unroll 8
        for (int pp = 0; pp < 64; pp++)
            Vp[(size_t)pp * HDq + lane] = stage[head_l*32 + lane][p_half + pp];
        return;
    }

    float* Ob = Out + (size_t)b * Cq * Pq;
    float slocal[2] = {0.f, 0.f}, qlocal[2] = {0.f, 0.f};
#pragma unroll
    for (int mt = 0; mt < 4; mt++) {
        int o0 = om + mwarp * 64 + mt * 16 + g;
#pragma unroll
        for (int nt = 0; nt < 4; nt++) {
            int p = p0 + nwarp * 32 + nt * 8 + s2;
            float d0 = acc[mt][nt][0], d1 = acc[mt][nt][1];
            float d2 = acc[mt][nt][2], d3 = acc[mt][nt][3];
            *(float2*)(Ob + (size_t)o0 * Pq + p)       = make_float2(d0, d1);
            *(float2*)(Ob + (size_t)(o0 + 8) * Pq + p) = make_float2(d2, d3);
            if (STATS) {
                int j = mt >> 1;
                slocal[j] += d0 + d1 + d2 + d3;
                qlocal[j] += d0*d0 + d1*d1 + d2*d2 + d3*d3;
            }
        }
    }

    if (STATS) {
#pragma unroll
        for (int j = 0; j < 2; j++) {
#pragma unroll
            for (int o = 16; o; o >>= 1) {
                slocal[j] += __shfl_xor_sync(0xFFFFFFFFu, slocal[j], o);
                qlocal[j] += __shfl_xor_sync(0xFFFFFFFFu, qlocal[j], o);
            }
            if (lane == 0) {
                int gidx = mwarp * 2 + j;
                atomicAdd(&ssum[gidx],     slocal[j]);
                atomicAdd(&ssum[4 + gidx], qlocal[j]);
            }
        }
        __syncthreads();
        if (tid < 4) {
            int gg = b * NHq + blockIdx.y * 4 + tid;
            atomicAdd(&g_sum[gg], ssum[tid]);
            atomicAdd(&g_sq[gg],  ssum[4 + tid]);
        }
    }
}

// ---------------------------------------------------------------- launch
extern "C" void kernel_launch(void* const* d_in, const int* in_sizes, int n_in,
                              void* d_out, int out_size) {
    const float* x     = (const float*)d_in[0];
    const float* dw    = (const float*)d_in[1];
    const float* offw  = (const float*)d_in[2];
    const float* offb  = (const float*)d_in[3];
    const float* vw    = (const float*)d_in[4];
    const float* ow    = (const float*)d_in[5];
    const float* gamma = (const float*)d_in[6];
    const float* beta  = (const float*)d_in[7];
    float* out = (float*)d_out;

    cudaFuncSetAttribute(k_gemm_pipe<false,true>, cudaFuncAttributeMaxDynamicSharedMemorySize, SMEM_GEMM_BYTES);
    cudaFuncSetAttribute(k_gemm_pipe<true,false>, cudaFuncAttributeMaxDynamicSharedMemorySize, SMEM_GEMM_BYTES);

    __nv_bfloat16 *xThi, *xTlo, *SThi, *STlo, *wvhi, *wvlo, *wohi, *wolo;
    cudaGetSymbolAddress((void**)&xThi, g_xThi);
    cudaGetSymbolAddress((void**)&xTlo, g_xTlo);
    cudaGetSymbolAddress((void**)&SThi, g_SThi);
    cudaGetSymbolAddress((void**)&STlo, g_STlo);
    cudaGetSymbolAddress((void**)&wvhi, g_wvhi);
    cudaGetSymbolAddress((void**)&wvlo, g_wvlo);
    cudaGetSymbolAddress((void**)&wohi, g_wohi);
    cudaGetSymbolAddress((void**)&wolo, g_wolo);

    k_zero<<<1, 64>>>();
    k_wcvt<<<128, 256>>>(vw, ow);
    k_cvt<<<dim3(Pq/32, Cq/64, Bq), 256>>>(x);
    k_offsets<<<dim3(Hq/2, Bq), 256>>>(x, dw, offw, offb);

    // V projection -> packed (B,NH,P,HD)
    k_gemm_pipe<false,true><<<dim3(Pq/128, Cq/128, Bq), 256, SMEM_GEMM_BYTES>>>(wvhi, wvlo, xThi, xTlo, nullptr);
    // Bilinear sampling -> (P,C) bf16 hi/lo
    k_sample<<<dim3(Pq/256, NHq, Bq), 256>>>();
    // O projection + groupnorm stats, into d_out
    k_gemm_pipe<true,false><<<dim3(Pq/128, Cq/128, Bq), 256, SMEM_GEMM_BYTES>>>(wohi, wolo, SThi, STlo, out);
    k_finalize<<<1, 64>>>();
    k_norm<<<(Bq*Cq*Pq)/256, 256>>>(x, gamma, beta, out);
}

// round 7
// speedup vs baseline: 1.5919x; 1.0558x over previous
#include <cuda_runtime.h>
#include <cuda_bf16.h>
#include <math.h>
#include <stdint.h>

#define Bq 8
#define Cq 256
#define Hq 128
#define Wq 128
#define Pq (Hq*Wq)
#define NHq 8
#define HDq 32
#define NGq (Bq*NHq)

// Scratch (no allocations allowed)
__device__ float g_ix[Bq*NHq*Pq];
__device__ float g_iy[Bq*NHq*Pq];
__device__ uint32_t g_Vp[(size_t)Bq*Cq*Pq];        // V packed (hi|lo bf16) in (B,NH,P,HD)
__device__ __nv_bfloat16 g_xThi[(size_t)Bq*Pq*Cq]; // x transposed (B,P,C) hi
__device__ __nv_bfloat16 g_xTlo[(size_t)Bq*Pq*Cq]; // x transposed (B,P,C) lo
__device__ __nv_bfloat16 g_SThi[(size_t)Bq*Pq*Cq]; // sampled (B,P,C) hi
__device__ __nv_bfloat16 g_STlo[(size_t)Bq*Pq*Cq]; // sampled (B,P,C) lo
__device__ __nv_bfloat16 g_wvhi[Cq*Cq], g_wvlo[Cq*Cq];
__device__ __nv_bfloat16 g_wohi[Cq*Cq], g_wolo[Cq*Cq];
__device__ float g_sum[NGq];
__device__ float g_sq [NGq];
__device__ float g_mean[NGq];
__device__ float g_rstd[NGq];

// ---------------------------------------------------------------- helpers
__device__ __forceinline__ uint32_t smem_u32(const void* p) {
    uint32_t a;
    asm("{ .reg .u64 t; cvta.to.shared.u64 t, %1; cvt.u32.u64 %0, t; }" : "=r"(a) : "l"(p));
    return a;
}

__device__ __forceinline__ uint32_t swz(uint32_t byte) {
    return byte ^ ((byte >> 3) & 0x70);
}

__device__ __forceinline__ void ldsm4(uint32_t* r, uint32_t a) {
    asm volatile("ldmatrix.sync.aligned.m8n8.x4.shared.b16 {%0,%1,%2,%3}, [%4];"
        : "=r"(r[0]), "=r"(r[1]), "=r"(r[2]), "=r"(r[3]) : "r"(a));
}

__device__ __forceinline__ void mma16816(float* d, const uint32_t* a, const uint32_t* b) {
    asm volatile(
        "mma.sync.aligned.m16n8k16.row.col.f32.bf16.bf16.f32 "
        "{%0,%1,%2,%3}, {%4,%5,%6,%7}, {%8,%9}, {%0,%1,%2,%3};"
        : "+f"(d[0]), "+f"(d[1]), "+f"(d[2]), "+f"(d[3])
        : "r"(a[0]), "r"(a[1]), "r"(a[2]), "r"(a[3]), "r"(b[0]), "r"(b[1]));
}

__device__ __forceinline__ uint32_t a_addr(uint32_t base, int m_base, int kb, int lane) {
    int mat = lane >> 3, r = lane & 7;
    int row = m_base + ((mat & 1) << 3) + r;
    int col = kb + ((mat >> 1) << 3);
    return base + swz((uint32_t)(row * 128 + col * 2));
}

__device__ __forceinline__ uint32_t b_addr(uint32_t base, int n_base, int kb, int lane) {
    int mat = lane >> 3, r = lane & 7;
    int row = n_base + ((mat >> 1) << 3) + r;
    int col = kb + ((mat & 1) << 3);
    return base + swz((uint32_t)(row * 128 + col * 2));
}

__device__ __forceinline__ void cp16(uint32_t s, const void* g) {
    asm volatile("cp.async.cg.shared.global [%0], [%1], 16;" :: "r"(s), "l"(g));
}

__device__ __forceinline__ uint32_t pack_hi2(float a, float b) {
    __nv_bfloat16 ha = __float2bfloat16(a), hb = __float2bfloat16(b);
    return (uint32_t)__bfloat16_as_ushort(ha) | ((uint32_t)__bfloat16_as_ushort(hb) << 16);
}
__device__ __forceinline__ uint32_t pack_lo2(float a, float b) {
    __nv_bfloat16 ha = __float2bfloat16(a), hb = __float2bfloat16(b);
    __nv_bfloat16 la = __float2bfloat16(a - __bfloat162float(ha));
    __nv_bfloat16 lb = __float2bfloat16(b - __bfloat162float(hb));
    return (uint32_t)__bfloat16_as_ushort(la) | ((uint32_t)__bfloat16_as_ushort(lb) << 16);
}
__device__ __forceinline__ uint32_t pack_hl(float v) {
    __nv_bfloat16 h = __float2bfloat16(v);
    __nv_bfloat16 l = __float2bfloat16(v - __bfloat162float(h));
    return (uint32_t)__bfloat16_as_ushort(h) | ((uint32_t)__bfloat16_as_ushort(l) << 16);
}
__device__ __forceinline__ float unpk(uint32_t u) {
    float h = __bfloat162float(__ushort_as_bfloat16((unsigned short)(u & 0xFFFF)));
    float l = __bfloat162float(__ushort_as_bfloat16((unsigned short)(u >> 16)));
    return h + l;
}

// ---------------------------------------------------------------- small kernels
__global__ void k_zero() {
    int i = threadIdx.x;
    if (i < NGq) { g_sum[i] = 0.f; g_sq[i] = 0.f; }
}

__global__ void k_wcvt(const float* __restrict__ vw, const float* __restrict__ ow) {
    int idx = blockIdx.x * 256 + threadIdx.x;
    int e = idx * 2;
    float v0 = __ldg(vw + e), v1 = __ldg(vw + e + 1);
    ((uint32_t*)g_wvhi)[idx] = pack_hi2(v0, v1);
    ((uint32_t*)g_wvlo)[idx] = pack_lo2(v0, v1);
    float o0 = __ldg(ow + e), o1 = __ldg(ow + e + 1);
    ((uint32_t*)g_wohi)[idx] = pack_hi2(o0, o1);
    ((uint32_t*)g_wolo)[idx] = pack_lo2(o0, o1);
}

// x (B,C,P) fp32 -> g_xThi/lo (B,P,C) bf16 hi/lo
__global__ void __launch_bounds__(256) k_cvt(const float* __restrict__ x) {
    __shared__ float xs[32][65];
    const int tid = threadIdx.x;
    const int p0 = blockIdx.x * 32, c0 = blockIdx.y * 64, b = blockIdx.z;
    const float* xb = x + (size_t)b * Cq * Pq;
#pragma unroll
    for (int i = 0; i < 8; i++) {
        int idx = tid + i * 256;
        int cr = idx >> 5, pc = idx & 31;
        xs[pc][cr] = xb[(size_t)(c0 + cr) * Pq + p0 + pc];
    }
    __syncthreads();
    uint32_t* dhi = (uint32_t*)g_xThi;
    uint32_t* dlo = (uint32_t*)g_xTlo;
#pragma unroll
    for (int i = 0; i < 4; i++) {
        int idx = tid + i * 256;
        int pr = idx >> 5, c2 = (idx & 31) * 2;
        float f0 = xs[pr][c2], f1 = xs[pr][c2 + 1];
        size_t e = (size_t)b * Pq * Cq + (size_t)(p0 + pr) * Cq + c0 + c2;
        dhi[e >> 1] = pack_hi2(f0, f1);
        dlo[e >> 1] = pack_lo2(f0, f1);
    }
}

// Fused dwconv 3x3 -> offset proj -> tanh -> grid coords (cp.async pipelined)
__global__ void __launch_bounds__(256) k_offsets(const float* __restrict__ x,
                                                 const float* __restrict__ dw,
                                                 const float* __restrict__ offw,
                                                 const float* __restrict__ offb) {
    __shared__ float xs[2][4][4][Wq];
    __shared__ float offw_s[Cq*16];
    __shared__ float dw_s[Cq*9];

    const int tid = threadIdx.x;
    const int px  = tid & 127;
    const int ry  = tid >> 7;
    const int b   = blockIdx.y;
    const int r0  = blockIdx.x * 2;

    for (int i = tid; i < Cq*9; i += 256) dw_s[i] = __ldg(dw + i);
#pragma unroll
    for (int o = 0; o < 16; o++) offw_s[tid*16 + o] = __ldg(offw + o*Cq + tid);

    float acc[16];
#pragma unroll
    for (int o = 0; o < 16; o++) acc[o] = __ldg(offb + o);

    const float* xb = x + (size_t)b * Cq * Pq;

    auto prefetch = [&](int g, int buf) {
        int c0 = g * 4;
#pragma unroll
        for (int i = 0; i < 2; i++) {
            int idx = tid + i * 256;
            int ci = idx >> 7;
            int rr = (idx >> 5) & 3;
            int p4 = (idx & 31) * 4;
            int gr = r0 - 1 + rr;
            if (gr >= 0 && gr < Hq) {
                cp16(smem_u32(&xs[buf][ci][rr][p4]),
                     xb + (size_t)(c0 + ci) * Pq + gr * Wq + p4);
            } else {
                *(float4*)&xs[buf][ci][rr][p4] = make_float4(0.f, 0.f, 0.f, 0.f);
            }
        }
    };

    prefetch(0, 0);
    asm volatile("cp.async.commit_group;");

    for (int g = 0; g < 64; g++) {
        if (g < 63) {
            prefetch(g + 1, (g + 1) & 1);
            asm volatile("cp.async.commit_group;");
            asm volatile("cp.async.wait_group 1;");
        } else {
            asm volatile("cp.async.wait_group 0;");
        }
        __syncthreads();
        const int buf = g & 1;
        const int c0  = g * 4;
#pragma unroll
        for (int ci = 0; ci < 4; ci++) {
            const int c = c0 + ci;
            const float* wv = &dw_s[c*9];
            float hv = 0.f;
#pragma unroll
            for (int ky = 0; ky < 3; ky++) {
                const float* row = xs[buf][ci][ry + ky];
                if (px > 0)      hv = fmaf(row[px-1], wv[ky*3+0], hv);
                                 hv = fmaf(row[px  ], wv[ky*3+1], hv);
                if (px < Wq-1)   hv = fmaf(row[px+1], wv[ky*3+2], hv);
            }
#pragma unroll
            for (int o4 = 0; o4 < 4; o4++) {
                float4 w4 = *(const float4*)&offw_s[c*16 + o4*4];
                acc[o4*4+0] = fmaf(hv, w4.x, acc[o4*4+0]);
                acc[o4*4+1] = fmaf(hv, w4.y, acc[o4*4+1]);
                acc[o4*4+2] = fmaf(hv, w4.z, acc[o4*4+2]);
                acc[o4*4+3] = fmaf(hv, w4.w, acc[o4*4+3]);
            }
        }
        __syncthreads();
    }

    const int y = r0 + ry;
    const int p = y * Wq + px;
    float gy = -1.f + 2.f * (float)y  / (float)(Hq - 1);
    float gx = -1.f + 2.f * (float)px / (float)(Wq - 1);
#pragma unroll
    for (int hh = 0; hh < NHq; hh++) {
        float dy = tanhf(acc[2*hh  ]) * 0.5f;
        float dx = tanhf(acc[2*hh+1]) * 0.5f;
        float sy = fminf(fmaxf(gy + dy, -1.f), 1.f);
        float sx = fminf(fmaxf(gx + dx, -1.f), 1.f);
        g_iy[(b*NHq + hh)*Pq + p] = (sy + 1.f) * 0.5f * (float)(Hq - 1);
        g_ix[(b*NHq + hh)*Pq + p] = (sx + 1.f) * 0.5f * (float)(Wq - 1);
    }
}

// Bilinear sampling from packed V (B,NH,P,HD) -> g_SThi/lo (B,P,C)
__global__ void __launch_bounds__(256) k_sample() {
    __shared__ uint32_t s_hi[256][17];
    __shared__ uint32_t s_lo[256][17];
    const int tid = threadIdx.x;
    const int p0  = blockIdx.x * 256;
    const int hh  = blockIdx.y;
    const int b   = blockIdx.z;
    const int p   = p0 + tid;
    const int bh  = b * NHq + hh;

    float ixv = g_ix[bh*Pq + p];
    float iyv = g_iy[bh*Pq + p];
    float x0f = floorf(ixv), y0f = floorf(iyv);
    float wx = ixv - x0f, wy = iyv - y0f;
    int x0 = min(max((int)x0f,     0), Wq - 1);
    int x1 = min(max((int)x0f + 1, 0), Wq - 1);
    int y0 = min(max((int)y0f,     0), Hq - 1);
    int y1 = min(max((int)y0f + 1, 0), Hq - 1);
    float w00 = (1.f-wx)*(1.f-wy), w01 = wx*(1.f-wy);
    float w10 = (1.f-wx)*wy,       w11 = wx*wy;

    const uint32_t* V00 = g_Vp + ((size_t)bh * Pq + (y0*Wq + x0)) * HDq;
    const uint32_t* V01 = g_Vp + ((size_t)bh * Pq + (y0*Wq + x1)) * HDq;
    const uint32_t* V10 = g_Vp + ((size_t)bh * Pq + (y1*Wq + x0)) * HDq;
    const uint32_t* V11 = g_Vp + ((size_t)bh * Pq + (y1*Wq + x1)) * HDq;

#pragma unroll
    for (int ch = 0; ch < 4; ch++) {
        const int c0 = ch * 8;
        uint4 a0 = *(const uint4*)(V00 + c0), a1 = *(const uint4*)(V00 + c0 + 4);
        uint4 b0 = *(const uint4*)(V01 + c0), b1 = *(const uint4*)(V01 + c0 + 4);
        uint4 c0v= *(const uint4*)(V10 + c0), c1v= *(const uint4*)(V10 + c0 + 4);
        uint4 d0 = *(const uint4*)(V11 + c0), d1 = *(const uint4*)(V11 + c0 + 4);
        uint32_t ua[8] = {a0.x,a0.y,a0.z,a0.w,a1.x,a1.y,a1.z,a1.w};
        uint32_t ub[8] = {b0.x,b0.y,b0.z,b0.w,b1.x,b1.y,b1.z,b1.w};
        uint32_t uc[8] = {c0v.x,c0v.y,c0v.z,c0v.w,c1v.x,c1v.y,c1v.z,c1v.w};
        uint32_t ud[8] = {d0.x,d0.y,d0.z,d0.w,d1.x,d1.y,d1.z,d1.w};
        float v[8];
#pragma unroll
        for (int j = 0; j < 8; j++) {
            v[j] = w00 * unpk(ua[j]) + w01 * unpk(ub[j])
                 + w10 * unpk(uc[j]) + w11 * unpk(ud[j]);
        }
#pragma unroll
        for (int jj = 0; jj < 4; jj++) {
            s_hi[tid][ch*4 + jj] = pack_hi2(v[2*jj], v[2*jj+1]);
            s_lo[tid][ch*4 + jj] = pack_lo2(v[2*jj], v[2*jj+1]);
        }
    }
    __syncthreads();

    uint32_t* dhi = (uint32_t*)g_SThi;
    uint32_t* dlo = (uint32_t*)g_STlo;
#pragma unroll
    for (int i = 0; i < 16; i++) {
        int idx = tid + i * 256;
        int row = idx >> 4, col = idx & 15;
        size_t e = (size_t)b * Pq * Cq + (size_t)(p0 + row) * Cq + hh * HDq;
        dhi[(e >> 1) + col] = s_hi[row][col];
        dlo[(e >> 1) + col] = s_lo[row][col];
    }
}

__global__ void k_finalize() {
    int g = threadIdx.x;
    if (g < NGq) {
        float n  = (float)(HDq * Pq);
        float mu = g_sum[g] / n;
        float var = g_sq[g] / n - mu * mu;
        g_mean[g] = mu;
        g_rstd[g] = rsqrtf(var + 1e-5f);
    }
}

__global__ void k_norm(const float* __restrict__ x,
                       const float* __restrict__ gamma,
                       const float* __restrict__ beta,
                       float* __restrict__ out) {
    size_t i = (size_t)blockIdx.x * blockDim.x + threadIdx.x;
    int c = (int)((i / Pq) % Cq);
    int b = (int)(i / ((size_t)Cq * Pq));
    int g = b * NHq + c / HDq;
    float v = out[i];
    out[i] = x[i] + (v - g_mean[g]) * g_rstd[g] * __ldg(gamma + c) + __ldg(beta + c);
}

// ---------------------------------------------------------------- pipelined HMMA GEMM
#define SMEM_GEMM_BYTES (131072 + 64)

template<bool STATS, bool PACKV>
__global__ void __launch_bounds__(256, 1) k_gemm_pipe(
    const __nv_bfloat16* __restrict__ Ahi, const __nv_bfloat16* __restrict__ Alo,
    const __nv_bfloat16* __restrict__ Bhi, const __nv_bfloat16* __restrict__ Blo,
    float* __restrict__ Out) {
    extern __shared__ char dsm[];
    const int tid   = threadIdx.x;
    const int lane  = tid & 31;
    const int wid   = tid >> 5;
    const int b     = blockIdx.z;
    const int om    = blockIdx.y * 128;
    const int p0    = blockIdx.x * 128;
    const int mwarp = wid & 1;
    const int nwarp = wid >> 1;

    uint32_t sb = smem_u32(dsm);
    float* ssum = (float*)(dsm + 131072);
    if (STATS && tid < 8) ssum[tid] = 0.f;

    const size_t bofs = (size_t)b * Pq * Cq;
    const __nv_bfloat16* Bh = Bhi + bofs;
    const __nv_bfloat16* Bl = Blo + bofs;

    float acc[4][4][4] = {};

    auto prefetch = [&](int kc, int buf) {
        uint32_t s0 = sb + buf * 65536;
        const int kofs = kc * 64;
#pragma unroll
        for (int i = 0; i < 4; i++) {
            int idx = tid + i * 256;
            int row = idx >> 3, ch = idx & 7;
            uint32_t sw = swz((uint32_t)(row * 128 + ch * 16));
            cp16(s0 + sw,         Ahi + (size_t)(om + row) * Cq + kofs + ch * 8);
            cp16(s0 + 16384 + sw, Alo + (size_t)(om + row) * Cq + kofs + ch * 8);
            cp16(s0 + 32768 + sw, Bh + (size_t)(p0 + row) * Cq + kofs + ch * 8);
            cp16(s0 + 49152 + sw, Bl + (size_t)(p0 + row) * Cq + kofs + ch * 8);
        }
    };

    prefetch(0, 0);
    asm volatile("cp.async.commit_group;");

    for (int kc = 0; kc < 4; kc++) {
        if (kc < 3) {
            prefetch(kc + 1, (kc + 1) & 1);
            asm volatile("cp.async.commit_group;");
            asm volatile("cp.async.wait_group 1;");
        } else {
            asm volatile("cp.async.wait_group 0;");
        }
        __syncthreads();

        const uint32_t sA_hi = sb + (kc & 1) * 65536;
        const uint32_t sB_hi = sA_hi + 32768;

#pragma unroll
        for (int ks = 0; ks < 4; ks++) {
            const int kb = ks * 16;
            uint32_t bh[8], bl[8];
#pragma unroll
            for (int t2 = 0; t2 < 2; t2++) {
                uint32_t ab = b_addr(sB_hi, nwarp * 32 + t2 * 16, kb, lane);
                ldsm4(&bh[t2 * 4], ab);
                ldsm4(&bl[t2 * 4], ab + 16384);
            }
#pragma unroll
            for (int mt = 0; mt < 4; mt++) {
                uint32_t aa = a_addr(sA_hi, mwarp * 64 + mt * 16, kb, lane);
                uint32_t ah[4], al[4];
                ldsm4(ah, aa);
                ldsm4(al, aa + 16384);
#pragma unroll
                for (int nt = 0; nt < 4; nt++) {
                    mma16816(acc[mt][nt], ah, &bh[nt * 2]);
                    mma16816(acc[mt][nt], ah, &bl[nt * 2]);
                    mma16816(acc[mt][nt], al, &bh[nt * 2]);
                }
            }
        }
        __syncthreads();
    }

    const int g  = lane >> 2;
    const int s2 = (lane & 3) * 2;

    if (PACKV) {
        uint32_t (*stage)[129] = (uint32_t (*)[129])dsm;
#pragma unroll
        for (int mt = 0; mt < 4; mt++) {
            int row = mwarp * 64 + mt * 16 + g;
#pragma unroll
            for (int nt = 0; nt < 4; nt++) {
                int col = nwarp * 32 + nt * 8 + s2;
                stage[row    ][col  ] = pack_hl(acc[mt][nt][0]);
                stage[row    ][col+1] = pack_hl(acc[mt][nt][1]);
                stage[row + 8][col  ] = pack_hl(acc[mt][nt][2]);
                stage[row + 8][col+1] = pack_hl(acc[mt][nt][3]);
            }
        }
        __syncthreads();
        const int head_l = wid & 3;
        const int p_half = (wid >> 2) * 64;
        uint32_t* Vp = g_Vp + ((size_t)(b*NHq + (om >> 5) + head_l) * Pq + p0 + p_half) * HDq;
#pragma unroll 8
        for (int pp = 0; pp < 64; pp++)
            Vp[(size_t)pp * HDq + lane] = stage[head_l*32 + lane][p_half + pp];
        return;
    }

    float* Ob = Out + (size_t)b * Cq * Pq;
    float slocal[2] = {0.f, 0.f}, qlocal[2] = {0.f, 0.f};
#pragma unroll
    for (int mt = 0; mt < 4; mt++) {
        int o0 = om + mwarp * 64 + mt * 16 + g;
#pragma unroll
        for (int nt = 0; nt < 4; nt++) {
            int p = p0 + nwarp * 32 + nt * 8 + s2;
            float d0 = acc[mt][nt][0], d1 = acc[mt][nt][1];
            float d2 = acc[mt][nt][2], d3 = acc[mt][nt][3];
            *(float2*)(Ob + (size_t)o0 * Pq + p)       = make_float2(d0, d1);
            *(float2*)(Ob + (size_t)(o0 + 8) * Pq + p) = make_float2(d2, d3);
            if (STATS) {
                int j = mt >> 1;
                slocal[j] += d0 + d1 + d2 + d3;
                qlocal[j] += d0*d0 + d1*d1 + d2*d2 + d3*d3;
            }
        }
    }

    if (STATS) {
#pragma unroll
        for (int j = 0; j < 2; j++) {
#pragma unroll
            for (int o = 16; o; o >>= 1) {
                slocal[j] += __shfl_xor_sync(0xFFFFFFFFu, slocal[j], o);
                qlocal[j] += __shfl_xor_sync(0xFFFFFFFFu, qlocal[j], o);
            }
            if (lane == 0) {
                int gidx = mwarp * 2 + j;
                atomicAdd(&ssum[gidx],     slocal[j]);
                atomicAdd(&ssum[4 + gidx], qlocal[j]);
            }
        }
        __syncthreads();
        if (tid < 4) {
            int gg = b * NHq + blockIdx.y * 4 + tid;
            atomicAdd(&g_sum[gg], ssum[tid]);
            atomicAdd(&g_sq[gg],  ssum[4 + tid]);
        }
    }
}

// ---------------------------------------------------------------- launch
extern "C" void kernel_launch(void* const* d_in, const int* in_sizes, int n_in,
                              void* d_out, int out_size) {
    const float* x     = (const float*)d_in[0];
    const float* dw    = (const float*)d_in[1];
    const float* offw  = (const float*)d_in[2];
    const float* offb  = (const float*)d_in[3];
    const float* vw    = (const float*)d_in[4];
    const float* ow    = (const float*)d_in[5];
    const float* gamma = (const float*)d_in[6];
    const float* beta  = (const float*)d_in[7];
    float* out = (float*)d_out;

    // One-time resource setup (first call is the non-captured correctness run)
    static cudaStream_t s_side = nullptr;
    static cudaEvent_t  ev_fork = nullptr, ev_join = nullptr;
    if (!s_side) {
        cudaStreamCreateWithFlags(&s_side, cudaStreamNonBlocking);
        cudaEventCreateWithFlags(&ev_fork, cudaEventDisableTiming);
        cudaEventCreateWithFlags(&ev_join, cudaEventDisableTiming);
        cudaFuncSetAttribute(k_gemm_pipe<false,true>, cudaFuncAttributeMaxDynamicSharedMemorySize, SMEM_GEMM_BYTES);
        cudaFuncSetAttribute(k_gemm_pipe<true,false>, cudaFuncAttributeMaxDynamicSharedMemorySize, SMEM_GEMM_BYTES);
    }

    __nv_bfloat16 *xThi, *xTlo, *SThi, *STlo, *wvhi, *wvlo, *wohi, *wolo;
    cudaGetSymbolAddress((void**)&xThi, g_xThi);
    cudaGetSymbolAddress((void**)&xTlo, g_xTlo);
    cudaGetSymbolAddress((void**)&SThi, g_SThi);
    cudaGetSymbolAddress((void**)&STlo, g_STlo);
    cudaGetSymbolAddress((void**)&wvhi, g_wvhi);
    cudaGetSymbolAddress((void**)&wvlo, g_wvlo);
    cudaGetSymbolAddress((void**)&wohi, g_wohi);
    cudaGetSymbolAddress((void**)&wolo, g_wolo);

    // Fork: k_offsets runs on side stream, overlapped with cvt + gemm1
    cudaEventRecord(ev_fork, 0);
    cudaStreamWaitEvent(s_side, ev_fork, 0);
    k_offsets<<<dim3(Hq/2, Bq), 256, 0, s_side>>>(x, dw, offw, offb);
    cudaEventRecord(ev_join, s_side);

    // Main chain
    k_zero<<<1, 64>>>();
    k_wcvt<<<128, 256>>>(vw, ow);
    k_cvt<<<dim3(Pq/32, Cq/64, Bq), 256>>>(x);
    k_gemm_pipe<false,true><<<dim3(Pq/128, Cq/128, Bq), 256, SMEM_GEMM_BYTES>>>(wvhi, wvlo, xThi, xTlo, nullptr);

    // Join: sampling needs both offsets and packed V
    cudaStreamWaitEvent(0, ev_join, 0);
    k_sample<<<dim3(Pq/256, NHq, Bq), 256>>>();
    k_gemm_pipe<true,false><<<dim3(Pq/128, Cq/128, Bq), 256, SMEM_GEMM_BYTES>>>(wohi, wolo, SThi, STlo, out);
    k_finalize<<<1, 64>>>();
    k_norm<<<(Bq*Cq*Pq)/256, 256>>>(x, gamma, beta, out);
}

// round 9
// speedup vs baseline: 1.7319x; 1.0879x over previous
#include <cuda_runtime.h>
#include <cuda_bf16.h>
#include <math.h>
#include <stdint.h>

#define Bq 8
#define Cq 256
#define Hq 128
#define Wq 128
#define Pq (Hq*Wq)
#define NHq 8
#define HDq 32
#define NGq (Bq*NHq)

// Scratch (no allocations allowed)
__device__ float g_ix[Bq*NHq*Pq];
__device__ float g_iy[Bq*NHq*Pq];
__device__ uint32_t g_Vp[(size_t)Bq*Cq*Pq];        // V packed (hi|lo bf16) in (B,NH,P,HD)
__device__ __nv_bfloat16 g_xThi[(size_t)Bq*Pq*Cq]; // x transposed (B,P,C) hi
__device__ __nv_bfloat16 g_xTlo[(size_t)Bq*Pq*Cq]; // x transposed (B,P,C) lo
__device__ __nv_bfloat16 g_SThi[(size_t)Bq*Pq*Cq]; // sampled (B,P,C) hi
__device__ __nv_bfloat16 g_STlo[(size_t)Bq*Pq*Cq]; // sampled (B,P,C) lo
__device__ __nv_bfloat16 g_wvhi[Cq*Cq], g_wvlo[Cq*Cq];
__device__ __nv_bfloat16 g_wohi[Cq*Cq], g_wolo[Cq*Cq];
__device__ float g_sum[NGq];
__device__ float g_sq [NGq];
__device__ float g_mean[NGq];
__device__ float g_rstd[NGq];

// ---------------------------------------------------------------- helpers
__device__ __forceinline__ uint32_t smem_u32(const void* p) {
    uint32_t a;
    asm("{ .reg .u64 t; cvta.to.shared.u64 t, %1; cvt.u32.u64 %0, t; }" : "=r"(a) : "l"(p));
    return a;
}

__device__ __forceinline__ uint32_t swz(uint32_t byte) {
    return byte ^ ((byte >> 3) & 0x70);
}

__device__ __forceinline__ void ldsm4(uint32_t* r, uint32_t a) {
    asm volatile("ldmatrix.sync.aligned.m8n8.x4.shared.b16 {%0,%1,%2,%3}, [%4];"
        : "=r"(r[0]), "=r"(r[1]), "=r"(r[2]), "=r"(r[3]) : "r"(a));
}

__device__ __forceinline__ void mma16816(float* d, const uint32_t* a, const uint32_t* b) {
    asm volatile(
        "mma.sync.aligned.m16n8k16.row.col.f32.bf16.bf16.f32 "
        "{%0,%1,%2,%3}, {%4,%5,%6,%7}, {%8,%9}, {%0,%1,%2,%3};"
        : "+f"(d[0]), "+f"(d[1]), "+f"(d[2]), "+f"(d[3])
        : "r"(a[0]), "r"(a[1]), "r"(a[2]), "r"(a[3]), "r"(b[0]), "r"(b[1]));
}

// A fragment addr: rows 128B, column byte offset cb (includes hi/lo half + k step)
__device__ __forceinline__ uint32_t a_addr(uint32_t base, int m_base, int cb, int lane) {
    int mat = lane >> 3, r = lane & 7;
    int row = m_base + ((mat & 1) << 3) + r;
    return base + swz((uint32_t)(row * 128 + cb + ((mat >> 1) << 4)));
}

__device__ __forceinline__ uint32_t b_addr(uint32_t base, int n_base, int cb, int lane) {
    int mat = lane >> 3, r = lane & 7;
    int row = n_base + ((mat >> 1) << 3) + r;
    return base + swz((uint32_t)(row * 128 + cb + ((mat & 1) << 4)));
}

__device__ __forceinline__ void cp16(uint32_t s, const void* g) {
    asm volatile("cp.async.cg.shared.global [%0], [%1], 16;" :: "r"(s), "l"(g));
}

__device__ __forceinline__ uint32_t pack_hi2(float a, float b) {
    __nv_bfloat16 ha = __float2bfloat16(a), hb = __float2bfloat16(b);
    return (uint32_t)__bfloat16_as_ushort(ha) | ((uint32_t)__bfloat16_as_ushort(hb) << 16);
}
__device__ __forceinline__ uint32_t pack_lo2(float a, float b) {
    __nv_bfloat16 ha = __float2bfloat16(a), hb = __float2bfloat16(b);
    __nv_bfloat16 la = __float2bfloat16(a - __bfloat162float(ha));
    __nv_bfloat16 lb = __float2bfloat16(b - __bfloat162float(hb));
    return (uint32_t)__bfloat16_as_ushort(la) | ((uint32_t)__bfloat16_as_ushort(lb) << 16);
}
__device__ __forceinline__ uint32_t pack_hl(float v) {
    __nv_bfloat16 h = __float2bfloat16(v);
    __nv_bfloat16 l = __float2bfloat16(v - __bfloat162float(h));
    return (uint32_t)__bfloat16_as_ushort(h) | ((uint32_t)__bfloat16_as_ushort(l) << 16);
}
__device__ __forceinline__ float unpk(uint32_t u) {
    float h = __bfloat162float(__ushort_as_bfloat16((unsigned short)(u & 0xFFFF)));
    float l = __bfloat162float(__ushort_as_bfloat16((unsigned short)(u >> 16)));
    return h + l;
}

// ---------------------------------------------------------------- small kernels
__global__ void k_zero() {
    int i = threadIdx.x;
    if (i < NGq) { g_sum[i] = 0.f; g_sq[i] = 0.f; }
}

__global__ void k_wcvt(const float* __restrict__ vw, const float* __restrict__ ow) {
    int idx = blockIdx.x * 256 + threadIdx.x;
    int e = idx * 2;
    float v0 = __ldg(vw + e), v1 = __ldg(vw + e + 1);
    ((uint32_t*)g_wvhi)[idx] = pack_hi2(v0, v1);
    ((uint32_t*)g_wvlo)[idx] = pack_lo2(v0, v1);
    float o0 = __ldg(ow + e), o1 = __ldg(ow + e + 1);
    ((uint32_t*)g_wohi)[idx] = pack_hi2(o0, o1);
    ((uint32_t*)g_wolo)[idx] = pack_lo2(o0, o1);
}

// x (B,C,P) fp32 -> g_xThi/lo (B,P,C) bf16 hi/lo
__global__ void __launch_bounds__(256) k_cvt(const float* __restrict__ x) {
    __shared__ float xs[32][65];
    const int tid = threadIdx.x;
    const int p0 = blockIdx.x * 32, c0 = blockIdx.y * 64, b = blockIdx.z;
    const float* xb = x + (size_t)b * Cq * Pq;
#pragma unroll
    for (int i = 0; i < 8; i++) {
        int idx = tid + i * 256;
        int cr = idx >> 5, pc = idx & 31;
        xs[pc][cr] = xb[(size_t)(c0 + cr) * Pq + p0 + pc];
    }
    __syncthreads();
    uint32_t* dhi = (uint32_t*)g_xThi;
    uint32_t* dlo = (uint32_t*)g_xTlo;
#pragma unroll
    for (int i = 0; i < 4; i++) {
        int idx = tid + i * 256;
        int pr = idx >> 5, c2 = (idx & 31) * 2;
        float f0 = xs[pr][c2], f1 = xs[pr][c2 + 1];
        size_t e = (size_t)b * Pq * Cq + (size_t)(p0 + pr) * Cq + c0 + c2;
        dhi[e >> 1] = pack_hi2(f0, f1);
        dlo[e >> 1] = pack_lo2(f0, f1);
    }
}

// Fused dwconv 3x3 -> offset proj -> tanh -> grid coords (cp.async pipelined)
__global__ void __launch_bounds__(256) k_offsets(const float* __restrict__ x,
                                                 const float* __restrict__ dw,
                                                 const float* __restrict__ offw,
                                                 const float* __restrict__ offb) {
    __shared__ float xs[2][4][4][Wq];
    __shared__ float offw_s[Cq*16];
    __shared__ float dw_s[Cq*9];

    const int tid = threadIdx.x;
    const int px  = tid & 127;
    const int ry  = tid >> 7;
    const int b   = blockIdx.y;
    const int r0  = blockIdx.x * 2;

    for (int i = tid; i < Cq*9; i += 256) dw_s[i] = __ldg(dw + i);
#pragma unroll
    for (int o = 0; o < 16; o++) offw_s[tid*16 + o] = __ldg(offw + o*Cq + tid);

    float acc[16];
#pragma unroll
    for (int o = 0; o < 16; o++) acc[o] = __ldg(offb + o);

    const float* xb = x + (size_t)b * Cq * Pq;

    auto prefetch = [&](int g, int buf) {
        int c0 = g * 4;
#pragma unroll
        for (int i = 0; i < 2; i++) {
            int idx = tid + i * 256;
            int ci = idx >> 7;
            int rr = (idx >> 5) & 3;
            int p4 = (idx & 31) * 4;
            int gr = r0 - 1 + rr;
            if (gr >= 0 && gr < Hq) {
                cp16(smem_u32(&xs[buf][ci][rr][p4]),
                     xb + (size_t)(c0 + ci) * Pq + gr * Wq + p4);
            } else {
                *(float4*)&xs[buf][ci][rr][p4] = make_float4(0.f, 0.f, 0.f, 0.f);
            }
        }
    };

    prefetch(0, 0);
    asm volatile("cp.async.commit_group;");

    for (int g = 0; g < 64; g++) {
        if (g < 63) {
            prefetch(g + 1, (g + 1) & 1);
            asm volatile("cp.async.commit_group;");
            asm volatile("cp.async.wait_group 1;");
        } else {
            asm volatile("cp.async.wait_group 0;");
        }
        __syncthreads();
        const int buf = g & 1;
        const int c0  = g * 4;
#pragma unroll
        for (int ci = 0; ci < 4; ci++) {
            const int c = c0 + ci;
            const float* wv = &dw_s[c*9];
            float hv = 0.f;
#pragma unroll
            for (int ky = 0; ky < 3; ky++) {
                const float* row = xs[buf][ci][ry + ky];
                if (px > 0)      hv = fmaf(row[px-1], wv[ky*3+0], hv);
                                 hv = fmaf(row[px  ], wv[ky*3+1], hv);
                if (px < Wq-1)   hv = fmaf(row[px+1], wv[ky*3+2], hv);
            }
#pragma unroll
            for (int o4 = 0; o4 < 4; o4++) {
                float4 w4 = *(const float4*)&offw_s[c*16 + o4*4];
                acc[o4*4+0] = fmaf(hv, w4.x, acc[o4*4+0]);
                acc[o4*4+1] = fmaf(hv, w4.y, acc[o4*4+1]);
                acc[o4*4+2] = fmaf(hv, w4.z, acc[o4*4+2]);
                acc[o4*4+3] = fmaf(hv, w4.w, acc[o4*4+3]);
            }
        }
        __syncthreads();
    }

    const int y = r0 + ry;
    const int p = y * Wq + px;
    float gy = -1.f + 2.f * (float)y  / (float)(Hq - 1);
    float gx = -1.f + 2.f * (float)px / (float)(Wq - 1);
#pragma unroll
    for (int hh = 0; hh < NHq; hh++) {
        float dy = tanhf(acc[2*hh  ]) * 0.5f;
        float dx = tanhf(acc[2*hh+1]) * 0.5f;
        float sy = fminf(fmaxf(gy + dy, -1.f), 1.f);
        float sx = fminf(fmaxf(gx + dx, -1.f), 1.f);
        g_iy[(b*NHq + hh)*Pq + p] = (sy + 1.f) * 0.5f * (float)(Hq - 1);
        g_ix[(b*NHq + hh)*Pq + p] = (sx + 1.f) * 0.5f * (float)(Wq - 1);
    }
}

// Bilinear sampling from packed V (B,NH,P,HD) -> g_SThi/lo (B,P,C)
__global__ void __launch_bounds__(256) k_sample() {
    __shared__ uint32_t s_hi[256][17];
    __shared__ uint32_t s_lo[256][17];
    const int tid = threadIdx.x;
    const int p0  = blockIdx.x * 256;
    const int hh  = blockIdx.y;
    const int b   = blockIdx.z;
    const int p   = p0 + tid;
    const int bh  = b * NHq + hh;

    float ixv = g_ix[bh*Pq + p];
    float iyv = g_iy[bh*Pq + p];
    float x0f = floorf(ixv), y0f = floorf(iyv);
    float wx = ixv - x0f, wy = iyv - y0f;
    int x0 = min(max((int)x0f,     0), Wq - 1);
    int x1 = min(max((int)x0f + 1, 0), Wq - 1);
    int y0 = min(max((int)y0f,     0), Hq - 1);
    int y1 = min(max((int)y0f + 1, 0), Hq - 1);
    float w00 = (1.f-wx)*(1.f-wy), w01 = wx*(1.f-wy);
    float w10 = (1.f-wx)*wy,       w11 = wx*wy;

    const uint32_t* V00 = g_Vp + ((size_t)bh * Pq + (y0*Wq + x0)) * HDq;
    const uint32_t* V01 = g_Vp + ((size_t)bh * Pq + (y0*Wq + x1)) * HDq;
    const uint32_t* V10 = g_Vp + ((size_t)bh * Pq + (y1*Wq + x0)) * HDq;
    const uint32_t* V11 = g_Vp + ((size_t)bh * Pq + (y1*Wq + x1)) * HDq;

#pragma unroll
    for (int ch = 0; ch < 4; ch++) {
        const int c0 = ch * 8;
        uint4 a0 = *(const uint4*)(V00 + c0), a1 = *(const uint4*)(V00 + c0 + 4);
        uint4 b0 = *(const uint4*)(V01 + c0), b1 = *(const uint4*)(V01 + c0 + 4);
        uint4 c0v= *(const uint4*)(V10 + c0), c1v= *(const uint4*)(V10 + c0 + 4);
        uint4 d0 = *(const uint4*)(V11 + c0), d1 = *(const uint4*)(V11 + c0 + 4);
        uint32_t ua[8] = {a0.x,a0.y,a0.z,a0.w,a1.x,a1.y,a1.z,a1.w};
        uint32_t ub[8] = {b0.x,b0.y,b0.z,b0.w,b1.x,b1.y,b1.z,b1.w};
        uint32_t uc[8] = {c0v.x,c0v.y,c0v.z,c0v.w,c1v.x,c1v.y,c1v.z,c1v.w};
        uint32_t ud[8] = {d0.x,d0.y,d0.z,d0.w,d1.x,d1.y,d1.z,d1.w};
        float v[8];
#pragma unroll
        for (int j = 0; j < 8; j++) {
            v[j] = w00 * unpk(ua[j]) + w01 * unpk(ub[j])
                 + w10 * unpk(uc[j]) + w11 * unpk(ud[j]);
        }
#pragma unroll
        for (int jj = 0; jj < 4; jj++) {
            s_hi[tid][ch*4 + jj] = pack_hi2(v[2*jj], v[2*jj+1]);
            s_lo[tid][ch*4 + jj] = pack_lo2(v[2*jj], v[2*jj+1]);
        }
    }
    __syncthreads();

    uint32_t* dhi = (uint32_t*)g_SThi;
    uint32_t* dlo = (uint32_t*)g_STlo;
#pragma unroll
    for (int i = 0; i < 16; i++) {
        int idx = tid + i * 256;
        int row = idx >> 4, col = idx & 15;
        size_t e = (size_t)b * Pq * Cq + (size_t)(p0 + row) * Cq + hh * HDq;
        dhi[(e >> 1) + col] = s_hi[row][col];
        dlo[(e >> 1) + col] = s_lo[row][col];
    }
}

__global__ void k_finalize() {
    int g = threadIdx.x;
    if (g < NGq) {
        float n  = (float)(HDq * Pq);
        float mu = g_sum[g] / n;
        float var = g_sq[g] / n - mu * mu;
        g_mean[g] = mu;
        g_rstd[g] = rsqrtf(var + 1e-5f);
    }
}

// out = x + (pre - mean)*rstd*gamma + beta  (float4 vectorized)
__global__ void k_norm(const float* __restrict__ x,
                       const float* __restrict__ gamma,
                       const float* __restrict__ beta,
                       float* __restrict__ out) {
    size_t i = ((size_t)blockIdx.x * blockDim.x + threadIdx.x) * 4;
    int c = (int)((i / Pq) % Cq);
    int b = (int)(i / ((size_t)Cq * Pq));
    int g = b * NHq + c / HDq;
    float mu = g_mean[g], rs = g_rstd[g];
    float gm = __ldg(gamma + c), bt = __ldg(beta + c);
    float4 v = *(float4*)(out + i);
    float4 xv = *(const float4*)(x + i);
    v.x = xv.x + (v.x - mu) * rs * gm + bt;
    v.y = xv.y + (v.y - mu) * rs * gm + bt;
    v.z = xv.z + (v.z - mu) * rs * gm + bt;
    v.w = xv.w + (v.w - mu) * rs * gm + bt;
    *(float4*)(out + i) = v;
}

// ---------------------------------------------------------------- pipelined HMMA GEMM
// K-chunks of 32; hi/lo packed in same 128B smem row (hi bytes 0-63, lo 64-127).
// 3-stage cp.async pipeline, 32KB/stage -> 96KB smem -> 2 blocks/SM.
#define STAGE_BYTES 32768
#define NSTAGE 3
#define SMEM_GEMM_BYTES (STAGE_BYTES*NSTAGE + 64)

template<bool STATS, bool PACKV>
__global__ void __launch_bounds__(256, 2) k_gemm_pipe(
    const __nv_bfloat16* __restrict__ Ahi, const __nv_bfloat16* __restrict__ Alo,
    const __nv_bfloat16* __restrict__ Bhi, const __nv_bfloat16* __restrict__ Blo,
    float* __restrict__ Out) {
    extern __shared__ char dsm[];
    const int tid   = threadIdx.x;
    const int lane  = tid & 31;
    const int wid   = tid >> 5;
    const int b     = blockIdx.z;
    const int om    = blockIdx.y * 128;
    const int p0    = blockIdx.x * 128;
    const int mwarp = wid & 1;
    const int nwarp = wid >> 1;

    uint32_t sb = smem_u32(dsm);
    float* ssum = (float*)(dsm + STAGE_BYTES*NSTAGE);
    if (STATS && tid < 8) ssum[tid] = 0.f;

    const size_t bofs = (size_t)b * Pq * Cq;
    const __nv_bfloat16* Bh = Bhi + bofs;
    const __nv_bfloat16* Bl = Blo + bofs;

    float acc[4][4][4] = {};

    // prefetch chunk kc (32 k) into stage buffer
    auto prefetch = [&](int kc, int st) {
        uint32_t s0 = sb + st * STAGE_BYTES;          // A: +0 (16KB), B: +16384
        const int kofs = kc * 32;
#pragma unroll
        for (int i = 0; i < 8; i++) {
            int idx = tid + i * 256;                  // 0..2047
            int t   = idx >> 9;                       // 0=Ahi 1=Alo 2=Bhi 3=Blo
            int r   = (idx >> 2) & 127;
            int ch  = idx & 3;
            uint32_t half = (t & 1) ? 64u : 0u;
            uint32_t base = (t < 2) ? s0 : (s0 + 16384);
            uint32_t dst  = base + swz((uint32_t)(r * 128) + half + ch * 16);
            const __nv_bfloat16* src;
            if (t == 0)      src = Ahi + (size_t)(om + r) * Cq + kofs + ch * 8;
            else if (t == 1) src = Alo + (size_t)(om + r) * Cq + kofs + ch * 8;
            else if (t == 2) src = Bh  + (size_t)(p0 + r) * Cq + kofs + ch * 8;
            else             src = Bl  + (size_t)(p0 + r) * Cq + kofs + ch * 8;
            cp16(dst, src);
        }
    };

    prefetch(0, 0);
    asm volatile("cp.async.commit_group;");
    prefetch(1, 1);
    asm volatile("cp.async.commit_group;");

    for (int kc = 0; kc < 8; kc++) {
        // Barrier BEFORE overwriting stage (kc+2)%3 == (kc-1)%3, which other
        // warps may still be reading from iteration kc-1. Needed for ALL kc>=1.
        if (kc >= 1) __syncthreads();
        if (kc + 2 < 8) {
            prefetch(kc + 2, (kc + 2) % NSTAGE);
            asm volatile("cp.async.commit_group;");
        }
        if (kc < 6)       asm volatile("cp.async.wait_group 2;");
        else if (kc == 6) asm volatile("cp.async.wait_group 1;");
        else              asm volatile("cp.async.wait_group 0;");
        __syncthreads();

        const uint32_t sA = sb + (kc % NSTAGE) * STAGE_BYTES;
        const uint32_t sB = sA + 16384;

#pragma unroll
        for (int ks = 0; ks < 2; ks++) {
            const int cb = ks * 32;        // column byte for hi; lo = cb + 64
            uint32_t bh[8], bl[8];
#pragma unroll
            for (int t2 = 0; t2 < 2; t2++) {
                ldsm4(&bh[t2 * 4], b_addr(sB, nwarp * 32 + t2 * 16, cb,      lane));
                ldsm4(&bl[t2 * 4], b_addr(sB, nwarp * 32 + t2 * 16, cb + 64, lane));
            }
#pragma unroll
            for (int mt = 0; mt < 4; mt++) {
                uint32_t ah[4], al[4];
                ldsm4(ah, a_addr(sA, mwarp * 64 + mt * 16, cb,      lane));
                ldsm4(al, a_addr(sA, mwarp * 64 + mt * 16, cb + 64, lane));
#pragma unroll
                for (int nt = 0; nt < 4; nt++) {
                    mma16816(acc[mt][nt], ah, &bh[nt * 2]);
                    mma16816(acc[mt][nt], ah, &bl[nt * 2]);
                    mma16816(acc[mt][nt], al, &bh[nt * 2]);
                }
            }
        }
    }
    __syncthreads();

    const int g  = lane >> 2;
    const int s2 = (lane & 3) * 2;

    if (PACKV) {
        uint32_t (*stage)[129] = (uint32_t (*)[129])dsm;
#pragma unroll
        for (int mt = 0; mt < 4; mt++) {
            int row = mwarp * 64 + mt * 16 + g;
#pragma unroll
            for (int nt = 0; nt < 4; nt++) {
                int col = nwarp * 32 + nt * 8 + s2;
                stage[row    ][col  ] = pack_hl(acc[mt][nt][0]);
                stage[row    ][col+1] = pack_hl(acc[mt][nt][1]);
                stage[row + 8][col  ] = pack_hl(acc[mt][nt][2]);
                stage[row + 8][col+1] = pack_hl(acc[mt][nt][3]);
            }
        }
        __syncthreads();
        const int head_l = wid & 3;
        const int p_half = (wid >> 2) * 64;
        uint32_t* Vp = g_Vp + ((size_t)(b*NHq + (om >> 5) + head_l) * Pq + p0 + p_half) * HDq;
#pragma unroll 8
        for (int pp = 0; pp < 64; pp++)
            Vp[(size_t)pp * HDq + lane] = stage[head_l*32 + lane][p_half + pp];
        return;
    }

    float* Ob = Out + (size_t)b * Cq * Pq;
    float slocal[2] = {0.f, 0.f}, qlocal[2] = {0.f, 0.f};
#pragma unroll
    for (int mt = 0; mt < 4; mt++) {
        int o0 = om + mwarp * 64 + mt * 16 + g;
#pragma unroll
        for (int nt = 0; nt < 4; nt++) {
            int p = p0 + nwarp * 32 + nt * 8 + s2;
            float d0 = acc[mt][nt][0], d1 = acc[mt][nt][1];
            float d2 = acc[mt][nt][2], d3 = acc[mt][nt][3];
            *(float2*)(Ob + (size_t)o0 * Pq + p)       = make_float2(d0, d1);
            *(float2*)(Ob + (size_t)(o0 + 8) * Pq + p) = make_float2(d2, d3);
            if (STATS) {
                int j = mt >> 1;
                slocal[j] += d0 + d1 + d2 + d3;
                qlocal[j] += d0*d0 + d1*d1 + d2*d2 + d3*d3;
            }
        }
    }

    if (STATS) {
#pragma unroll
        for (int j = 0; j < 2; j++) {
#pragma unroll
            for (int o = 16; o; o >>= 1) {
                slocal[j] += __shfl_xor_sync(0xFFFFFFFFu, slocal[j], o);
                qlocal[j] += __shfl_xor_sync(0xFFFFFFFFu, qlocal[j], o);
            }
            if (lane == 0) {
                int gidx = mwarp * 2 + j;
                atomicAdd(&ssum[gidx],     slocal[j]);
                atomicAdd(&ssum[4 + gidx], qlocal[j]);
            }
        }
        __syncthreads();
        if (tid < 4) {
            int gg = b * NHq + blockIdx.y * 4 + tid;
            atomicAdd(&g_sum[gg], ssum[tid]);
            atomicAdd(&g_sq[gg],  ssum[4 + tid]);
        }
    }
}

// ---------------------------------------------------------------- launch
extern "C" void kernel_launch(void* const* d_in, const int* in_sizes, int n_in,
                              void* d_out, int out_size) {
    const float* x     = (const float*)d_in[0];
    const float* dw    = (const float*)d_in[1];
    const float* offw  = (const float*)d_in[2];
    const float* offb  = (const float*)d_in[3];
    const float* vw    = (const float*)d_in[4];
    const float* ow    = (const float*)d_in[5];
    const float* gamma = (const float*)d_in[6];
    const float* beta  = (const float*)d_in[7];
    float* out = (float*)d_out;

    static cudaStream_t s_side = nullptr;
    static cudaEvent_t  ev_fork = nullptr, ev_join = nullptr;
    if (!s_side) {
        cudaStreamCreateWithFlags(&s_side, cudaStreamNonBlocking);
        cudaEventCreateWithFlags(&ev_fork, cudaEventDisableTiming);
        cudaEventCreateWithFlags(&ev_join, cudaEventDisableTiming);
        cudaFuncSetAttribute(k_gemm_pipe<false,true>, cudaFuncAttributeMaxDynamicSharedMemorySize, SMEM_GEMM_BYTES);
        cudaFuncSetAttribute(k_gemm_pipe<true,false>, cudaFuncAttributeMaxDynamicSharedMemorySize, SMEM_GEMM_BYTES);
    }

    __nv_bfloat16 *xThi, *xTlo, *SThi, *STlo, *wvhi, *wvlo, *wohi, *wolo;
    cudaGetSymbolAddress((void**)&xThi, g_xThi);
    cudaGetSymbolAddress((void**)&xTlo, g_xTlo);
    cudaGetSymbolAddress((void**)&SThi, g_SThi);
    cudaGetSymbolAddress((void**)&STlo, g_STlo);
    cudaGetSymbolAddress((void**)&wvhi, g_wvhi);
    cudaGetSymbolAddress((void**)&wvlo, g_wvlo);
    cudaGetSymbolAddress((void**)&wohi, g_wohi);
    cudaGetSymbolAddress((void**)&wolo, g_wolo);

    // Fork: k_offsets on side stream, overlapped with cvt + gemm1
    cudaEventRecord(ev_fork, 0);
    cudaStreamWaitEvent(s_side, ev_fork, 0);
    k_offsets<<<dim3(Hq/2, Bq), 256, 0, s_side>>>(x, dw, offw, offb);
    cudaEventRecord(ev_join, s_side);

    // Main chain
    k_zero<<<1, 64>>>();
    k_wcvt<<<128, 256>>>(vw, ow);
    k_cvt<<<dim3(Pq/32, Cq/64, Bq), 256>>>(x);
    k_gemm_pipe<false,true><<<dim3(Pq/128, Cq/128, Bq), 256, SMEM_GEMM_BYTES>>>(wvhi, wvlo, xThi, xTlo, nullptr);

    // Join: sampling needs both offsets and packed V
    cudaStreamWaitEvent(0, ev_join, 0);
    k_sample<<<dim3(Pq/256, NHq, Bq), 256>>>();
    k_gemm_pipe<true,false><<<dim3(Pq/128, Cq/128, Bq), 256, SMEM_GEMM_BYTES>>>(wohi, wolo, SThi, STlo, out);
    k_finalize<<<1, 64>>>();
    k_norm<<<(Bq*Cq*Pq)/1024, 256>>>(x, gamma, beta, out);
}

// round 11
// speedup vs baseline: 1.7417x; 1.0057x over previous
#include <cuda_runtime.h>
#include <cuda_bf16.h>
#include <math.h>
#include <stdint.h>

#define Bq 8
#define Cq 256
#define Hq 128
#define Wq 128
#define Pq (Hq*Wq)
#define NHq 8
#define HDq 32
#define NGq (Bq*NHq)

// Scratch (no allocations allowed)
__device__ float g_ix[Bq*NHq*Pq];
__device__ float g_iy[Bq*NHq*Pq];
__device__ uint32_t g_Vp[(size_t)Bq*Cq*Pq];        // V packed (B,NH,P,HD); reused as packed pre-norm (B,C,P)
__device__ __nv_bfloat16 g_xThi[(size_t)Bq*Pq*Cq]; // x transposed (B,P,C) hi
__device__ __nv_bfloat16 g_xTlo[(size_t)Bq*Pq*Cq]; // x transposed (B,P,C) lo
__device__ __nv_bfloat16 g_SThi[(size_t)Bq*Pq*Cq]; // sampled (B,P,C) hi
__device__ __nv_bfloat16 g_STlo[(size_t)Bq*Pq*Cq]; // sampled (B,P,C) lo
__device__ __nv_bfloat16 g_wvhi[Cq*Cq], g_wvlo[Cq*Cq];
__device__ __nv_bfloat16 g_wohi[Cq*Cq], g_wolo[Cq*Cq];
__device__ float g_sum[NGq];
__device__ float g_sq [NGq];
__device__ float g_mean[NGq];
__device__ float g_rstd[NGq];

// ---------------------------------------------------------------- helpers
__device__ __forceinline__ uint32_t smem_u32(const void* p) {
    uint32_t a;
    asm("{ .reg .u64 t; cvta.to.shared.u64 t, %1; cvt.u32.u64 %0, t; }" : "=r"(a) : "l"(p));
    return a;
}

__device__ __forceinline__ uint32_t swz(uint32_t byte) {
    return byte ^ ((byte >> 3) & 0x70);
}

__device__ __forceinline__ void ldsm4(uint32_t* r, uint32_t a) {
    asm volatile("ldmatrix.sync.aligned.m8n8.x4.shared.b16 {%0,%1,%2,%3}, [%4];"
        : "=r"(r[0]), "=r"(r[1]), "=r"(r[2]), "=r"(r[3]) : "r"(a));
}

__device__ __forceinline__ void mma16816(float* d, const uint32_t* a, const uint32_t* b) {
    asm volatile(
        "mma.sync.aligned.m16n8k16.row.col.f32.bf16.bf16.f32 "
        "{%0,%1,%2,%3}, {%4,%5,%6,%7}, {%8,%9}, {%0,%1,%2,%3};"
        : "+f"(d[0]), "+f"(d[1]), "+f"(d[2]), "+f"(d[3])
        : "r"(a[0]), "r"(a[1]), "r"(a[2]), "r"(a[3]), "r"(b[0]), "r"(b[1]));
}

__device__ __forceinline__ uint32_t a_addr(uint32_t base, int m_base, int cb, int lane) {
    int mat = lane >> 3, r = lane & 7;
    int row = m_base + ((mat & 1) << 3) + r;
    return base + swz((uint32_t)(row * 128 + cb + ((mat >> 1) << 4)));
}

__device__ __forceinline__ uint32_t b_addr(uint32_t base, int n_base, int cb, int lane) {
    int mat = lane >> 3, r = lane & 7;
    int row = n_base + ((mat >> 1) << 3) + r;
    return base + swz((uint32_t)(row * 128 + cb + ((mat & 1) << 4)));
}

__device__ __forceinline__ void cp16(uint32_t s, const void* g) {
    asm volatile("cp.async.cg.shared.global [%0], [%1], 16;" :: "r"(s), "l"(g));
}

__device__ __forceinline__ uint32_t pack_hi2(float a, float b) {
    __nv_bfloat16 ha = __float2bfloat16(a), hb = __float2bfloat16(b);
    return (uint32_t)__bfloat16_as_ushort(ha) | ((uint32_t)__bfloat16_as_ushort(hb) << 16);
}
__device__ __forceinline__ uint32_t pack_lo2(float a, float b) {
    __nv_bfloat16 ha = __float2bfloat16(a), hb = __float2bfloat16(b);
    __nv_bfloat16 la = __float2bfloat16(a - __bfloat162float(ha));
    __nv_bfloat16 lb = __float2bfloat16(b - __bfloat162float(hb));
    return (uint32_t)__bfloat16_as_ushort(la) | ((uint32_t)__bfloat16_as_ushort(lb) << 16);
}
__device__ __forceinline__ uint32_t pack_hl(float v) {
    __nv_bfloat16 h = __float2bfloat16(v);
    __nv_bfloat16 l = __float2bfloat16(v - __bfloat162float(h));
    return (uint32_t)__bfloat16_as_ushort(h) | ((uint32_t)__bfloat16_as_ushort(l) << 16);
}
__device__ __forceinline__ float unpk(uint32_t u) {
    float h = __bfloat162float(__ushort_as_bfloat16((unsigned short)(u & 0xFFFF)));
    float l = __bfloat162float(__ushort_as_bfloat16((unsigned short)(u >> 16)));
    return h + l;
}

// ---------------------------------------------------------------- small kernels
__global__ void k_wcvt(const float* __restrict__ vw, const float* __restrict__ ow) {
    int tid = threadIdx.x;
    if (blockIdx.x == 0 && tid < NGq) { g_sum[tid] = 0.f; g_sq[tid] = 0.f; }
    int idx = blockIdx.x * 256 + tid;
    int e = idx * 2;
    float v0 = __ldg(vw + e), v1 = __ldg(vw + e + 1);
    ((uint32_t*)g_wvhi)[idx] = pack_hi2(v0, v1);
    ((uint32_t*)g_wvlo)[idx] = pack_lo2(v0, v1);
    float o0 = __ldg(ow + e), o1 = __ldg(ow + e + 1);
    ((uint32_t*)g_wohi)[idx] = pack_hi2(o0, o1);
    ((uint32_t*)g_wolo)[idx] = pack_lo2(o0, o1);
}

// x (B,C,P) fp32 -> g_xThi/lo (B,P,C) bf16 hi/lo
__global__ void __launch_bounds__(256) k_cvt(const float* __restrict__ x) {
    __shared__ float xs[32][65];
    const int tid = threadIdx.x;
    const int p0 = blockIdx.x * 32, c0 = blockIdx.y * 64, b = blockIdx.z;
    const float* xb = x + (size_t)b * Cq * Pq;
#pragma unroll
    for (int i = 0; i < 8; i++) {
        int idx = tid + i * 256;
        int cr = idx >> 5, pc = idx & 31;
        xs[pc][cr] = xb[(size_t)(c0 + cr) * Pq + p0 + pc];
    }
    __syncthreads();
    uint32_t* dhi = (uint32_t*)g_xThi;
    uint32_t* dlo = (uint32_t*)g_xTlo;
#pragma unroll
    for (int i = 0; i < 4; i++) {
        int idx = tid + i * 256;
        int pr = idx >> 5, c2 = (idx & 31) * 2;
        float f0 = xs[pr][c2], f1 = xs[pr][c2 + 1];
        size_t e = (size_t)b * Pq * Cq + (size_t)(p0 + pr) * Cq + c0 + c2;
        dhi[e >> 1] = pack_hi2(f0, f1);
        dlo[e >> 1] = pack_lo2(f0, f1);
    }
}

// Fused dwconv 3x3 -> offset proj -> tanh -> grid coords (cp.async pipelined)
__global__ void __launch_bounds__(256) k_offsets(const float* __restrict__ x,
                                                 const float* __restrict__ dw,
                                                 const float* __restrict__ offw,
                                                 const float* __restrict__ offb) {
    __shared__ float xs[2][4][4][Wq];
    __shared__ float offw_s[Cq*16];
    __shared__ float dw_s[Cq*9];

    const int tid = threadIdx.x;
    const int px  = tid & 127;
    const int ry  = tid >> 7;
    const int b   = blockIdx.y;
    const int r0  = blockIdx.x * 2;

    for (int i = tid; i < Cq*9; i += 256) dw_s[i] = __ldg(dw + i);
#pragma unroll
    for (int o = 0; o < 16; o++) offw_s[tid*16 + o] = __ldg(offw + o*Cq + tid);

    float acc[16];
#pragma unroll
    for (int o = 0; o < 16; o++) acc[o] = __ldg(offb + o);

    const float* xb = x + (size_t)b * Cq * Pq;

    auto prefetch = [&](int g, int buf) {
        int c0 = g * 4;
#pragma unroll
        for (int i = 0; i < 2; i++) {
            int idx = tid + i * 256;
            int ci = idx >> 7;
            int rr = (idx >> 5) & 3;
            int p4 = (idx & 31) * 4;
            int gr = r0 - 1 + rr;
            if (gr >= 0 && gr < Hq) {
                cp16(smem_u32(&xs[buf][ci][rr][p4]),
                     xb + (size_t)(c0 + ci) * Pq + gr * Wq + p4);
            } else {
                *(float4*)&xs[buf][ci][rr][p4] = make_float4(0.f, 0.f, 0.f, 0.f);
            }
        }
    };

    prefetch(0, 0);
    asm volatile("cp.async.commit_group;");

    for (int g = 0; g < 64; g++) {
        if (g < 63) {
            prefetch(g + 1, (g + 1) & 1);
            asm volatile("cp.async.commit_group;");
            asm volatile("cp.async.wait_group 1;");
        } else {
            asm volatile("cp.async.wait_group 0;");
        }
        __syncthreads();
        const int buf = g & 1;
        const int c0  = g * 4;
#pragma unroll
        for (int ci = 0; ci < 4; ci++) {
            const int c = c0 + ci;
            const float* wv = &dw_s[c*9];
            float hv = 0.f;
#pragma unroll
            for (int ky = 0; ky < 3; ky++) {
                const float* row = xs[buf][ci][ry + ky];
                if (px > 0)      hv = fmaf(row[px-1], wv[ky*3+0], hv);
                                 hv = fmaf(row[px  ], wv[ky*3+1], hv);
                if (px < Wq-1)   hv = fmaf(row[px+1], wv[ky*3+2], hv);
            }
#pragma unroll
            for (int o4 = 0; o4 < 4; o4++) {
                float4 w4 = *(const float4*)&offw_s[c*16 + o4*4];
                acc[o4*4+0] = fmaf(hv, w4.x, acc[o4*4+0]);
                acc[o4*4+1] = fmaf(hv, w4.y, acc[o4*4+1]);
                acc[o4*4+2] = fmaf(hv, w4.z, acc[o4*4+2]);
                acc[o4*4+3] = fmaf(hv, w4.w, acc[o4*4+3]);
            }
        }
        __syncthreads();
    }

    const int y = r0 + ry;
    const int p = y * Wq + px;
    float gy = -1.f + 2.f * (float)y  / (float)(Hq - 1);
    float gx = -1.f + 2.f * (float)px / (float)(Wq - 1);
#pragma unroll
    for (int hh = 0; hh < NHq; hh++) {
        float dy = tanhf(acc[2*hh  ]) * 0.5f;
        float dx = tanhf(acc[2*hh+1]) * 0.5f;
        float sy = fminf(fmaxf(gy + dy, -1.f), 1.f);
        float sx = fminf(fmaxf(gx + dx, -1.f), 1.f);
        g_iy[(b*NHq + hh)*Pq + p] = (sy + 1.f) * 0.5f * (float)(Hq - 1);
        g_ix[(b*NHq + hh)*Pq + p] = (sx + 1.f) * 0.5f * (float)(Wq - 1);
    }
}

// Bilinear sampling from packed V (B,NH,P,HD) -> g_SThi/lo (B,P,C); direct uint4 stores
__global__ void __launch_bounds__(256) k_sample() {
    const int tid = threadIdx.x;
    const int p0  = blockIdx.x * 256;
    const int hh  = blockIdx.y;
    const int b   = blockIdx.z;
    const int p   = p0 + tid;
    const int bh  = b * NHq + hh;

    float ixv = g_ix[bh*Pq + p];
    float iyv = g_iy[bh*Pq + p];
    float x0f = floorf(ixv), y0f = floorf(iyv);
    float wx = ixv - x0f, wy = iyv - y0f;
    int x0 = min(max((int)x0f,     0), Wq - 1);
    int x1 = min(max((int)x0f + 1, 0), Wq - 1);
    int y0 = min(max((int)y0f,     0), Hq - 1);
    int y1 = min(max((int)y0f + 1, 0), Hq - 1);
    float w00 = (1.f-wx)*(1.f-wy), w01 = wx*(1.f-wy);
    float w10 = (1.f-wx)*wy,       w11 = wx*wy;

    const uint32_t* V00 = g_Vp + ((size_t)bh * Pq + (y0*Wq + x0)) * HDq;
    const uint32_t* V01 = g_Vp + ((size_t)bh * Pq + (y0*Wq + x1)) * HDq;
    const uint32_t* V10 = g_Vp + ((size_t)bh * Pq + (y1*Wq + x0)) * HDq;
    const uint32_t* V11 = g_Vp + ((size_t)bh * Pq + (y1*Wq + x1)) * HDq;

    size_t e = (size_t)b * Pq * Cq + (size_t)p * Cq + hh * HDq;   // element index
    uint32_t* dhi = (uint32_t*)g_SThi + (e >> 1);
    uint32_t* dlo = (uint32_t*)g_STlo + (e >> 1);

#pragma unroll
    for (int ch = 0; ch < 4; ch++) {
        const int c0 = ch * 8;
        uint4 a0 = *(const uint4*)(V00 + c0), a1 = *(const uint4*)(V00 + c0 + 4);
        uint4 b0 = *(const uint4*)(V01 + c0), b1 = *(const uint4*)(V01 + c0 + 4);
        uint4 c0v= *(const uint4*)(V10 + c0), c1v= *(const uint4*)(V10 + c0 + 4);
        uint4 d0 = *(const uint4*)(V11 + c0), d1 = *(const uint4*)(V11 + c0 + 4);
        uint32_t ua[8] = {a0.x,a0.y,a0.z,a0.w,a1.x,a1.y,a1.z,a1.w};
        uint32_t ub[8] = {b0.x,b0.y,b0.z,b0.w,b1.x,b1.y,b1.z,b1.w};
        uint32_t uc[8] = {c0v.x,c0v.y,c0v.z,c0v.w,c1v.x,c1v.y,c1v.z,c1v.w};
        uint32_t ud[8] = {d0.x,d0.y,d0.z,d0.w,d1.x,d1.y,d1.z,d1.w};
        float v[8];
#pragma unroll
        for (int j = 0; j < 8; j++) {
            v[j] = w00 * unpk(ua[j]) + w01 * unpk(ub[j])
                 + w10 * unpk(uc[j]) + w11 * unpk(ud[j]);
        }
        uint4 hi4 = make_uint4(pack_hi2(v[0],v[1]), pack_hi2(v[2],v[3]),
                               pack_hi2(v[4],v[5]), pack_hi2(v[6],v[7]));
        uint4 lo4 = make_uint4(pack_lo2(v[0],v[1]), pack_lo2(v[2],v[3]),
                               pack_lo2(v[4],v[5]), pack_lo2(v[6],v[7]));
        *(uint4*)(dhi + ch*4) = hi4;
        *(uint4*)(dlo + ch*4) = lo4;
    }
}

__global__ void k_finalize() {
    int g = threadIdx.x;
    if (g < NGq) {
        float n  = (float)(HDq * Pq);
        float mu = g_sum[g] / n;
        float var = g_sq[g] / n - mu * mu;
        g_mean[g] = mu;
        g_rstd[g] = rsqrtf(var + 1e-5f);
    }
}

// out = x + (pre - mean)*rstd*gamma + beta; pre read as packed hl u32 from g_Vp
__global__ void k_norm(const float* __restrict__ x,
                       const float* __restrict__ gamma,
                       const float* __restrict__ beta,
                       float* __restrict__ out) {
    size_t i = ((size_t)blockIdx.x * blockDim.x + threadIdx.x) * 4;
    int c = (int)((i / Pq) % Cq);
    int b = (int)(i / ((size_t)Cq * Pq));
    int g = b * NHq + c / HDq;
    float mu = g_mean[g], rs = g_rstd[g];
    float gm = __ldg(gamma + c), bt = __ldg(beta + c);
    uint4 pv = *(const uint4*)(g_Vp + i);
    float4 xv = *(const float4*)(x + i);
    float4 o;
    o.x = xv.x + (unpk(pv.x) - mu) * rs * gm + bt;
    o.y = xv.y + (unpk(pv.y) - mu) * rs * gm + bt;
    o.z = xv.z + (unpk(pv.z) - mu) * rs * gm + bt;
    o.w = xv.w + (unpk(pv.w) - mu) * rs * gm + bt;
    *(float4*)(out + i) = o;
}

// ---------------------------------------------------------------- pipelined HMMA GEMM
// K-chunks of 32; hi/lo packed in same 128B smem row. 3-stage cp.async pipeline,
// single __syncthreads per iteration (cutlass ordering).
#define STAGE_BYTES 32768
#define NSTAGE 3
#define SMEM_GEMM_BYTES (STAGE_BYTES*NSTAGE + 64)

template<bool STATS, bool PACKV>
__global__ void __launch_bounds__(256, 2) k_gemm_pipe(
    const __nv_bfloat16* __restrict__ Ahi, const __nv_bfloat16* __restrict__ Alo,
    const __nv_bfloat16* __restrict__ Bhi, const __nv_bfloat16* __restrict__ Blo,
    uint32_t* __restrict__ OutP) {
    extern __shared__ char dsm[];
    const int tid   = threadIdx.x;
    const int lane  = tid & 31;
    const int wid   = tid >> 5;
    const int b     = blockIdx.z;
    const int om    = blockIdx.y * 128;
    const int p0    = blockIdx.x * 128;
    const int mwarp = wid & 1;
    const int nwarp = wid >> 1;

    uint32_t sb = smem_u32(dsm);
    float* ssum = (float*)(dsm + STAGE_BYTES*NSTAGE);
    if (STATS && tid < 8) ssum[tid] = 0.f;

    const size_t bofs = (size_t)b * Pq * Cq;
    const __nv_bfloat16* Bh = Bhi + bofs;
    const __nv_bfloat16* Bl = Blo + bofs;

    float acc[4][4][4] = {};

    auto prefetch = [&](int kc, int st) {
        uint32_t s0 = sb + st * STAGE_BYTES;
        const int kofs = kc * 32;
#pragma unroll
        for (int i = 0; i < 8; i++) {
            int idx = tid + i * 256;
            int t   = idx >> 9;
            int r   = (idx >> 2) & 127;
            int ch  = idx & 3;
            uint32_t half = (t & 1) ? 64u : 0u;
            uint32_t base = (t < 2) ? s0 : (s0 + 16384);
            uint32_t dst  = base + swz((uint32_t)(r * 128) + half + ch * 16);
            const __nv_bfloat16* src;
            if (t == 0)      src = Ahi + (size_t)(om + r) * Cq + kofs + ch * 8;
            else if (t == 1) src = Alo + (size_t)(om + r) * Cq + kofs + ch * 8;
            else if (t == 2) src = Bh  + (size_t)(p0 + r) * Cq + kofs + ch * 8;
            else             src = Bl  + (size_t)(p0 + r) * Cq + kofs + ch * 8;
            cp16(dst, src);
        }
    };

    prefetch(0, 0);
    asm volatile("cp.async.commit_group;");
    prefetch(1, 1);
    asm volatile("cp.async.commit_group;");

    for (int kc = 0; kc < 8; kc++) {
        // wait for chunk kc's copy (it is the oldest outstanding group)
        if (kc < 7) asm volatile("cp.async.wait_group 1;");
        else        asm volatile("cp.async.wait_group 0;");
        // one barrier: after it, all warps finished compute of kc-1, so the
        // stage being overwritten below ( (kc+2)%3 == (kc-1)%3 ) is free.
        __syncthreads();
        if (kc + 2 < 8) {
            prefetch(kc + 2, (kc + 2) % NSTAGE);
            asm volatile("cp.async.commit_group;");
        }

        const uint32_t sA = sb + (kc % NSTAGE) * STAGE_BYTES;
        const uint32_t sB = sA + 16384;

#pragma unroll
        for (int ks = 0; ks < 2; ks++) {
            const int cb = ks * 32;
            uint32_t bh[8], bl[8];
#pragma unroll
            for (int t2 = 0; t2 < 2; t2++) {
                ldsm4(&bh[t2 * 4], b_addr(sB, nwarp * 32 + t2 * 16, cb,      lane));
                ldsm4(&bl[t2 * 4], b_addr(sB, nwarp * 32 + t2 * 16, cb + 64, lane));
            }
#pragma unroll
            for (int mt = 0; mt < 4; mt++) {
                uint32_t ah[4], al[4];
                ldsm4(ah, a_addr(sA, mwarp * 64 + mt * 16, cb,      lane));
                ldsm4(al, a_addr(sA, mwarp * 64 + mt * 16, cb + 64, lane));
#pragma unroll
                for (int nt = 0; nt < 4; nt++) {
                    mma16816(acc[mt][nt], ah, &bh[nt * 2]);
                    mma16816(acc[mt][nt], ah, &bl[nt * 2]);
                    mma16816(acc[mt][nt], al, &bh[nt * 2]);
                }
            }
        }
    }
    __syncthreads();

    const int g  = lane >> 2;
    const int s2 = (lane & 3) * 2;

    if (PACKV) {
        // packed V for sampling: (B,NH,P,HD) via smem restage
        uint32_t (*stage)[129] = (uint32_t (*)[129])dsm;
#pragma unroll
        for (int mt = 0; mt < 4; mt++) {
            int row = mwarp * 64 + mt * 16 + g;
#pragma unroll
            for (int nt = 0; nt < 4; nt++) {
                int col = nwarp * 32 + nt * 8 + s2;
                stage[row    ][col  ] = pack_hl(acc[mt][nt][0]);
                stage[row    ][col+1] = pack_hl(acc[mt][nt][1]);
                stage[row + 8][col  ] = pack_hl(acc[mt][nt][2]);
                stage[row + 8][col+1] = pack_hl(acc[mt][nt][3]);
            }
        }
        __syncthreads();
        const int head_l = wid & 3;
        const int p_half = (wid >> 2) * 64;
        uint32_t* Vp = OutP + ((size_t)(b*NHq + (om >> 5) + head_l) * Pq + p0 + p_half) * HDq;
#pragma unroll 8
        for (int pp = 0; pp < 64; pp++)
            Vp[(size_t)pp * HDq + lane] = stage[head_l*32 + lane][p_half + pp];
        return;
    }

    // non-PACKV: write packed (hi|lo) u32 pre-norm values to OutP (B,C,P layout)
    uint32_t* Ob = OutP + (size_t)b * Cq * Pq;
    float slocal[2] = {0.f, 0.f}, qlocal[2] = {0.f, 0.f};
#pragma unroll
    for (int mt = 0; mt < 4; mt++) {
        int o0 = om + mwarp * 64 + mt * 16 + g;
#pragma unroll
        for (int nt = 0; nt < 4; nt++) {
            int p = p0 + nwarp * 32 + nt * 8 + s2;
            float d0 = acc[mt][nt][0], d1 = acc[mt][nt][1];
            float d2 = acc[mt][nt][2], d3 = acc[mt][nt][3];
            *(uint2*)(Ob + (size_t)o0 * Pq + p)       = make_uint2(pack_hl(d0), pack_hl(d1));
            *(uint2*)(Ob + (size_t)(o0 + 8) * Pq + p) = make_uint2(pack_hl(d2), pack_hl(d3));
            if (STATS) {
                int j = mt >> 1;
                slocal[j] += d0 + d1 + d2 + d3;
                qlocal[j] += d0*d0 + d1*d1 + d2*d2 + d3*d3;
            }
        }
    }

    if (STATS) {
#pragma unroll
        for (int j = 0; j < 2; j++) {
#pragma unroll
            for (int o = 16; o; o >>= 1) {
                slocal[j] += __shfl_xor_sync(0xFFFFFFFFu, slocal[j], o);
                qlocal[j] += __shfl_xor_sync(0xFFFFFFFFu, qlocal[j], o);
            }
            if (lane == 0) {
                int gidx = mwarp * 2 + j;
                atomicAdd(&ssum[gidx],     slocal[j]);
                atomicAdd(&ssum[4 + gidx], qlocal[j]);
            }
        }
        __syncthreads();
        if (tid < 4) {
            int gg = b * NHq + blockIdx.y * 4 + tid;
            atomicAdd(&g_sum[gg], ssum[tid]);
            atomicAdd(&g_sq[gg],  ssum[4 + tid]);
        }
    }
}

// ---------------------------------------------------------------- launch
extern "C" void kernel_launch(void* const* d_in, const int* in_sizes, int n_in,
                              void* d_out, int out_size) {
    const float* x     = (const float*)d_in[0];
    const float* dw    = (const float*)d_in[1];
    const float* offw  = (const float*)d_in[2];
    const float* offb  = (const float*)d_in[3];
    const float* vw    = (const float*)d_in[4];
    const float* ow    = (const float*)d_in[5];
    const float* gamma = (const float*)d_in[6];
    const float* beta  = (const float*)d_in[7];
    float* out = (float*)d_out;

    static cudaStream_t s_side = nullptr;
    static cudaEvent_t  ev_fork = nullptr, ev_join = nullptr;
    if (!s_side) {
        cudaStreamCreateWithFlags(&s_side, cudaStreamNonBlocking);
        cudaEventCreateWithFlags(&ev_fork, cudaEventDisableTiming);
        cudaEventCreateWithFlags(&ev_join, cudaEventDisableTiming);
        cudaFuncSetAttribute(k_gemm_pipe<false,true>, cudaFuncAttributeMaxDynamicSharedMemorySize, SMEM_GEMM_BYTES);
        cudaFuncSetAttribute(k_gemm_pipe<true,false>, cudaFuncAttributeMaxDynamicSharedMemorySize, SMEM_GEMM_BYTES);
    }

    uint32_t* gVp = nullptr;
    cudaGetSymbolAddress((void**)&gVp, g_Vp);
    __nv_bfloat16 *xThi, *xTlo, *SThi, *STlo, *wvhi, *wvlo, *wohi, *wolo;
    cudaGetSymbolAddress((void**)&xThi, g_xThi);
    cudaGetSymbolAddress((void**)&xTlo, g_xTlo);
    cudaGetSymbolAddress((void**)&SThi, g_SThi);
    cudaGetSymbolAddress((void**)&STlo, g_STlo);
    cudaGetSymbolAddress((void**)&wvhi, g_wvhi);
    cudaGetSymbolAddress((void**)&wvlo, g_wvlo);
    cudaGetSymbolAddress((void**)&wohi, g_wohi);
    cudaGetSymbolAddress((void**)&wolo, g_wolo);

    // Fork: k_offsets on side stream, overlapped with cvt + gemm1
    cudaEventRecord(ev_fork, 0);
    cudaStreamWaitEvent(s_side, ev_fork, 0);
    k_offsets<<<dim3(Hq/2, Bq), 256, 0, s_side>>>(x, dw, offw, offb);
    cudaEventRecord(ev_join, s_side);

    // Main chain
    k_wcvt<<<128, 256>>>(vw, ow);
    k_cvt<<<dim3(Pq/32, Cq/64, Bq), 256>>>(x);
    // V projection -> packed (B,NH,P,HD) in g_Vp
    k_gemm_pipe<false,true><<<dim3(Pq/128, Cq/128, Bq), 256, SMEM_GEMM_BYTES>>>(wvhi, wvlo, xThi, xTlo, gVp);

    // Join: sampling needs both offsets and packed V
    cudaStreamWaitEvent(0, ev_join, 0);
    k_sample<<<dim3(Pq/256, NHq, Bq), 256>>>();
    // O projection -> packed pre-norm into g_Vp (V no longer needed) + stats
    k_gemm_pipe<true,false><<<dim3(Pq/128, Cq/128, Bq), 256, SMEM_GEMM_BYTES>>>(wohi, wolo, SThi, STlo, gVp);
    k_finalize<<<1, 64>>>();
    k_norm<<<(Bq*Cq*Pq)/1024, 256>>>(x, gamma, beta, out);
}

// round 12
// speedup vs baseline: 2.1533x; 1.2363x over previous
#include <cuda_runtime.h>
#include <cuda_bf16.h>
#include <cuda_fp16.h>
#include <math.h>
#include <stdint.h>

#define Bq 8
#define Cq 256
#define Hq 128
#define Wq 128
#define Pq (Hq*Wq)
#define NHq 8
#define HDq 32
#define NGq (Bq*NHq)

// Scratch (no allocations allowed)
__device__ float g_ix[Bq*NHq*Pq];
__device__ float g_iy[Bq*NHq*Pq];
__device__ uint32_t g_Vp[(size_t)Bq*Cq*Pq];        // V packed (bf16 hi|lo) (B,NH,P,HD); reused as packed pre-norm (B,C,P)
__device__ __half g_xT[(size_t)Bq*Pq*Cq];          // x transposed (B,P,C) fp16
__device__ __half g_ST[(size_t)Bq*Pq*Cq];          // sampled (B,P,C) fp16
__device__ __half g_wvhi[Cq*Cq], g_wvlo[Cq*Cq];    // weights fp16 hi/lo
__device__ __half g_wohi[Cq*Cq], g_wolo[Cq*Cq];
__device__ float g_sum[NGq];
__device__ float g_sq [NGq];
__device__ float g_mean[NGq];
__device__ float g_rstd[NGq];

// ---------------------------------------------------------------- helpers
__device__ __forceinline__ uint32_t smem_u32(const void* p) {
    uint32_t a;
    asm("{ .reg .u64 t; cvta.to.shared.u64 t, %1; cvt.u32.u64 %0, t; }" : "=r"(a) : "l"(p));
    return a;
}

__device__ __forceinline__ uint32_t swz(uint32_t byte) {
    return byte ^ ((byte >> 3) & 0x70);
}

__device__ __forceinline__ void ldsm4(uint32_t* r, uint32_t a) {
    asm volatile("ldmatrix.sync.aligned.m8n8.x4.shared.b16 {%0,%1,%2,%3}, [%4];"
        : "=r"(r[0]), "=r"(r[1]), "=r"(r[2]), "=r"(r[3]) : "r"(a));
}

// fp16 MMA, fp32 accumulate
__device__ __forceinline__ void mma16816(float* d, const uint32_t* a, const uint32_t* b) {
    asm volatile(
        "mma.sync.aligned.m16n8k16.row.col.f32.f16.f16.f32 "
        "{%0,%1,%2,%3}, {%4,%5,%6,%7}, {%8,%9}, {%0,%1,%2,%3};"
        : "+f"(d[0]), "+f"(d[1]), "+f"(d[2]), "+f"(d[3])
        : "r"(a[0]), "r"(a[1]), "r"(a[2]), "r"(a[3]), "r"(b[0]), "r"(b[1]));
}

__device__ __forceinline__ uint32_t a_addr(uint32_t base, int m_base, int cb, int lane) {
    int mat = lane >> 3, r = lane & 7;
    int row = m_base + ((mat & 1) << 3) + r;
    return base + swz((uint32_t)(row * 128 + cb + ((mat >> 1) << 4)));
}

__device__ __forceinline__ uint32_t b_addr(uint32_t base, int n_base, int cb, int lane) {
    int mat = lane >> 3, r = lane & 7;
    int row = n_base + ((mat >> 1) << 3) + r;
    return base + swz((uint32_t)(row * 128 + cb + ((mat & 1) << 4)));
}

__device__ __forceinline__ void cp16(uint32_t s, const void* g) {
    asm volatile("cp.async.cg.shared.global [%0], [%1], 16;" :: "r"(s), "l"(g));
}

// fp16 packers
__device__ __forceinline__ uint32_t pack2h(float a, float b) {
    __half2 h = __floats2half2_rn(a, b);
    return *(uint32_t*)&h;
}
__device__ __forceinline__ uint32_t pack2h_lo(float a, float b) {
    __half ha = __float2half_rn(a), hb = __float2half_rn(b);
    __half2 l = __floats2half2_rn(a - __half2float(ha), b - __half2float(hb));
    return *(uint32_t*)&l;
}
// bf16 hi|lo pair packers (for V / pre-norm storage)
__device__ __forceinline__ uint32_t pack_hl(float v) {
    __nv_bfloat16 h = __float2bfloat16(v);
    __nv_bfloat16 l = __float2bfloat16(v - __bfloat162float(h));
    return (uint32_t)__bfloat16_as_ushort(h) | ((uint32_t)__bfloat16_as_ushort(l) << 16);
}
__device__ __forceinline__ float unpk(uint32_t u) {
    float h = __bfloat162float(__ushort_as_bfloat16((unsigned short)(u & 0xFFFF)));
    float l = __bfloat162float(__ushort_as_bfloat16((unsigned short)(u >> 16)));
    return h + l;
}

// ---------------------------------------------------------------- small kernels
__global__ void k_wcvt(const float* __restrict__ vw, const float* __restrict__ ow) {
    int tid = threadIdx.x;
    if (blockIdx.x == 0 && tid < NGq) { g_sum[tid] = 0.f; g_sq[tid] = 0.f; }
    int idx = blockIdx.x * 256 + tid;
    int e = idx * 2;
    float v0 = __ldg(vw + e), v1 = __ldg(vw + e + 1);
    ((uint32_t*)g_wvhi)[idx] = pack2h(v0, v1);
    ((uint32_t*)g_wvlo)[idx] = pack2h_lo(v0, v1);
    float o0 = __ldg(ow + e), o1 = __ldg(ow + e + 1);
    ((uint32_t*)g_wohi)[idx] = pack2h(o0, o1);
    ((uint32_t*)g_wolo)[idx] = pack2h_lo(o0, o1);
}

// x (B,C,P) fp32 -> g_xT (B,P,C) fp16
__global__ void __launch_bounds__(256) k_cvt(const float* __restrict__ x) {
    __shared__ float xs[32][65];
    const int tid = threadIdx.x;
    const int p0 = blockIdx.x * 32, c0 = blockIdx.y * 64, b = blockIdx.z;
    const float* xb = x + (size_t)b * Cq * Pq;
#pragma unroll
    for (int i = 0; i < 8; i++) {
        int idx = tid + i * 256;
        int cr = idx >> 5, pc = idx & 31;
        xs[pc][cr] = xb[(size_t)(c0 + cr) * Pq + p0 + pc];
    }
    __syncthreads();
    uint32_t* dst = (uint32_t*)g_xT;
#pragma unroll
    for (int i = 0; i < 4; i++) {
        int idx = tid + i * 256;
        int pr = idx >> 5, c2 = (idx & 31) * 2;
        size_t e = (size_t)b * Pq * Cq + (size_t)(p0 + pr) * Cq + c0 + c2;
        dst[e >> 1] = pack2h(xs[pr][c2], xs[pr][c2 + 1]);
    }
}

// Fused dwconv 3x3 -> offset proj -> tanh -> grid coords (cp.async pipelined)
__global__ void __launch_bounds__(256) k_offsets(const float* __restrict__ x,
                                                 const float* __restrict__ dw,
                                                 const float* __restrict__ offw,
                                                 const float* __restrict__ offb) {
    __shared__ float xs[2][4][4][Wq];
    __shared__ float offw_s[Cq*16];
    __shared__ float dw_s[Cq*9];

    const int tid = threadIdx.x;
    const int px  = tid & 127;
    const int ry  = tid >> 7;
    const int b   = blockIdx.y;
    const int r0  = blockIdx.x * 2;

    for (int i = tid; i < Cq*9; i += 256) dw_s[i] = __ldg(dw + i);
#pragma unroll
    for (int o = 0; o < 16; o++) offw_s[tid*16 + o] = __ldg(offw + o*Cq + tid);

    float acc[16];
#pragma unroll
    for (int o = 0; o < 16; o++) acc[o] = __ldg(offb + o);

    const float* xb = x + (size_t)b * Cq * Pq;

    auto prefetch = [&](int g, int buf) {
        int c0 = g * 4;
#pragma unroll
        for (int i = 0; i < 2; i++) {
            int idx = tid + i * 256;
            int ci = idx >> 7;
            int rr = (idx >> 5) & 3;
            int p4 = (idx & 31) * 4;
            int gr = r0 - 1 + rr;
            if (gr >= 0 && gr < Hq) {
                cp16(smem_u32(&xs[buf][ci][rr][p4]),
                     xb + (size_t)(c0 + ci) * Pq + gr * Wq + p4);
            } else {
                *(float4*)&xs[buf][ci][rr][p4] = make_float4(0.f, 0.f, 0.f, 0.f);
            }
        }
    };

    prefetch(0, 0);
    asm volatile("cp.async.commit_group;");

    for (int g = 0; g < 64; g++) {
        if (g < 63) {
            prefetch(g + 1, (g + 1) & 1);
            asm volatile("cp.async.commit_group;");
            asm volatile("cp.async.wait_group 1;");
        } else {
            asm volatile("cp.async.wait_group 0;");
        }
        __syncthreads();
        const int buf = g & 1;
        const int c0  = g * 4;
#pragma unroll
        for (int ci = 0; ci < 4; ci++) {
            const int c = c0 + ci;
            const float* wv = &dw_s[c*9];
            float hv = 0.f;
#pragma unroll
            for (int ky = 0; ky < 3; ky++) {
                const float* row = xs[buf][ci][ry + ky];
                if (px > 0)      hv = fmaf(row[px-1], wv[ky*3+0], hv);
                                 hv = fmaf(row[px  ], wv[ky*3+1], hv);
                if (px < Wq-1)   hv = fmaf(row[px+1], wv[ky*3+2], hv);
            }
#pragma unroll
            for (int o4 = 0; o4 < 4; o4++) {
                float4 w4 = *(const float4*)&offw_s[c*16 + o4*4];
                acc[o4*4+0] = fmaf(hv, w4.x, acc[o4*4+0]);
                acc[o4*4+1] = fmaf(hv, w4.y, acc[o4*4+1]);
                acc[o4*4+2] = fmaf(hv, w4.z, acc[o4*4+2]);
                acc[o4*4+3] = fmaf(hv, w4.w, acc[o4*4+3]);
            }
        }
        __syncthreads();
    }

    const int y = r0 + ry;
    const int p = y * Wq + px;
    float gy = -1.f + 2.f * (float)y  / (float)(Hq - 1);
    float gx = -1.f + 2.f * (float)px / (float)(Wq - 1);
#pragma unroll
    for (int hh = 0; hh < NHq; hh++) {
        float dy = tanhf(acc[2*hh  ]) * 0.5f;
        float dx = tanhf(acc[2*hh+1]) * 0.5f;
        float sy = fminf(fmaxf(gy + dy, -1.f), 1.f);
        float sx = fminf(fmaxf(gx + dx, -1.f), 1.f);
        g_iy[(b*NHq + hh)*Pq + p] = (sy + 1.f) * 0.5f * (float)(Hq - 1);
        g_ix[(b*NHq + hh)*Pq + p] = (sx + 1.f) * 0.5f * (float)(Wq - 1);
    }
}

// Bilinear sampling from packed V (B,NH,P,HD) -> g_ST (B,P,C) fp16
__global__ void __launch_bounds__(256) k_sample() {
    const int tid = threadIdx.x;
    const int p0  = blockIdx.x * 256;
    const int hh  = blockIdx.y;
    const int b   = blockIdx.z;
    const int p   = p0 + tid;
    const int bh  = b * NHq + hh;

    float ixv = g_ix[bh*Pq + p];
    float iyv = g_iy[bh*Pq + p];
    float x0f = floorf(ixv), y0f = floorf(iyv);
    float wx = ixv - x0f, wy = iyv - y0f;
    int x0 = min(max((int)x0f,     0), Wq - 1);
    int x1 = min(max((int)x0f + 1, 0), Wq - 1);
    int y0 = min(max((int)y0f,     0), Hq - 1);
    int y1 = min(max((int)y0f + 1, 0), Hq - 1);
    float w00 = (1.f-wx)*(1.f-wy), w01 = wx*(1.f-wy);
    float w10 = (1.f-wx)*wy,       w11 = wx*wy;

    const uint32_t* V00 = g_Vp + ((size_t)bh * Pq + (y0*Wq + x0)) * HDq;
    const uint32_t* V01 = g_Vp + ((size_t)bh * Pq + (y0*Wq + x1)) * HDq;
    const uint32_t* V10 = g_Vp + ((size_t)bh * Pq + (y1*Wq + x0)) * HDq;
    const uint32_t* V11 = g_Vp + ((size_t)bh * Pq + (y1*Wq + x1)) * HDq;

    size_t e = (size_t)b * Pq * Cq + (size_t)p * Cq + hh * HDq;
    uint32_t* dst = (uint32_t*)g_ST + (e >> 1);

#pragma unroll
    for (int ch = 0; ch < 4; ch++) {
        const int c0 = ch * 8;
        uint4 a0 = *(const uint4*)(V00 + c0), a1 = *(const uint4*)(V00 + c0 + 4);
        uint4 b0 = *(const uint4*)(V01 + c0), b1 = *(const uint4*)(V01 + c0 + 4);
        uint4 c0v= *(const uint4*)(V10 + c0), c1v= *(const uint4*)(V10 + c0 + 4);
        uint4 d0 = *(const uint4*)(V11 + c0), d1 = *(const uint4*)(V11 + c0 + 4);
        uint32_t ua[8] = {a0.x,a0.y,a0.z,a0.w,a1.x,a1.y,a1.z,a1.w};
        uint32_t ub[8] = {b0.x,b0.y,b0.z,b0.w,b1.x,b1.y,b1.z,b1.w};
        uint32_t uc[8] = {c0v.x,c0v.y,c0v.z,c0v.w,c1v.x,c1v.y,c1v.z,c1v.w};
        uint32_t ud[8] = {d0.x,d0.y,d0.z,d0.w,d1.x,d1.y,d1.z,d1.w};
        float v[8];
#pragma unroll
        for (int j = 0; j < 8; j++) {
            v[j] = w00 * unpk(ua[j]) + w01 * unpk(ub[j])
                 + w10 * unpk(uc[j]) + w11 * unpk(ud[j]);
        }
        uint4 o4 = make_uint4(pack2h(v[0],v[1]), pack2h(v[2],v[3]),
                              pack2h(v[4],v[5]), pack2h(v[6],v[7]));
        *(uint4*)(dst + ch*4) = o4;
    }
}

__global__ void k_finalize() {
    int g = threadIdx.x;
    if (g < NGq) {
        float n  = (float)(HDq * Pq);
        float mu = g_sum[g] / n;
        float var = g_sq[g] / n - mu * mu;
        g_mean[g] = mu;
        g_rstd[g] = rsqrtf(var + 1e-5f);
    }
}

// out = x + (pre - mean)*rstd*gamma + beta; pre read as packed bf16-pair from g_Vp
__global__ void k_norm(const float* __restrict__ x,
                       const float* __restrict__ gamma,
                       const float* __restrict__ beta,
                       float* __restrict__ out) {
    size_t i = ((size_t)blockIdx.x * blockDim.x + threadIdx.x) * 4;
    int c = (int)((i / Pq) % Cq);
    int b = (int)(i / ((size_t)Cq * Pq));
    int g = b * NHq + c / HDq;
    float mu = g_mean[g], rs = g_rstd[g];
    float gm = __ldg(gamma + c), bt = __ldg(beta + c);
    uint4 pv = *(const uint4*)(g_Vp + i);
    float4 xv = *(const float4*)(x + i);
    float4 o;
    o.x = xv.x + (unpk(pv.x) - mu) * rs * gm + bt;
    o.y = xv.y + (unpk(pv.y) - mu) * rs * gm + bt;
    o.z = xv.z + (unpk(pv.z) - mu) * rs * gm + bt;
    o.w = xv.w + (unpk(pv.w) - mu) * rs * gm + bt;
    *(float4*)(out + i) = o;
}

// ---------------------------------------------------------------- pipelined HMMA GEMM (fp16, 2-pass)
// D = (Ah + Al) · B.  Chunk = 64 k. Stage: Ahi 16KB | Alo 16KB | B 16KB = 48KB.
// 2 stages -> 96KB smem, 2 blocks/SM. Schedule: wait(0) -> sync -> prefetch(kc+1) -> compute(kc).
#define STAGE_BYTES 49152
#define NSTAGE 2
#define SMEM_GEMM_BYTES (STAGE_BYTES*NSTAGE + 64)

template<bool STATS, bool PACKV>
__global__ void __launch_bounds__(256, 2) k_gemm_pipe(
    const __half* __restrict__ Ahi, const __half* __restrict__ Alo,
    const __half* __restrict__ B,
    uint32_t* __restrict__ OutP) {
    extern __shared__ char dsm[];
    const int tid   = threadIdx.x;
    const int lane  = tid & 31;
    const int wid   = tid >> 5;
    const int b     = blockIdx.z;
    const int om    = blockIdx.y * 128;
    const int p0    = blockIdx.x * 128;
    const int mwarp = wid & 1;
    const int nwarp = wid >> 1;

    uint32_t sb = smem_u32(dsm);
    float* ssum = (float*)(dsm + STAGE_BYTES*NSTAGE);
    if (STATS && tid < 8) ssum[tid] = 0.f;

    const __half* Bb = B + (size_t)b * Pq * Cq;

    float acc[4][4][4] = {};

    // prefetch chunk kc (64 k) into stage st: 3 tiles x 16KB, 12 cp16/thread
    auto prefetch = [&](int kc, int st) {
        uint32_t s0 = sb + st * STAGE_BYTES;
        const int kofs = kc * 64;
#pragma unroll
        for (int i = 0; i < 12; i++) {
            int idx = tid + i * 256;                 // 0..3071
            int t   = idx >> 10;                     // 0=Ahi 1=Alo 2=B
            int r   = (idx >> 3) & 127;
            int ch  = idx & 7;
            uint32_t dst = s0 + t * 16384 + swz((uint32_t)(r * 128 + ch * 16));
            const __half* src;
            if (t == 0)      src = Ahi + (size_t)(om + r) * Cq + kofs + ch * 8;
            else if (t == 1) src = Alo + (size_t)(om + r) * Cq + kofs + ch * 8;
            else             src = Bb  + (size_t)(p0 + r) * Cq + kofs + ch * 8;
            cp16(dst, src);
        }
    };

    prefetch(0, 0);
    asm volatile("cp.async.commit_group;");

    for (int kc = 0; kc < 4; kc++) {
        asm volatile("cp.async.wait_group 0;");   // chunk kc copy done
        __syncthreads();                          // also: all warps done with kc-1 (frees other stage)
        if (kc + 1 < 4) {
            prefetch(kc + 1, (kc + 1) & 1);       // overlaps compute below
            asm volatile("cp.async.commit_group;");
        }

        const uint32_t sA_hi = sb + (kc & 1) * STAGE_BYTES;
        const uint32_t sA_lo = sA_hi + 16384;
        const uint32_t sB    = sA_hi + 32768;

#pragma unroll
        for (int ks = 0; ks < 4; ks++) {
            const int cb = ks * 32;               // 16 fp16 = 32 bytes per k16 step
            uint32_t bf[8];
#pragma unroll
            for (int t2 = 0; t2 < 2; t2++)
                ldsm4(&bf[t2 * 4], b_addr(sB, nwarp * 32 + t2 * 16, cb, lane));
#pragma unroll
            for (int mt = 0; mt < 4; mt++) {
                uint32_t ah[4], al[4];
                ldsm4(ah, a_addr(sA_hi, mwarp * 64 + mt * 16, cb, lane));
                ldsm4(al, a_addr(sA_lo, mwarp * 64 + mt * 16, cb, lane));
#pragma unroll
                for (int nt = 0; nt < 4; nt++) {
                    mma16816(acc[mt][nt], ah, &bf[nt * 2]);
                    mma16816(acc[mt][nt], al, &bf[nt * 2]);
                }
            }
        }
    }
    __syncthreads();

    const int g  = lane >> 2;
    const int s2 = (lane & 3) * 2;

    if (PACKV) {
        // packed V (bf16 hi|lo) for sampling: (B,NH,P,HD) via smem restage
        uint32_t (*stage)[129] = (uint32_t (*)[129])dsm;
#pragma unroll
        for (int mt = 0; mt < 4; mt++) {
            int row = mwarp * 64 + mt * 16 + g;
#pragma unroll
            for (int nt = 0; nt < 4; nt++) {
                int col = nwarp * 32 + nt * 8 + s2;
                stage[row    ][col  ] = pack_hl(acc[mt][nt][0]);
                stage[row    ][col+1] = pack_hl(acc[mt][nt][1]);
                stage[row + 8][col  ] = pack_hl(acc[mt][nt][2]);
                stage[row + 8][col+1] = pack_hl(acc[mt][nt][3]);
            }
        }
        __syncthreads();
        const int head_l = wid & 3;
        const int p_half = (wid >> 2) * 64;
        uint32_t* Vp = OutP + ((size_t)(b*NHq + (om >> 5) + head_l) * Pq + p0 + p_half) * HDq;
#pragma unroll 8
        for (int pp = 0; pp < 64; pp++)
            Vp[(size_t)pp * HDq + lane] = stage[head_l*32 + lane][p_half + pp];
        return;
    }

    // write packed (bf16 hi|lo) pre-norm values to OutP (B,C,P layout) + stats
    uint32_t* Ob = OutP + (size_t)b * Cq * Pq;
    float slocal[2] = {0.f, 0.f}, qlocal[2] = {0.f, 0.f};
#pragma unroll
    for (int mt = 0; mt < 4; mt++) {
        int o0 = om + mwarp * 64 + mt * 16 + g;
#pragma unroll
        for (int nt = 0; nt < 4; nt++) {
            int p = p0 + nwarp * 32 + nt * 8 + s2;
            float d0 = acc[mt][nt][0], d1 = acc[mt][nt][1];
            float d2 = acc[mt][nt][2], d3 = acc[mt][nt][3];
            *(uint2*)(Ob + (size_t)o0 * Pq + p)       = make_uint2(pack_hl(d0), pack_hl(d1));
            *(uint2*)(Ob + (size_t)(o0 + 8) * Pq + p) = make_uint2(pack_hl(d2), pack_hl(d3));
            if (STATS) {
                int j = mt >> 1;
                slocal[j] += d0 + d1 + d2 + d3;
                qlocal[j] += d0*d0 + d1*d1 + d2*d2 + d3*d3;
            }
        }
    }

    if (STATS) {
#pragma unroll
        for (int j = 0; j < 2; j++) {
#pragma unroll
            for (int o = 16; o; o >>= 1) {
                slocal[j] += __shfl_xor_sync(0xFFFFFFFFu, slocal[j], o);
                qlocal[j] += __shfl_xor_sync(0xFFFFFFFFu, qlocal[j], o);
            }
            if (lane == 0) {
                int gidx = mwarp * 2 + j;
                atomicAdd(&ssum[gidx],     slocal[j]);
                atomicAdd(&ssum[4 + gidx], qlocal[j]);
            }
        }
        __syncthreads();
        if (tid < 4) {
            int gg = b * NHq + blockIdx.y * 4 + tid;
            atomicAdd(&g_sum[gg], ssum[tid]);
            atomicAdd(&g_sq[gg],  ssum[4 + tid]);
        }
    }
}

// ---------------------------------------------------------------- launch
extern "C" void kernel_launch(void* const* d_in, const int* in_sizes, int n_in,
                              void* d_out, int out_size) {
    const float* x     = (const float*)d_in[0];
    const float* dw    = (const float*)d_in[1];
    const float* offw  = (const float*)d_in[2];
    const float* offb  = (const float*)d_in[3];
    const float* vw    = (const float*)d_in[4];
    const float* ow    = (const float*)d_in[5];
    const float* gamma = (const float*)d_in[6];
    const float* beta  = (const float*)d_in[7];
    float* out = (float*)d_out;

    static cudaStream_t s_side = nullptr;
    static cudaEvent_t  ev_fork = nullptr, ev_join = nullptr;
    if (!s_side) {
        cudaStreamCreateWithFlags(&s_side, cudaStreamNonBlocking);
        cudaEventCreateWithFlags(&ev_fork, cudaEventDisableTiming);
        cudaEventCreateWithFlags(&ev_join, cudaEventDisableTiming);
        cudaFuncSetAttribute(k_gemm_pipe<false,true>, cudaFuncAttributeMaxDynamicSharedMemorySize, SMEM_GEMM_BYTES);
        cudaFuncSetAttribute(k_gemm_pipe<true,false>, cudaFuncAttributeMaxDynamicSharedMemorySize, SMEM_GEMM_BYTES);
    }

    uint32_t* gVp = nullptr;
    cudaGetSymbolAddress((void**)&gVp, g_Vp);
    __half *xT, *ST, *wvhi, *wvlo, *wohi, *wolo;
    cudaGetSymbolAddress((void**)&xT,   g_xT);
    cudaGetSymbolAddress((void**)&ST,   g_ST);
    cudaGetSymbolAddress((void**)&wvhi, g_wvhi);
    cudaGetSymbolAddress((void**)&wvlo, g_wvlo);
    cudaGetSymbolAddress((void**)&wohi, g_wohi);
    cudaGetSymbolAddress((void**)&wolo, g_wolo);

    // Fork: k_offsets on side stream, overlapped with cvt + gemm1
    cudaEventRecord(ev_fork, 0);
    cudaStreamWaitEvent(s_side, ev_fork, 0);
    k_offsets<<<dim3(Hq/2, Bq), 256, 0, s_side>>>(x, dw, offw, offb);
    cudaEventRecord(ev_join, s_side);

    // Main chain
    k_wcvt<<<128, 256>>>(vw, ow);
    k_cvt<<<dim3(Pq/32, Cq/64, Bq), 256>>>(x);
    // V projection -> packed (B,NH,P,HD) in g_Vp
    k_gemm_pipe<false,true><<<dim3(Pq/128, Cq/128, Bq), 256, SMEM_GEMM_BYTES>>>(wvhi, wvlo, xT, gVp);

    // Join: sampling needs both offsets and packed V
    cudaStreamWaitEvent(0, ev_join, 0);
    k_sample<<<dim3(Pq/256, NHq, Bq), 256>>>();
    // O projection -> packed pre-norm into g_Vp (V no longer needed) + stats
    k_gemm_pipe<true,false><<<dim3(Pq/128, Cq/128, Bq), 256, SMEM_GEMM_BYTES>>>(wohi, wolo, ST, gVp);
    k_finalize<<<1, 64>>>();
    k_norm<<<(Bq*Cq*Pq)/1024, 256>>>(x, gamma, beta, out);
}

// round 14
// speedup vs baseline: 2.4239x; 1.1257x over previous
#include <cuda_runtime.h>
#include <cuda_bf16.h>
#include <cuda_fp16.h>
#include <math.h>
#include <stdint.h>

#define Bq 8
#define Cq 256
#define Hq 128
#define Wq 128
#define Pq (Hq*Wq)
#define NHq 8
#define HDq 32
#define NGq (Bq*NHq)

// Scratch (no allocations allowed)
__device__ float g_ix[Bq*NHq*Pq];
__device__ float g_iy[Bq*NHq*Pq];
__device__ uint32_t g_Vp[(size_t)Bq*Cq*Pq];        // V packed (bf16 hi|lo) (B,NH,P,HD); reused as packed pre-norm (B,C,P)
__device__ __half g_xT[(size_t)Bq*Pq*Cq];          // x transposed (B,P,C) fp16
__device__ __half g_ST[(size_t)Bq*Pq*Cq];          // sampled (B,P,C) fp16
__device__ __half g_wv[Cq*Cq];                     // weights fp16
__device__ __half g_wo[Cq*Cq];
__device__ float g_sum[NGq];
__device__ float g_sq [NGq];
__device__ float g_mean[NGq];
__device__ float g_rstd[NGq];

// ---------------------------------------------------------------- helpers
__device__ __forceinline__ uint32_t smem_u32(const void* p) {
    uint32_t a;
    asm("{ .reg .u64 t; cvta.to.shared.u64 t, %1; cvt.u32.u64 %0, t; }" : "=r"(a) : "l"(p));
    return a;
}

__device__ __forceinline__ uint32_t swz(uint32_t byte) {
    return byte ^ ((byte >> 3) & 0x70);
}

__device__ __forceinline__ void ldsm4(uint32_t* r, uint32_t a) {
    asm volatile("ldmatrix.sync.aligned.m8n8.x4.shared.b16 {%0,%1,%2,%3}, [%4];"
        : "=r"(r[0]), "=r"(r[1]), "=r"(r[2]), "=r"(r[3]) : "r"(a));
}

// fp16 MMA, fp32 accumulate
__device__ __forceinline__ void mma16816(float* d, const uint32_t* a, const uint32_t* b) {
    asm volatile(
        "mma.sync.aligned.m16n8k16.row.col.f32.f16.f16.f32 "
        "{%0,%1,%2,%3}, {%4,%5,%6,%7}, {%8,%9}, {%0,%1,%2,%3};"
        : "+f"(d[0]), "+f"(d[1]), "+f"(d[2]), "+f"(d[3])
        : "r"(a[0]), "r"(a[1]), "r"(a[2]), "r"(a[3]), "r"(b[0]), "r"(b[1]));
}

__device__ __forceinline__ uint32_t a_addr(uint32_t base, int m_base, int cb, int lane) {
    int mat = lane >> 3, r = lane & 7;
    int row = m_base + ((mat & 1) << 3) + r;
    return base + swz((uint32_t)(row * 128 + cb + ((mat >> 1) << 4)));
}

__device__ __forceinline__ uint32_t b_addr(uint32_t base, int n_base, int cb, int lane) {
    int mat = lane >> 3, r = lane & 7;
    int row = n_base + ((mat >> 1) << 3) + r;
    return base + swz((uint32_t)(row * 128 + cb + ((mat & 1) << 4)));
}

__device__ __forceinline__ void cp16(uint32_t s, const void* g) {
    asm volatile("cp.async.cg.shared.global [%0], [%1], 16;" :: "r"(s), "l"(g));
}

__device__ __forceinline__ uint32_t pack2h(float a, float b) {
    __half2 h = __floats2half2_rn(a, b);
    return *(uint32_t*)&h;
}
// bf16 hi|lo pair packers (for V / pre-norm storage)
__device__ __forceinline__ uint32_t pack_hl(float v) {
    __nv_bfloat16 h = __float2bfloat16(v);
    __nv_bfloat16 l = __float2bfloat16(v - __bfloat162float(h));
    return (uint32_t)__bfloat16_as_ushort(h) | ((uint32_t)__bfloat16_as_ushort(l) << 16);
}
__device__ __forceinline__ float unpk(uint32_t u) {
    float h = __bfloat162float(__ushort_as_bfloat16((unsigned short)(u & 0xFFFF)));
    float l = __bfloat162float(__ushort_as_bfloat16((unsigned short)(u >> 16)));
    return h + l;
}

// ---------------------------------------------------------------- small kernels
__global__ void k_wcvt(const float* __restrict__ vw, const float* __restrict__ ow) {
    int tid = threadIdx.x;
    if (blockIdx.x == 0 && tid < NGq) { g_sum[tid] = 0.f; g_sq[tid] = 0.f; }
    int idx = blockIdx.x * 256 + tid;
    int e = idx * 2;
    ((uint32_t*)g_wv)[idx] = pack2h(__ldg(vw + e), __ldg(vw + e + 1));
    ((uint32_t*)g_wo)[idx] = pack2h(__ldg(ow + e), __ldg(ow + e + 1));
}

// x (B,C,P) fp32 -> g_xT (B,P,C) fp16
__global__ void __launch_bounds__(256) k_cvt(const float* __restrict__ x) {
    __shared__ float xs[32][65];
    const int tid = threadIdx.x;
    const int p0 = blockIdx.x * 32, c0 = blockIdx.y * 64, b = blockIdx.z;
    const float* xb = x + (size_t)b * Cq * Pq;
#pragma unroll
    for (int i = 0; i < 8; i++) {
        int idx = tid + i * 256;
        int cr = idx >> 5, pc = idx & 31;
        xs[pc][cr] = xb[(size_t)(c0 + cr) * Pq + p0 + pc];
    }
    __syncthreads();
    uint32_t* dst = (uint32_t*)g_xT;
#pragma unroll
    for (int i = 0; i < 4; i++) {
        int idx = tid + i * 256;
        int pr = idx >> 5, c2 = (idx & 31) * 2;
        size_t e = (size_t)b * Pq * Cq + (size_t)(p0 + pr) * Cq + c0 + c2;
        dst[e >> 1] = pack2h(xs[pr][c2], xs[pr][c2 + 1]);
    }
}

// Fused dwconv 3x3 -> offset proj -> tanh -> grid coords (cp.async pipelined)
__global__ void __launch_bounds__(256) k_offsets(const float* __restrict__ x,
                                                 const float* __restrict__ dw,
                                                 const float* __restrict__ offw,
                                                 const float* __restrict__ offb) {
    __shared__ float xs[2][4][4][Wq];
    __shared__ float offw_s[Cq*16];
    __shared__ float dw_s[Cq*9];

    const int tid = threadIdx.x;
    const int px  = tid & 127;
    const int ry  = tid >> 7;
    const int b   = blockIdx.y;
    const int r0  = blockIdx.x * 2;

    for (int i = tid; i < Cq*9; i += 256) dw_s[i] = __ldg(dw + i);
#pragma unroll
    for (int o = 0; o < 16; o++) offw_s[tid*16 + o] = __ldg(offw + o*Cq + tid);

    float acc[16];
#pragma unroll
    for (int o = 0; o < 16; o++) acc[o] = __ldg(offb + o);

    const float* xb = x + (size_t)b * Cq * Pq;

    auto prefetch = [&](int g, int buf) {
        int c0 = g * 4;
#pragma unroll
        for (int i = 0; i < 2; i++) {
            int idx = tid + i * 256;
            int ci = idx >> 7;
            int rr = (idx >> 5) & 3;
            int p4 = (idx & 31) * 4;
            int gr = r0 - 1 + rr;
            if (gr >= 0 && gr < Hq) {
                cp16(smem_u32(&xs[buf][ci][rr][p4]),
                     xb + (size_t)(c0 + ci) * Pq + gr * Wq + p4);
            } else {
                *(float4*)&xs[buf][ci][rr][p4] = make_float4(0.f, 0.f, 0.f, 0.f);
            }
        }
    };

    prefetch(0, 0);
    asm volatile("cp.async.commit_group;");

    for (int g = 0; g < 64; g++) {
        if (g < 63) {
            prefetch(g + 1, (g + 1) & 1);
            asm volatile("cp.async.commit_group;");
            asm volatile("cp.async.wait_group 1;");
        } else {
            asm volatile("cp.async.wait_group 0;");
        }
        __syncthreads();
        const int buf = g & 1;
        const int c0  = g * 4;
#pragma unroll
        for (int ci = 0; ci < 4; ci++) {
            const int c = c0 + ci;
            const float* wv = &dw_s[c*9];
            float hv = 0.f;
#pragma unroll
            for (int ky = 0; ky < 3; ky++) {
                const float* row = xs[buf][ci][ry + ky];
                if (px > 0)      hv = fmaf(row[px-1], wv[ky*3+0], hv);
                                 hv = fmaf(row[px  ], wv[ky*3+1], hv);
                if (px < Wq-1)   hv = fmaf(row[px+1], wv[ky*3+2], hv);
            }
#pragma unroll
            for (int o4 = 0; o4 < 4; o4++) {
                float4 w4 = *(const float4*)&offw_s[c*16 + o4*4];
                acc[o4*4+0] = fmaf(hv, w4.x, acc[o4*4+0]);
                acc[o4*4+1] = fmaf(hv, w4.y, acc[o4*4+1]);
                acc[o4*4+2] = fmaf(hv, w4.z, acc[o4*4+2]);
                acc[o4*4+3] = fmaf(hv, w4.w, acc[o4*4+3]);
            }
        }
        __syncthreads();
    }

    const int y = r0 + ry;
    const int p = y * Wq + px;
    float gy = -1.f + 2.f * (float)y  / (float)(Hq - 1);
    float gx = -1.f + 2.f * (float)px / (float)(Wq - 1);
#pragma unroll
    for (int hh = 0; hh < NHq; hh++) {
        float dy = tanhf(acc[2*hh  ]) * 0.5f;
        float dx = tanhf(acc[2*hh+1]) * 0.5f;
        float sy = fminf(fmaxf(gy + dy, -1.f), 1.f);
        float sx = fminf(fmaxf(gx + dx, -1.f), 1.f);
        g_iy[(b*NHq + hh)*Pq + p] = (sy + 1.f) * 0.5f * (float)(Hq - 1);
        g_ix[(b*NHq + hh)*Pq + p] = (sx + 1.f) * 0.5f * (float)(Wq - 1);
    }
}

// Bilinear sampling from packed V (B,NH,P,HD) -> g_ST (B,P,C) fp16
__global__ void __launch_bounds__(256) k_sample() {
    const int tid = threadIdx.x;
    const int p0  = blockIdx.x * 256;
    const int hh  = blockIdx.y;
    const int b   = blockIdx.z;
    const int p   = p0 + tid;
    const int bh  = b * NHq + hh;

    float ixv = g_ix[bh*Pq + p];
    float iyv = g_iy[bh*Pq + p];
    float x0f = floorf(ixv), y0f = floorf(iyv);
    float wx = ixv - x0f, wy = iyv - y0f;
    int x0 = min(max((int)x0f,     0), Wq - 1);
    int x1 = min(max((int)x0f + 1, 0), Wq - 1);
    int y0 = min(max((int)y0f,     0), Hq - 1);
    int y1 = min(max((int)y0f + 1, 0), Hq - 1);
    float w00 = (1.f-wx)*(1.f-wy), w01 = wx*(1.f-wy);
    float w10 = (1.f-wx)*wy,       w11 = wx*wy;

    const uint32_t* V00 = g_Vp + ((size_t)bh * Pq + (y0*Wq + x0)) * HDq;
    const uint32_t* V01 = g_Vp + ((size_t)bh * Pq + (y0*Wq + x1)) * HDq;
    const uint32_t* V10 = g_Vp + ((size_t)bh * Pq + (y1*Wq + x0)) * HDq;
    const uint32_t* V11 = g_Vp + ((size_t)bh * Pq + (y1*Wq + x1)) * HDq;

    size_t e = (size_t)b * Pq * Cq + (size_t)p * Cq + hh * HDq;
    uint32_t* dst = (uint32_t*)g_ST + (e >> 1);

#pragma unroll
    for (int ch = 0; ch < 4; ch++) {
        const int c0 = ch * 8;
        uint4 a0 = *(const uint4*)(V00 + c0), a1 = *(const uint4*)(V00 + c0 + 4);
        uint4 b0 = *(const uint4*)(V01 + c0), b1 = *(const uint4*)(V01 + c0 + 4);
        uint4 c0v= *(const uint4*)(V10 + c0), c1v= *(const uint4*)(V10 + c0 + 4);
        uint4 d0 = *(const uint4*)(V11 + c0), d1 = *(const uint4*)(V11 + c0 + 4);
        uint32_t ua[8] = {a0.x,a0.y,a0.z,a0.w,a1.x,a1.y,a1.z,a1.w};
        uint32_t ub[8] = {b0.x,b0.y,b0.z,b0.w,b1.x,b1.y,b1.z,b1.w};
        uint32_t uc[8] = {c0v.x,c0v.y,c0v.z,c0v.w,c1v.x,c1v.y,c1v.z,c1v.w};
        uint32_t ud[8] = {d0.x,d0.y,d0.z,d0.w,d1.x,d1.y,d1.z,d1.w};
        float v[8];
#pragma unroll
        for (int j = 0; j < 8; j++) {
            v[j] = w00 * unpk(ua[j]) + w01 * unpk(ub[j])
                 + w10 * unpk(uc[j]) + w11 * unpk(ud[j]);
        }
        uint4 o4 = make_uint4(pack2h(v[0],v[1]), pack2h(v[2],v[3]),
                              pack2h(v[4],v[5]), pack2h(v[6],v[7]));
        *(uint4*)(dst + ch*4) = o4;
    }
}

__global__ void k_finalize() {
    int g = threadIdx.x;
    if (g < NGq) {
        float n  = (float)(HDq * Pq);
        float mu = g_sum[g] / n;
        float var = g_sq[g] / n - mu * mu;
        g_mean[g] = mu;
        g_rstd[g] = rsqrtf(var + 1e-5f);
    }
}

// out = x + (pre - mean)*rstd*gamma + beta; pre read as packed bf16-pair from g_Vp
__global__ void k_norm(const float* __restrict__ x,
                       const float* __restrict__ gamma,
                       const float* __restrict__ beta,
                       float* __restrict__ out) {
    size_t i = ((size_t)blockIdx.x * blockDim.x + threadIdx.x) * 4;
    int c = (int)((i / Pq) % Cq);
    int b = (int)(i / ((size_t)Cq * Pq));
    int g = b * NHq + c / HDq;
    float mu = g_mean[g], rs = g_rstd[g];
    float gm = __ldg(gamma + c), bt = __ldg(beta + c);
    uint4 pv = *(const uint4*)(g_Vp + i);
    float4 xv = *(const float4*)(x + i);
    float4 o;
    o.x = xv.x + (unpk(pv.x) - mu) * rs * gm + bt;
    o.y = xv.y + (unpk(pv.y) - mu) * rs * gm + bt;
    o.z = xv.z + (unpk(pv.z) - mu) * rs * gm + bt;
    o.w = xv.w + (unpk(pv.w) - mu) * rs * gm + bt;
    *(float4*)(out + i) = o;
}

// ---------------------------------------------------------------- pipelined HMMA GEMM (fp16, single pass)
// D = A · B, both fp16. Chunk = 64 k. Stage: A 16KB | B 16KB = 32KB, 2 stages.
// SMEM must also hold the PACKV restage tile: 128 * 129 * 4 = 66048 bytes.
#define STAGE_BYTES 32768
#define NSTAGE 2
#define SMEM_GEMM_BYTES (128*129*4 + 64)   // 66112: covers 2 stages (65536) AND restage tile

template<bool STATS, bool PACKV>
__global__ void __launch_bounds__(256, 2) k_gemm_pipe(
    const __half* __restrict__ A,
    const __half* __restrict__ B,
    uint32_t* __restrict__ OutP) {
    extern __shared__ char dsm[];
    const int tid   = threadIdx.x;
    const int lane  = tid & 31;
    const int wid   = tid >> 5;
    const int b     = blockIdx.z;
    const int om    = blockIdx.y * 128;
    const int p0    = blockIdx.x * 128;
    const int mwarp = wid & 1;
    const int nwarp = wid >> 1;

    uint32_t sb = smem_u32(dsm);
    float* ssum = (float*)(dsm + STAGE_BYTES*NSTAGE);   // beyond both stages, within 66112
    if (STATS && tid < 8) ssum[tid] = 0.f;

    const __half* Bb = B + (size_t)b * Pq * Cq;

    float acc[4][4][4] = {};

    // prefetch chunk kc (64 k): A 16KB + B 16KB, 8 cp16/thread
    auto prefetch = [&](int kc, int st) {
        uint32_t s0 = sb + st * STAGE_BYTES;
        const int kofs = kc * 64;
#pragma unroll
        for (int i = 0; i < 8; i++) {
            int idx = tid + i * 256;                 // 0..2047
            int t   = idx >> 10;                     // 0=A 1=B
            int r   = (idx >> 3) & 127;
            int ch  = idx & 7;
            uint32_t dst = s0 + t * 16384 + swz((uint32_t)(r * 128 + ch * 16));
            const __half* src = t == 0
                ? A  + (size_t)(om + r) * Cq + kofs + ch * 8
                : Bb + (size_t)(p0 + r) * Cq + kofs + ch * 8;
            cp16(dst, src);
        }
    };

    prefetch(0, 0);
    asm volatile("cp.async.commit_group;");

    for (int kc = 0; kc < 4; kc++) {
        asm volatile("cp.async.wait_group 0;");   // chunk kc copy done
        __syncthreads();                          // all warps done with kc-1 (frees other stage)
        if (kc + 1 < 4) {
            prefetch(kc + 1, (kc + 1) & 1);       // overlaps compute below
            asm volatile("cp.async.commit_group;");
        }

        const uint32_t sA = sb + (kc & 1) * STAGE_BYTES;
        const uint32_t sB = sA + 16384;

#pragma unroll
        for (int ks = 0; ks < 4; ks++) {
            const int cb = ks * 32;               // 16 fp16 = 32 bytes per k16 step
            uint32_t bf[8];
#pragma unroll
            for (int t2 = 0; t2 < 2; t2++)
                ldsm4(&bf[t2 * 4], b_addr(sB, nwarp * 32 + t2 * 16, cb, lane));
#pragma unroll
            for (int mt = 0; mt < 4; mt++) {
                uint32_t af[4];
                ldsm4(af, a_addr(sA, mwarp * 64 + mt * 16, cb, lane));
#pragma unroll
                for (int nt = 0; nt < 4; nt++)
                    mma16816(acc[mt][nt], af, &bf[nt * 2]);
            }
        }
    }
    __syncthreads();

    const int g  = lane >> 2;
    const int s2 = (lane & 3) * 2;

    if (PACKV) {
        // packed V (bf16 hi|lo) for sampling: (B,NH,P,HD) via smem restage (66048 B, fits)
        uint32_t (*stage)[129] = (uint32_t (*)[129])dsm;
#pragma unroll
        for (int mt = 0; mt < 4; mt++) {
            int row = mwarp * 64 + mt * 16 + g;
#pragma unroll
            for (int nt = 0; nt < 4; nt++) {
                int col = nwarp * 32 + nt * 8 + s2;
                stage[row    ][col  ] = pack_hl(acc[mt][nt][0]);
                stage[row    ][col+1] = pack_hl(acc[mt][nt][1]);
                stage[row + 8][col  ] = pack_hl(acc[mt][nt][2]);
                stage[row + 8][col+1] = pack_hl(acc[mt][nt][3]);
            }
        }
        __syncthreads();
        const int head_l = wid & 3;
        const int p_half = (wid >> 2) * 64;
        uint32_t* Vp = OutP + ((size_t)(b*NHq + (om >> 5) + head_l) * Pq + p0 + p_half) * HDq;
#pragma unroll 8
        for (int pp = 0; pp < 64; pp++)
            Vp[(size_t)pp * HDq + lane] = stage[head_l*32 + lane][p_half + pp];
        return;
    }

    // write packed (bf16 hi|lo) pre-norm values to OutP (B,C,P layout) + stats
    uint32_t* Ob = OutP + (size_t)b * Cq * Pq;
    float slocal[2] = {0.f, 0.f}, qlocal[2] = {0.f, 0.f};
#pragma unroll
    for (int mt = 0; mt < 4; mt++) {
        int o0 = om + mwarp * 64 + mt * 16 + g;
#pragma unroll
        for (int nt = 0; nt < 4; nt++) {
            int p = p0 + nwarp * 32 + nt * 8 + s2;
            float d0 = acc[mt][nt][0], d1 = acc[mt][nt][1];
            float d2 = acc[mt][nt][2], d3 = acc[mt][nt][3];
            *(uint2*)(Ob + (size_t)o0 * Pq + p)       = make_uint2(pack_hl(d0), pack_hl(d1));
            *(uint2*)(Ob + (size_t)(o0 + 8) * Pq + p) = make_uint2(pack_hl(d2), pack_hl(d3));
            if (STATS) {
                int j = mt >> 1;
                slocal[j] += d0 + d1 + d2 + d3;
                qlocal[j] += d0*d0 + d1*d1 + d2*d2 + d3*d3;
            }
        }
    }

    if (STATS) {
#pragma unroll
        for (int j = 0; j < 2; j++) {
#pragma unroll
            for (int o = 16; o; o >>= 1) {
                slocal[j] += __shfl_xor_sync(0xFFFFFFFFu, slocal[j], o);
                qlocal[j] += __shfl_xor_sync(0xFFFFFFFFu, qlocal[j], o);
            }
            if (lane == 0) {
                int gidx = mwarp * 2 + j;
                atomicAdd(&ssum[gidx],     slocal[j]);
                atomicAdd(&ssum[4 + gidx], qlocal[j]);
            }
        }
        __syncthreads();
        if (tid < 4) {
            int gg = b * NHq + blockIdx.y * 4 + tid;
            atomicAdd(&g_sum[gg], ssum[tid]);
            atomicAdd(&g_sq[gg],  ssum[4 + tid]);
        }
    }
}

// ---------------------------------------------------------------- launch
extern "C" void kernel_launch(void* const* d_in, const int* in_sizes, int n_in,
                              void* d_out, int out_size) {
    const float* x     = (const float*)d_in[0];
    const float* dw    = (const float*)d_in[1];
    const float* offw  = (const float*)d_in[2];
    const float* offb  = (const float*)d_in[3];
    const float* vw    = (const float*)d_in[4];
    const float* ow    = (const float*)d_in[5];
    const float* gamma = (const float*)d_in[6];
    const float* beta  = (const float*)d_in[7];
    float* out = (float*)d_out;

    static cudaStream_t s_side = nullptr;
    static cudaEvent_t  ev_fork = nullptr, ev_join = nullptr;
    if (!s_side) {
        cudaStreamCreateWithFlags(&s_side, cudaStreamNonBlocking);
        cudaEventCreateWithFlags(&ev_fork, cudaEventDisableTiming);
        cudaEventCreateWithFlags(&ev_join, cudaEventDisableTiming);
        cudaFuncSetAttribute(k_gemm_pipe<false,true>, cudaFuncAttributeMaxDynamicSharedMemorySize, SMEM_GEMM_BYTES);
        cudaFuncSetAttribute(k_gemm_pipe<true,false>, cudaFuncAttributeMaxDynamicSharedMemorySize, SMEM_GEMM_BYTES);
    }

    uint32_t* gVp = nullptr;
    cudaGetSymbolAddress((void**)&gVp, g_Vp);
    __half *xT, *ST, *wv, *wo;
    cudaGetSymbolAddress((void**)&xT, g_xT);
    cudaGetSymbolAddress((void**)&ST, g_ST);
    cudaGetSymbolAddress((void**)&wv, g_wv);
    cudaGetSymbolAddress((void**)&wo, g_wo);

    // Fork: k_offsets on side stream, overlapped with cvt + gemm1
    cudaEventRecord(ev_fork, 0);
    cudaStreamWaitEvent(s_side, ev_fork, 0);
    k_offsets<<<dim3(Hq/2, Bq), 256, 0, s_side>>>(x, dw, offw, offb);
    cudaEventRecord(ev_join, s_side);

    // Main chain
    k_wcvt<<<128, 256>>>(vw, ow);
    k_cvt<<<dim3(Pq/32, Cq/64, Bq), 256>>>(x);
    // V projection -> packed (B,NH,P,HD) in g_Vp
    k_gemm_pipe<false,true><<<dim3(Pq/128, Cq/128, Bq), 256, SMEM_GEMM_BYTES>>>(wv, xT, gVp);

    // Join: sampling needs both offsets and packed V
    cudaStreamWaitEvent(0, ev_join, 0);
    k_sample<<<dim3(Pq/256, NHq, Bq), 256>>>();
    // O projection -> packed pre-norm into g_Vp (V no longer needed) + stats
    k_gemm_pipe<true,false><<<dim3(Pq/128, Cq/128, Bq), 256, SMEM_GEMM_BYTES>>>(wo, ST, gVp);
    k_finalize<<<1, 64>>>();
    k_norm<<<(Bq*Cq*Pq)/1024, 256>>>(x, gamma, beta, out);
}

// round 15
// speedup vs baseline: 2.9946x; 1.2354x over previous
#include <cuda_runtime.h>
#include <cuda_bf16.h>
#include <cuda_fp16.h>
#include <math.h>
#include <stdint.h>

#define Bq 8
#define Cq 256
#define Hq 128
#define Wq 128
#define Pq (Hq*Wq)
#define NHq 8
#define HDq 32
#define NGq (Bq*NHq)

// Scratch (no allocations allowed)
__device__ float g_ix[Bq*NHq*Pq];
__device__ float g_iy[Bq*NHq*Pq];
// V as half2-per-2ch (B,NH,P,HD/2) u32; reused as fp16 pre-norm (B,C,P) halves
__device__ uint32_t g_Vp[(size_t)Bq*Cq*Pq/2];
__device__ __half g_xT[(size_t)Bq*Pq*Cq];          // x transposed (B,P,C) fp16
__device__ __half g_ST[(size_t)Bq*Pq*Cq];          // sampled (B,P,C) fp16
__device__ __half g_wv[Cq*Cq];                     // weights fp16
__device__ __half g_wo[Cq*Cq];
__device__ float g_sum[NGq];
__device__ float g_sq [NGq];
__device__ float g_mean[NGq];
__device__ float g_rstd[NGq];

// ---------------------------------------------------------------- helpers
__device__ __forceinline__ uint32_t smem_u32(const void* p) {
    uint32_t a;
    asm("{ .reg .u64 t; cvta.to.shared.u64 t, %1; cvt.u32.u64 %0, t; }" : "=r"(a) : "l"(p));
    return a;
}

__device__ __forceinline__ uint32_t swz(uint32_t byte) {
    return byte ^ ((byte >> 3) & 0x70);
}

__device__ __forceinline__ void ldsm4(uint32_t* r, uint32_t a) {
    asm volatile("ldmatrix.sync.aligned.m8n8.x4.shared.b16 {%0,%1,%2,%3}, [%4];"
        : "=r"(r[0]), "=r"(r[1]), "=r"(r[2]), "=r"(r[3]) : "r"(a));
}

// fp16 MMA, fp32 accumulate
__device__ __forceinline__ void mma16816(float* d, const uint32_t* a, const uint32_t* b) {
    asm volatile(
        "mma.sync.aligned.m16n8k16.row.col.f32.f16.f16.f32 "
        "{%0,%1,%2,%3}, {%4,%5,%6,%7}, {%8,%9}, {%0,%1,%2,%3};"
        : "+f"(d[0]), "+f"(d[1]), "+f"(d[2]), "+f"(d[3])
        : "r"(a[0]), "r"(a[1]), "r"(a[2]), "r"(a[3]), "r"(b[0]), "r"(b[1]));
}

__device__ __forceinline__ uint32_t a_addr(uint32_t base, int m_base, int cb, int lane) {
    int mat = lane >> 3, r = lane & 7;
    int row = m_base + ((mat & 1) << 3) + r;
    return base + swz((uint32_t)(row * 128 + cb + ((mat >> 1) << 4)));
}

__device__ __forceinline__ uint32_t b_addr(uint32_t base, int n_base, int cb, int lane) {
    int mat = lane >> 3, r = lane & 7;
    int row = n_base + ((mat >> 1) << 3) + r;
    return base + swz((uint32_t)(row * 128 + cb + ((mat & 1) << 4)));
}

__device__ __forceinline__ void cp16(uint32_t s, const void* g) {
    asm volatile("cp.async.cg.shared.global [%0], [%1], 16;" :: "r"(s), "l"(g));
}

__device__ __forceinline__ uint32_t pack2h(float a, float b) {
    __half2 h = __floats2half2_rn(a, b);
    return *(uint32_t*)&h;
}
__device__ __forceinline__ float2 up2h(uint32_t u) {
    __half2 h = *(__half2*)&u;
    return __half22float2(h);
}

// ---------------------------------------------------------------- small kernels
__global__ void k_wcvt(const float* __restrict__ vw, const float* __restrict__ ow) {
    int tid = threadIdx.x;
    if (blockIdx.x == 0 && tid < NGq) { g_sum[tid] = 0.f; g_sq[tid] = 0.f; }
    int idx = blockIdx.x * 256 + tid;
    int e = idx * 2;
    ((uint32_t*)g_wv)[idx] = pack2h(__ldg(vw + e), __ldg(vw + e + 1));
    ((uint32_t*)g_wo)[idx] = pack2h(__ldg(ow + e), __ldg(ow + e + 1));
}

// x (B,C,P) fp32 -> g_xT (B,P,C) fp16
__global__ void __launch_bounds__(256) k_cvt(const float* __restrict__ x) {
    __shared__ float xs[32][65];
    const int tid = threadIdx.x;
    const int p0 = blockIdx.x * 32, c0 = blockIdx.y * 64, b = blockIdx.z;
    const float* xb = x + (size_t)b * Cq * Pq;
#pragma unroll
    for (int i = 0; i < 8; i++) {
        int idx = tid + i * 256;
        int cr = idx >> 5, pc = idx & 31;
        xs[pc][cr] = xb[(size_t)(c0 + cr) * Pq + p0 + pc];
    }
    __syncthreads();
    uint32_t* dst = (uint32_t*)g_xT;
#pragma unroll
    for (int i = 0; i < 4; i++) {
        int idx = tid + i * 256;
        int pr = idx >> 5, c2 = (idx & 31) * 2;
        size_t e = (size_t)b * Pq * Cq + (size_t)(p0 + pr) * Cq + c0 + c2;
        dst[e >> 1] = pack2h(xs[pr][c2], xs[pr][c2 + 1]);
    }
}

// Fused dwconv 3x3 -> offset proj -> tanh -> grid coords (cp.async pipelined)
__global__ void __launch_bounds__(256) k_offsets(const float* __restrict__ x,
                                                 const float* __restrict__ dw,
                                                 const float* __restrict__ offw,
                                                 const float* __restrict__ offb) {
    __shared__ float xs[2][4][4][Wq];
    __shared__ float offw_s[Cq*16];
    __shared__ float dw_s[Cq*9];

    const int tid = threadIdx.x;
    const int px  = tid & 127;
    const int ry  = tid >> 7;
    const int b   = blockIdx.y;
    const int r0  = blockIdx.x * 2;

    for (int i = tid; i < Cq*9; i += 256) dw_s[i] = __ldg(dw + i);
#pragma unroll
    for (int o = 0; o < 16; o++) offw_s[tid*16 + o] = __ldg(offw + o*Cq + tid);

    float acc[16];
#pragma unroll
    for (int o = 0; o < 16; o++) acc[o] = __ldg(offb + o);

    const float* xb = x + (size_t)b * Cq * Pq;

    auto prefetch = [&](int g, int buf) {
        int c0 = g * 4;
#pragma unroll
        for (int i = 0; i < 2; i++) {
            int idx = tid + i * 256;
            int ci = idx >> 7;
            int rr = (idx >> 5) & 3;
            int p4 = (idx & 31) * 4;
            int gr = r0 - 1 + rr;
            if (gr >= 0 && gr < Hq) {
                cp16(smem_u32(&xs[buf][ci][rr][p4]),
                     xb + (size_t)(c0 + ci) * Pq + gr * Wq + p4);
            } else {
                *(float4*)&xs[buf][ci][rr][p4] = make_float4(0.f, 0.f, 0.f, 0.f);
            }
        }
    };

    prefetch(0, 0);
    asm volatile("cp.async.commit_group;");

    for (int g = 0; g < 64; g++) {
        if (g < 63) {
            prefetch(g + 1, (g + 1) & 1);
            asm volatile("cp.async.commit_group;");
            asm volatile("cp.async.wait_group 1;");
        } else {
            asm volatile("cp.async.wait_group 0;");
        }
        __syncthreads();
        const int buf = g & 1;
        const int c0  = g * 4;
#pragma unroll
        for (int ci = 0; ci < 4; ci++) {
            const int c = c0 + ci;
            const float* wv = &dw_s[c*9];
            float hv = 0.f;
#pragma unroll
            for (int ky = 0; ky < 3; ky++) {
                const float* row = xs[buf][ci][ry + ky];
                if (px > 0)      hv = fmaf(row[px-1], wv[ky*3+0], hv);
                                 hv = fmaf(row[px  ], wv[ky*3+1], hv);
                if (px < Wq-1)   hv = fmaf(row[px+1], wv[ky*3+2], hv);
            }
#pragma unroll
            for (int o4 = 0; o4 < 4; o4++) {
                float4 w4 = *(const float4*)&offw_s[c*16 + o4*4];
                acc[o4*4+0] = fmaf(hv, w4.x, acc[o4*4+0]);
                acc[o4*4+1] = fmaf(hv, w4.y, acc[o4*4+1]);
                acc[o4*4+2] = fmaf(hv, w4.z, acc[o4*4+2]);
                acc[o4*4+3] = fmaf(hv, w4.w, acc[o4*4+3]);
            }
        }
        __syncthreads();
    }

    const int y = r0 + ry;
    const int p = y * Wq + px;
    float gy = -1.f + 2.f * (float)y  / (float)(Hq - 1);
    float gx = -1.f + 2.f * (float)px / (float)(Wq - 1);
#pragma unroll
    for (int hh = 0; hh < NHq; hh++) {
        float dy = tanhf(acc[2*hh  ]) * 0.5f;
        float dx = tanhf(acc[2*hh+1]) * 0.5f;
        float sy = fminf(fmaxf(gy + dy, -1.f), 1.f);
        float sx = fminf(fmaxf(gx + dx, -1.f), 1.f);
        g_iy[(b*NHq + hh)*Pq + p] = (sy + 1.f) * 0.5f * (float)(Hq - 1);
        g_ix[(b*NHq + hh)*Pq + p] = (sx + 1.f) * 0.5f * (float)(Wq - 1);
    }
}

// Bilinear sampling from fp16 V (B,NH,P,HD/2 u32) -> g_ST (B,P,C) fp16
__global__ void __launch_bounds__(256) k_sample() {
    const int tid = threadIdx.x;
    const int p0  = blockIdx.x * 256;
    const int hh  = blockIdx.y;
    const int b   = blockIdx.z;
    const int p   = p0 + tid;
    const int bh  = b * NHq + hh;

    float ixv = g_ix[bh*Pq + p];
    float iyv = g_iy[bh*Pq + p];
    float x0f = floorf(ixv), y0f = floorf(iyv);
    float wx = ixv - x0f, wy = iyv - y0f;
    int x0 = min(max((int)x0f,     0), Wq - 1);
    int x1 = min(max((int)x0f + 1, 0), Wq - 1);
    int y0 = min(max((int)y0f,     0), Hq - 1);
    int y1 = min(max((int)y0f + 1, 0), Hq - 1);
    float w00 = (1.f-wx)*(1.f-wy), w01 = wx*(1.f-wy);
    float w10 = (1.f-wx)*wy,       w11 = wx*wy;

    const int HD2 = HDq / 2;   // 16 u32 per pixel-head
    const uint32_t* V00 = g_Vp + ((size_t)bh * Pq + (y0*Wq + x0)) * HD2;
    const uint32_t* V01 = g_Vp + ((size_t)bh * Pq + (y0*Wq + x1)) * HD2;
    const uint32_t* V10 = g_Vp + ((size_t)bh * Pq + (y1*Wq + x0)) * HD2;
    const uint32_t* V11 = g_Vp + ((size_t)bh * Pq + (y1*Wq + x1)) * HD2;

    size_t e = (size_t)b * Pq * Cq + (size_t)p * Cq + hh * HDq;
    uint32_t* dst = (uint32_t*)g_ST + (e >> 1);

#pragma unroll
    for (int ch = 0; ch < 4; ch++) {
        uint4 a = *(const uint4*)(V00 + ch*4);
        uint4 bb= *(const uint4*)(V01 + ch*4);
        uint4 c = *(const uint4*)(V10 + ch*4);
        uint4 d = *(const uint4*)(V11 + ch*4);
        uint32_t ua[4] = {a.x,a.y,a.z,a.w};
        uint32_t ub[4] = {bb.x,bb.y,bb.z,bb.w};
        uint32_t uc[4] = {c.x,c.y,c.z,c.w};
        uint32_t ud[4] = {d.x,d.y,d.z,d.w};
        uint32_t o[4];
#pragma unroll
        for (int j = 0; j < 4; j++) {
            float2 fa = up2h(ua[j]), fb = up2h(ub[j]);
            float2 fc = up2h(uc[j]), fd = up2h(ud[j]);
            float vx = w00*fa.x + w01*fb.x + w10*fc.x + w11*fd.x;
            float vy = w00*fa.y + w01*fb.y + w10*fc.y + w11*fd.y;
            o[j] = pack2h(vx, vy);
        }
        *(uint4*)(dst + ch*4) = make_uint4(o[0], o[1], o[2], o[3]);
    }
}

__global__ void k_finalize() {
    int g = threadIdx.x;
    if (g < NGq) {
        float n  = (float)(HDq * Pq);
        float mu = g_sum[g] / n;
        float var = g_sq[g] / n - mu * mu;
        g_mean[g] = mu;
        g_rstd[g] = rsqrtf(var + 1e-5f);
    }
}

// out = x + (pre - mean)*rstd*gamma + beta; pre read as fp16 halves from g_Vp
__global__ void k_norm(const float* __restrict__ x,
                       const float* __restrict__ gamma,
                       const float* __restrict__ beta,
                       float* __restrict__ out) {
    size_t i = ((size_t)blockIdx.x * blockDim.x + threadIdx.x) * 4;
    int c = (int)((i / Pq) % Cq);
    int b = (int)(i / ((size_t)Cq * Pq));
    int g = b * NHq + c / HDq;
    float mu = g_mean[g], rs = g_rstd[g];
    float gm = __ldg(gamma + c), bt = __ldg(beta + c);
    uint2 pv = *(const uint2*)(g_Vp + (i >> 1));
    float2 v01 = up2h(pv.x), v23 = up2h(pv.y);
    float4 xv = *(const float4*)(x + i);
    float4 o;
    o.x = xv.x + (v01.x - mu) * rs * gm + bt;
    o.y = xv.y + (v01.y - mu) * rs * gm + bt;
    o.z = xv.z + (v23.x - mu) * rs * gm + bt;
    o.w = xv.w + (v23.y - mu) * rs * gm + bt;
    *(float4*)(out + i) = o;
}

// ---------------------------------------------------------------- pipelined HMMA GEMM (fp16, single pass)
// D = A · B, both fp16. Chunk = 64 k. Stage: A 16KB | B 16KB = 32KB, 2 stages.
#define STAGE_BYTES 32768
#define NSTAGE 2
#define SMEM_GEMM_BYTES (STAGE_BYTES*NSTAGE + 64)

template<bool STATS, bool PACKV>
__global__ void __launch_bounds__(256, 2) k_gemm_pipe(
    const __half* __restrict__ A,
    const __half* __restrict__ B,
    uint32_t* __restrict__ OutP) {
    extern __shared__ char dsm[];
    const int tid   = threadIdx.x;
    const int lane  = tid & 31;
    const int wid   = tid >> 5;
    const int b     = blockIdx.z;
    const int om    = blockIdx.y * 128;
    const int p0    = blockIdx.x * 128;
    const int mwarp = wid & 1;
    const int nwarp = wid >> 1;

    uint32_t sb = smem_u32(dsm);
    float* ssum = (float*)(dsm + STAGE_BYTES*NSTAGE);
    if (STATS && tid < 8) ssum[tid] = 0.f;

    const __half* Bb = B + (size_t)b * Pq * Cq;

    float acc[4][4][4] = {};

    // prefetch chunk kc (64 k): A 16KB + B 16KB, 8 cp16/thread
    auto prefetch = [&](int kc, int st) {
        uint32_t s0 = sb + st * STAGE_BYTES;
        const int kofs = kc * 64;
#pragma unroll
        for (int i = 0; i < 8; i++) {
            int idx = tid + i * 256;                 // 0..2047
            int t   = idx >> 10;                     // 0=A 1=B
            int r   = (idx >> 3) & 127;
            int ch  = idx & 7;
            uint32_t dst = s0 + t * 16384 + swz((uint32_t)(r * 128 + ch * 16));
            const __half* src = t == 0
                ? A  + (size_t)(om + r) * Cq + kofs + ch * 8
                : Bb + (size_t)(p0 + r) * Cq + kofs + ch * 8;
            cp16(dst, src);
        }
    };

    prefetch(0, 0);
    asm volatile("cp.async.commit_group;");

    for (int kc = 0; kc < 4; kc++) {
        asm volatile("cp.async.wait_group 0;");   // chunk kc copy done
        __syncthreads();                          // all warps done with kc-1 (frees other stage)
        if (kc + 1 < 4) {
            prefetch(kc + 1, (kc + 1) & 1);       // overlaps compute below
            asm volatile("cp.async.commit_group;");
        }

        const uint32_t sA = sb + (kc & 1) * STAGE_BYTES;
        const uint32_t sB = sA + 16384;

#pragma unroll
        for (int ks = 0; ks < 4; ks++) {
            const int cb = ks * 32;               // 16 fp16 = 32 bytes per k16 step
            uint32_t bf[8];
#pragma unroll
            for (int t2 = 0; t2 < 2; t2++)
                ldsm4(&bf[t2 * 4], b_addr(sB, nwarp * 32 + t2 * 16, cb, lane));
#pragma unroll
            for (int mt = 0; mt < 4; mt++) {
                uint32_t af[4];
                ldsm4(af, a_addr(sA, mwarp * 64 + mt * 16, cb, lane));
#pragma unroll
                for (int nt = 0; nt < 4; nt++)
                    mma16816(acc[mt][nt], af, &bf[nt * 2]);
            }
        }
    }
    __syncthreads();

    const int g  = lane >> 2;
    const int s2 = (lane & 3) * 2;

    if (PACKV) {
        // fp16 V for sampling: (B,NH,P,HD/2 u32) via smem half restage
        // stage_h[c 128][p 128] halves, row stride 138 (bank-spread); 35328 B < 64KB
        __half (*stageh)[138] = (__half (*)[138])dsm;
#pragma unroll
        for (int mt = 0; mt < 4; mt++) {
            int row = mwarp * 64 + mt * 16 + g;
#pragma unroll
            for (int nt = 0; nt < 4; nt++) {
                int col = nwarp * 32 + nt * 8 + s2;
                stageh[row    ][col  ] = __float2half_rn(acc[mt][nt][0]);
                stageh[row    ][col+1] = __float2half_rn(acc[mt][nt][1]);
                stageh[row + 8][col  ] = __float2half_rn(acc[mt][nt][2]);
                stageh[row + 8][col+1] = __float2half_rn(acc[mt][nt][3]);
            }
        }
        __syncthreads();
        const int HD2 = HDq / 2;
        const int head_l = wid & 3;
        const int p_half = (wid >> 2) * 64;
        const int cl   = lane & 15;      // channel pair 0..15
        const int pofs = lane >> 4;      // 0/1
        uint32_t* Vp = OutP + ((size_t)(b*NHq + (om >> 5) + head_l) * Pq + p0 + p_half) * HD2;
#pragma unroll 4
        for (int pp = 0; pp < 64; pp += 2) {
            int col = p_half + pp + pofs;
            __half h0 = stageh[head_l*32 + 2*cl    ][col];
            __half h1 = stageh[head_l*32 + 2*cl + 1][col];
            uint32_t u = (uint32_t)__half_as_ushort(h0) | ((uint32_t)__half_as_ushort(h1) << 16);
            Vp[(size_t)(pp + pofs) * HD2 + cl] = u;
        }
        return;
    }

    // write fp16 pre-norm values to OutP (B,C,P halves) + stats
    __half* Ob = (__half*)OutP + (size_t)b * Cq * Pq;
    float slocal[2] = {0.f, 0.f}, qlocal[2] = {0.f, 0.f};
#pragma unroll
    for (int mt = 0; mt < 4; mt++) {
        int o0 = om + mwarp * 64 + mt * 16 + g;
#pragma unroll
        for (int nt = 0; nt < 4; nt++) {
            int p = p0 + nwarp * 32 + nt * 8 + s2;
            float d0 = acc[mt][nt][0], d1 = acc[mt][nt][1];
            float d2 = acc[mt][nt][2], d3 = acc[mt][nt][3];
            *(uint32_t*)(Ob + (size_t)o0 * Pq + p)       = pack2h(d0, d1);
            *(uint32_t*)(Ob + (size_t)(o0 + 8) * Pq + p) = pack2h(d2, d3);
            if (STATS) {
                int j = mt >> 1;
                slocal[j] += d0 + d1 + d2 + d3;
                qlocal[j] += d0*d0 + d1*d1 + d2*d2 + d3*d3;
            }
        }
    }

    if (STATS) {
#pragma unroll
        for (int j = 0; j < 2; j++) {
#pragma unroll
            for (int o = 16; o; o >>= 1) {
                slocal[j] += __shfl_xor_sync(0xFFFFFFFFu, slocal[j], o);
                qlocal[j] += __shfl_xor_sync(0xFFFFFFFFu, qlocal[j], o);
            }
            if (lane == 0) {
                int gidx = mwarp * 2 + j;
                atomicAdd(&ssum[gidx],     slocal[j]);
                atomicAdd(&ssum[4 + gidx], qlocal[j]);
            }
        }
        __syncthreads();
        if (tid < 4) {
            int gg = b * NHq + blockIdx.y * 4 + tid;
            atomicAdd(&g_sum[gg], ssum[tid]);
            atomicAdd(&g_sq[gg],  ssum[4 + tid]);
        }
    }
}

// ---------------------------------------------------------------- launch
extern "C" void kernel_launch(void* const* d_in, const int* in_sizes, int n_in,
                              void* d_out, int out_size) {
    const float* x     = (const float*)d_in[0];
    const float* dw    = (const float*)d_in[1];
    const float* offw  = (const float*)d_in[2];
    const float* offb  = (const float*)d_in[3];
    const float* vw    = (const float*)d_in[4];
    const float* ow    = (const float*)d_in[5];
    const float* gamma = (const float*)d_in[6];
    const float* beta  = (const float*)d_in[7];
    float* out = (float*)d_out;

    static cudaStream_t s_side = nullptr;
    static cudaEvent_t  ev_fork = nullptr, ev_join = nullptr;
    if (!s_side) {
        cudaStreamCreateWithFlags(&s_side, cudaStreamNonBlocking);
        cudaEventCreateWithFlags(&ev_fork, cudaEventDisableTiming);
        cudaEventCreateWithFlags(&ev_join, cudaEventDisableTiming);
        cudaFuncSetAttribute(k_gemm_pipe<false,true>, cudaFuncAttributeMaxDynamicSharedMemorySize, SMEM_GEMM_BYTES);
        cudaFuncSetAttribute(k_gemm_pipe<true,false>, cudaFuncAttributeMaxDynamicSharedMemorySize, SMEM_GEMM_BYTES);
    }

    uint32_t* gVp = nullptr;
    cudaGetSymbolAddress((void**)&gVp, g_Vp);
    __half *xT, *ST, *wv, *wo;
    cudaGetSymbolAddress((void**)&xT, g_xT);
    cudaGetSymbolAddress((void**)&ST, g_ST);
    cudaGetSymbolAddress((void**)&wv, g_wv);
    cudaGetSymbolAddress((void**)&wo, g_wo);

    // Fork: k_offsets on side stream, overlapped with cvt + gemm1
    cudaEventRecord(ev_fork, 0);
    cudaStreamWaitEvent(s_side, ev_fork, 0);
    k_offsets<<<dim3(Hq/2, Bq), 256, 0, s_side>>>(x, dw, offw, offb);
    cudaEventRecord(ev_join, s_side);

    // Main chain
    k_wcvt<<<128, 256>>>(vw, ow);
    k_cvt<<<dim3(Pq/32, Cq/64, Bq), 256>>>(x);
    // V projection -> fp16 packed (B,NH,P,HD/2) in g_Vp
    k_gemm_pipe<false,true><<<dim3(Pq/128, Cq/128, Bq), 256, SMEM_GEMM_BYTES>>>(wv, xT, gVp);

    // Join: sampling needs both offsets and V
    cudaStreamWaitEvent(0, ev_join, 0);
    k_sample<<<dim3(Pq/256, NHq, Bq), 256>>>();
    // O projection -> fp16 pre-norm into g_Vp (V no longer needed) + stats
    k_gemm_pipe<true,false><<<dim3(Pq/128, Cq/128, Bq), 256, SMEM_GEMM_BYTES>>>(wo, ST, gVp);
    k_finalize<<<1, 64>>>();
    k_norm<<<(Bq*Cq*Pq)/1024, 256>>>(x, gamma, beta, out);
}